// round 3
// baseline (speedup 1.0000x reference)
#include <cuda_runtime.h>
#include <math.h>

// Problem constants
#define NI 2048
#define KSEN 16
#define H 768
#define H2 1536
#define RR (NI*KSEN)   // 32768

// ---------------- device scratch (static; no allocations) ----------------
__device__ float g_feat[NI*H2];      // pooled concat features [N,2H]
__device__ float g_predcat[NI*H2];   // concat(pred_dec, pred_gls) [N,2H]
__device__ float g_h[NI*H];          // relu(feat@s1_w + s1_b)
__device__ float g_score[NI];
__device__ int   g_sel;
__device__ float g_bias_attn[H];     // sel_mg@W1 + W1_b + W2_b
__device__ float g_bias_v[H];        // sel_mg@V1 + V1_b + V2_b
__device__ float g_M[H*2];           // U_w @ cls_w
__device__ float g_c2[2];            // U_b @ cls_w
__device__ float g_logit_part[(size_t)RR*6];
__device__ float g_rv_part[(size_t)RR*12];  // [r][6][2]
__device__ float g_attn[RR];

// ---------------- helpers ----------------
__device__ __forceinline__ unsigned long long pk2(float lo, float hi){
    unsigned long long r;
    asm("mov.b64 %0, {%1, %2};" : "=l"(r) : "f"(lo), "f"(hi));
    return r;
}
__device__ __forceinline__ void up2(unsigned long long v, float& lo, float& hi){
    asm("mov.b64 {%0, %1}, %2;" : "=f"(lo), "=f"(hi) : "l"(v));
}
__device__ __forceinline__ void ffma2(unsigned long long& d, unsigned long long a, unsigned long long b){
    asm("fma.rn.f32x2 %0, %1, %2, %0;" : "+l"(d) : "l"(a), "l"(b));
}
__device__ __forceinline__ float wsum(float v){
    #pragma unroll
    for (int o=16;o;o>>=1) v += __shfl_xor_sync(0xffffffffu, v, o);
    return v;
}

// ---------------- K1: pooled features + predicted-sense vectors ----------------
__global__ void k_pool(const float* __restrict__ dec, const float* __restrict__ gls,
                       const int* __restrict__ pred){
    int n = blockIdx.x;
    int p = pred[n];
    const float* db = dec + (size_t)n*KSEN*H;
    const float* gb = gls + (size_t)n*KSEN*H;
    for (int d = threadIdx.x; d < H; d += blockDim.x){
        float sd=0.f, sg=0.f;
        #pragma unroll
        for (int k=0;k<KSEN;k++){ sd += db[k*H+d]; sg += gb[k*H+d]; }
        float pd = db[p*H+d], pg = gb[p*H+d];
        g_feat[(size_t)n*H2 + d]      = pd - sd*(1.0f/16.0f);
        g_feat[(size_t)n*H2 + H + d]  = pg - sg*(1.0f/16.0f);
        g_predcat[(size_t)n*H2 + d]     = pd;
        g_predcat[(size_t)n*H2 + H + d] = pg;
    }
}

// ---------------- K2: h = relu(feat @ s1_w + s1_b)  [2048,1536]@[1536,768] ----------------
__global__ void __launch_bounds__(256,2) k_gemm1(const float* __restrict__ B, const float* __restrict__ bias){
    __shared__ float As[16][129];
    __shared__ float Bs[16][128];
    int tid=threadIdx.x, bx=blockIdx.x, by=blockIdx.y;
    int tx=tid&15, ty=tid>>4;
    int arow=tid>>1, akc=(tid&1)*8;
    int bkr=tid>>4, bc0=(tid&15)*8;
    const float* Ap = g_feat + (size_t)(by*128+arow)*H2 + akc;
    const float* Bp = B + (size_t)bkr*H + bx*128 + bc0;
    unsigned long long acc[8][4];
    #pragma unroll
    for(int i=0;i<8;i++){
        #pragma unroll
        for(int j=0;j<4;j++) acc[i][j]=0ull;
    }
    for (int kt=0; kt<H2/16; kt++){
        float4 a0 = *(const float4*)(Ap + kt*16);
        float4 a1 = *(const float4*)(Ap + kt*16 + 4);
        As[akc+0][arow]=a0.x; As[akc+1][arow]=a0.y; As[akc+2][arow]=a0.z; As[akc+3][arow]=a0.w;
        As[akc+4][arow]=a1.x; As[akc+5][arow]=a1.y; As[akc+6][arow]=a1.z; As[akc+7][arow]=a1.w;
        const float* bsrc = Bp + (size_t)kt*16*H;
        *(float4*)&Bs[bkr][bc0]   = *(const float4*)(bsrc);
        *(float4*)&Bs[bkr][bc0+4] = *(const float4*)(bsrc+4);
        __syncthreads();
        #pragma unroll
        for (int k=0;k<16;k++){
            float ra[8];
            #pragma unroll
            for (int i=0;i<8;i++) ra[i]=As[k][ty*8+i];
            float4 bb0 = *(float4*)&Bs[k][tx*8];
            float4 bb1 = *(float4*)&Bs[k][tx*8+4];
            unsigned long long rb[4];
            rb[0]=pk2(bb0.x,bb0.y); rb[1]=pk2(bb0.z,bb0.w);
            rb[2]=pk2(bb1.x,bb1.y); rb[3]=pk2(bb1.z,bb1.w);
            #pragma unroll
            for (int i=0;i<8;i++){
                unsigned long long aa = pk2(ra[i],ra[i]);
                #pragma unroll
                for (int jp=0;jp<4;jp++) ffma2(acc[i][jp], aa, rb[jp]);
            }
        }
        __syncthreads();
    }
    int gc = bx*128 + tx*8;
    float bias8[8];
    #pragma unroll
    for (int j=0;j<8;j++) bias8[j]=bias[gc+j];
    #pragma unroll
    for (int i=0;i<8;i++){
        int row = by*128 + ty*8 + i;
        float v[8];
        #pragma unroll
        for (int jp=0;jp<4;jp++) up2(acc[i][jp], v[2*jp], v[2*jp+1]);
        float o[8];
        #pragma unroll
        for (int j=0;j<8;j++){ float t=v[j]+bias8[j]; o[j]= t>0.f? t : 0.f; }
        float4* dst=(float4*)(g_h + (size_t)row*H + gc);
        dst[0]=make_float4(o[0],o[1],o[2],o[3]);
        dst[1]=make_float4(o[4],o[5],o[6],o[7]);
    }
}

// ---------------- K3: score[n] = h[n] . s2_w + s2_b ----------------
__global__ void k_score(const float* __restrict__ s2w, const float* __restrict__ s2b){
    int w = (blockIdx.x*blockDim.x + threadIdx.x) >> 5;
    int lane = threadIdx.x & 31;
    if (w >= NI) return;
    const float* hr = g_h + (size_t)w*H;
    float s=0.f;
    for (int j=lane;j<H;j+=32) s += hr[j]*s2w[j];
    s = wsum(s);
    if (lane==0) g_score[w] = s + s2b[0];
}

// ---------------- K4: softmax over N + first-occurrence argmax ----------------
__global__ void k_softmax(float* __restrict__ probs){
    __shared__ float sv[1024];
    __shared__ int   si[1024];
    int tid=threadIdx.x;
    float a=g_score[tid], b=g_score[tid+1024];
    float m; int mi;
    if (a>=b){ m=a; mi=tid; } else { m=b; mi=tid+1024; }
    sv[tid]=m; si[tid]=mi;
    __syncthreads();
    for (int s=512;s>0;s>>=1){
        if (tid<s){
            float ov=sv[tid+s]; int oi=si[tid+s];
            if (ov>sv[tid] || (ov==sv[tid] && oi<si[tid])){ sv[tid]=ov; si[tid]=oi; }
        }
        __syncthreads();
    }
    float mx = sv[0]; int sel = si[0];
    if (tid==0) g_sel = sel;
    __syncthreads();
    float e0 = expf(a-mx), e1 = expf(b-mx);
    sv[tid] = e0+e1;
    __syncthreads();
    for (int s=512;s>0;s>>=1){ if (tid<s) sv[tid]+=sv[tid+s]; __syncthreads(); }
    float inv = 1.0f/sv[0];
    probs[tid]      = e0*inv;
    probs[tid+1024] = e1*inv;
}

// ---------------- K5a: M = U_w @ cls_w, c2 = U_b @ cls_w ----------------
__global__ void k_mcls(const float* __restrict__ Uw, const float* __restrict__ Ub,
                       const float* __restrict__ clsw){
    int j = blockIdx.x*128 + threadIdx.x;
    const float* ur = Uw + (size_t)j*H;
    float m0=0.f, m1=0.f;
    for (int t=0;t<H;t++){ float u=ur[t]; m0+=u*clsw[2*t]; m1+=u*clsw[2*t+1]; }
    g_M[2*j]=m0; g_M[2*j+1]=m1;
    if (blockIdx.x==0 && threadIdx.x<2){
        int c=threadIdx.x; float s=0.f;
        for (int t=0;t<H;t++) s += Ub[t]*clsw[2*t+c];
        g_c2[c]=s;
    }
}

// ---------------- K5b: sel-dependent bias vectors ----------------
__global__ void k_bias(const float* __restrict__ W1, const float* __restrict__ W1b, const float* __restrict__ W2b,
                       const float* __restrict__ V1, const float* __restrict__ V1b, const float* __restrict__ V2b){
    int half = (blockIdx.x < 6) ? 0 : 1;
    int j = ((half ? blockIdx.x-6 : blockIdx.x)*128) + threadIdx.x;
    int sel = g_sel;
    const float* m = half ? V1 : W1;
    const float* srow = g_predcat + (size_t)sel*H2;
    float s=0.f;
    for (int i=0;i<H2;i++) s += srow[i]*m[(size_t)i*H + j];
    if (half) g_bias_v[j]    = s + V1b[j] + V2b[j];
    else      g_bias_attn[j] = s + W1b[j] + W2b[j];
}

// ---------------- K6: big fused GEMM [32768,1536]@[1536,1536] + reduce epilogue ----------------
// bx in [0,6): columns of W2 (attn path); bx in [6,12): columns of V2 (value path)
__global__ void __launch_bounds__(256,2) k_big(const float* __restrict__ dec, const float* __restrict__ gls,
                                               const float* __restrict__ W2, const float* __restrict__ V2,
                                               const float* __restrict__ Wa){
    __shared__ float As[16][129];
    __shared__ float Bs[16][128];
    __shared__ float red[128][17];
    int tid=threadIdx.x, bx=blockIdx.x, by=blockIdx.y;
    int tx=tid&15, ty=tid>>4;
    int arow=tid>>1, akc=(tid&1)*8;
    int bkr=tid>>4, bc0=(tid&15)*8;
    const float* Bmat = (bx<6) ? W2 : V2;
    int colbase = ((bx<6) ? bx : bx-6)*128;
    size_t arowoff = (size_t)(by*128+arow)*H + akc;
    const float* Bp = Bmat + (size_t)bkr*H + colbase + bc0;
    unsigned long long acc[8][4];
    #pragma unroll
    for(int i=0;i<8;i++){
        #pragma unroll
        for(int j=0;j<4;j++) acc[i][j]=0ull;
    }
    for (int kt=0; kt<H2/16; kt++){
        int koff = kt*16;
        const float* Abase = (koff < H) ? (dec + koff) : (gls + (koff - H));
        float4 a0 = *(const float4*)(Abase + arowoff);
        float4 a1 = *(const float4*)(Abase + arowoff + 4);
        As[akc+0][arow]=a0.x; As[akc+1][arow]=a0.y; As[akc+2][arow]=a0.z; As[akc+3][arow]=a0.w;
        As[akc+4][arow]=a1.x; As[akc+5][arow]=a1.y; As[akc+6][arow]=a1.z; As[akc+7][arow]=a1.w;
        const float* bsrc = Bp + (size_t)kt*16*H;
        *(float4*)&Bs[bkr][bc0]   = *(const float4*)(bsrc);
        *(float4*)&Bs[bkr][bc0+4] = *(const float4*)(bsrc+4);
        __syncthreads();
        #pragma unroll
        for (int k=0;k<16;k++){
            float ra[8];
            #pragma unroll
            for (int i=0;i<8;i++) ra[i]=As[k][ty*8+i];
            float4 bb0 = *(float4*)&Bs[k][tx*8];
            float4 bb1 = *(float4*)&Bs[k][tx*8+4];
            unsigned long long rb[4];
            rb[0]=pk2(bb0.x,bb0.y); rb[1]=pk2(bb0.z,bb0.w);
            rb[2]=pk2(bb1.x,bb1.y); rb[3]=pk2(bb1.z,bb1.w);
            #pragma unroll
            for (int i=0;i<8;i++){
                unsigned long long aa = pk2(ra[i],ra[i]);
                #pragma unroll
                for (int jp=0;jp<4;jp++) ffma2(acc[i][jp], aa, rb[jp]);
            }
        }
        __syncthreads();
    }
    int lc = colbase + tx*8;   // local column within the 768-wide half
    if (bx < 6){
        float ba[8], wa[8];
        #pragma unroll
        for (int j=0;j<8;j++){ ba[j]=g_bias_attn[lc+j]; wa[j]=Wa[lc+j]; }
        #pragma unroll
        for (int i=0;i<8;i++){
            float v[8];
            #pragma unroll
            for (int jp=0;jp<4;jp++) up2(acc[i][jp], v[2*jp], v[2*jp+1]);
            float p=0.f;
            #pragma unroll
            for (int j=0;j<8;j++) p += tanhf(v[j]+ba[j])*wa[j];
            red[ty*8+i][tx] = p;
        }
        __syncthreads();
        if (tid < 128){
            float s=0.f;
            #pragma unroll
            for (int t=0;t<16;t++) s += red[tid][t];
            g_logit_part[(size_t)(by*128+tid)*6 + bx] = s;
        }
    } else {
        float bv[8], m0[8], m1[8];
        #pragma unroll
        for (int j=0;j<8;j++){ bv[j]=g_bias_v[lc+j]; m0[j]=g_M[(lc+j)*2]; m1[j]=g_M[(lc+j)*2+1]; }
        // pass 0: M[:,0]
        #pragma unroll
        for (int i=0;i<8;i++){
            float v[8];
            #pragma unroll
            for (int jp=0;jp<4;jp++) up2(acc[i][jp], v[2*jp], v[2*jp+1]);
            float p=0.f;
            #pragma unroll
            for (int j=0;j<8;j++){ float t=v[j]+bv[j]; t = t>0.f? t:0.f; p += t*m0[j]; }
            red[ty*8+i][tx] = p;
        }
        __syncthreads();
        if (tid < 128){
            float s=0.f;
            #pragma unroll
            for (int t=0;t<16;t++) s += red[tid][t];
            g_rv_part[(size_t)(by*128+tid)*12 + (bx-6)*2 + 0] = s;
        }
        __syncthreads();
        // pass 1: M[:,1]
        #pragma unroll
        for (int i=0;i<8;i++){
            float v[8];
            #pragma unroll
            for (int jp=0;jp<4;jp++) up2(acc[i][jp], v[2*jp], v[2*jp+1]);
            float p=0.f;
            #pragma unroll
            for (int j=0;j<8;j++){ float t=v[j]+bv[j]; t = t>0.f? t:0.f; p += t*m1[j]; }
            red[ty*8+i][tx] = p;
        }
        __syncthreads();
        if (tid < 128){
            float s=0.f;
            #pragma unroll
            for (int t=0;t<16;t++) s += red[tid][t];
            g_rv_part[(size_t)(by*128+tid)*12 + (bx-6)*2 + 1] = s;
        }
    }
}

// ---------------- K7: per-instance softmax over K senses ----------------
__global__ void k_attn(const float* __restrict__ Wab){
    int n = blockIdx.x, lane = threadIdx.x;
    float lg = -INFINITY;
    if (lane < KSEN){
        int r = n*KSEN + lane;
        float s = Wab[0];
        #pragma unroll
        for (int p=0;p<6;p++) s += g_logit_part[(size_t)r*6+p];
        lg = s;
    }
    float m = lg;
    #pragma unroll
    for (int o=16;o;o>>=1) m = fmaxf(m, __shfl_xor_sync(0xffffffffu, m, o));
    float e = (lane < KSEN) ? expf(lg - m) : 0.f;
    float t = wsum(e);
    if (lane < KSEN) g_attn[n*KSEN + lane] = e/t;
}

// ---------------- K8: final logits ----------------
__global__ void k_final(const float* __restrict__ dec, const float* __restrict__ clsw,
                        const float* __restrict__ clsb, float* __restrict__ out){
    int r = blockIdx.x*8 + (threadIdx.x>>5);
    int lane = threadIdx.x & 31;
    const float* drow = dec + (size_t)r*H;
    float a0=0.f, a1=0.f;
    for (int t=lane;t<H;t+=32){ float d=drow[t]; a0 += d*clsw[2*t]; a1 += d*clsw[2*t+1]; }
    a0=wsum(a0); a1=wsum(a1);
    if (lane==0){
        int n = r >> 4;
        float o0 = a0 + clsb[0], o1 = a1 + clsb[1];
        if (n != g_sel){
            float rv0=g_c2[0], rv1=g_c2[1];
            #pragma unroll
            for (int p=0;p<6;p++){ rv0 += g_rv_part[(size_t)r*12 + p*2]; rv1 += g_rv_part[(size_t)r*12 + p*2 + 1]; }
            float at = g_attn[r];
            o0 += at*rv0; o1 += at*rv1;
        }
        out[2*r]   = o0;
        out[2*r+1] = o1;
    }
}

// ---------------- launcher ----------------
extern "C" void kernel_launch(void* const* d_in, const int* in_sizes, int n_in,
                              void* d_out, int out_size){
    (void)n_in; (void)out_size;
    const float *dec,*gls,*s1w,*s1b,*s2w,*s2b,*W1w,*W1b,*W2w,*W2b,*Waw,*Wab,*V1w,*V1b,*V2w,*V2b,*Uw,*Ub,*clsw,*clsb;
    const int* pred;
    if (in_sizes[2] == NI){
        // setup_inputs dict order: pred at index 2
        dec=(const float*)d_in[0]; gls=(const float*)d_in[1]; pred=(const int*)d_in[2];
        s1w=(const float*)d_in[3];  s1b=(const float*)d_in[4];
        s2w=(const float*)d_in[5];  s2b=(const float*)d_in[6];
        W1w=(const float*)d_in[7];  W1b=(const float*)d_in[8];
        W2w=(const float*)d_in[9];  W2b=(const float*)d_in[10];
        Waw=(const float*)d_in[11]; Wab=(const float*)d_in[12];
        V1w=(const float*)d_in[13]; V1b=(const float*)d_in[14];
        V2w=(const float*)d_in[15]; V2b=(const float*)d_in[16];
        Uw =(const float*)d_in[17]; Ub =(const float*)d_in[18];
        clsw=(const float*)d_in[19]; clsb=(const float*)d_in[20];
    } else {
        // reference signature order: pred last
        dec=(const float*)d_in[0]; gls=(const float*)d_in[1];
        s1w=(const float*)d_in[2];  s1b=(const float*)d_in[3];
        s2w=(const float*)d_in[4];  s2b=(const float*)d_in[5];
        W1w=(const float*)d_in[6];  W1b=(const float*)d_in[7];
        W2w=(const float*)d_in[8];  W2b=(const float*)d_in[9];
        Waw=(const float*)d_in[10]; Wab=(const float*)d_in[11];
        V1w=(const float*)d_in[12]; V1b=(const float*)d_in[13];
        V2w=(const float*)d_in[14]; V2b=(const float*)d_in[15];
        Uw =(const float*)d_in[16]; Ub =(const float*)d_in[17];
        clsw=(const float*)d_in[18]; clsb=(const float*)d_in[19];
        pred=(const int*)d_in[20];
    }
    float* out = (float*)d_out;

    k_pool   <<<NI, 256>>>(dec, gls, pred);
    k_gemm1  <<<dim3(6,16), 256>>>(s1w, s1b);
    k_score  <<<256, 256>>>(s2w, s2b);
    k_softmax<<<1, 1024>>>(out + 2*RR);
    k_mcls   <<<6, 128>>>(Uw, Ub, clsw);
    k_bias   <<<12, 128>>>(W1w, W1b, W2b, V1w, V1b, V2b);
    k_big    <<<dim3(12, RR/128), 256>>>(dec, gls, W2w, V2w, Waw);
    k_attn   <<<NI, 32>>>(Wab);
    k_final  <<<RR/8, 256>>>(dec, clsw, clsb, out);
}

// round 5
// speedup vs baseline: 1.9088x; 1.9088x over previous
#include <cuda_runtime.h>
#include <cuda_bf16.h>
#include <math.h>
#include <stdint.h>

// Problem constants
#define NI 2048
#define KSEN 16
#define H 768
#define H2 1536
#define RR (NI*KSEN)   // 32768

// ---------------- device scratch (static; no allocations) ----------------
__device__ float g_feat[NI*H2];      // pooled concat features [N,2H]
__device__ float g_predcat[NI*H2];   // concat(pred_dec, pred_gls) [N,2H]
__device__ float g_h[NI*H];          // relu(feat@s1_w + s1_b)
__device__ float g_score[NI];
__device__ int   g_sel;
__device__ float g_bias_attn[H];     // sel_mg@W1 + W1_b + W2_b
__device__ float g_bias_v[H];        // sel_mg@V1 + V1_b + V2_b
__device__ float g_M[H*2];           // U_w @ cls_w
__device__ float g_c2[2];            // U_b @ cls_w
__device__ float g_logit_part[(size_t)RR*12];
__device__ float g_rv_part[(size_t)RR*24];  // [r][12][2]
__device__ float g_attn[RR];

// split-bf16 operands for the big GEMM
__device__ __nv_bfloat16 g_Ahi[(size_t)RR*H2];
__device__ __nv_bfloat16 g_Alo[(size_t)RR*H2];
__device__ __nv_bfloat16 g_Bhi[(size_t)H2*H2];   // [n][k], n<768: W2 col n; n>=768: V2 col n-768
__device__ __nv_bfloat16 g_Blo[(size_t)H2*H2];

// ---------------- fp32 packed helpers ----------------
__device__ __forceinline__ unsigned long long pk2(float lo, float hi){
    unsigned long long r;
    asm("mov.b64 %0, {%1, %2};" : "=l"(r) : "f"(lo), "f"(hi));
    return r;
}
__device__ __forceinline__ void up2(unsigned long long v, float& lo, float& hi){
    asm("mov.b64 {%0, %1}, %2;" : "=f"(lo), "=f"(hi) : "l"(v));
}
__device__ __forceinline__ void ffma2(unsigned long long& d, unsigned long long a, unsigned long long b){
    asm("fma.rn.f32x2 %0, %1, %2, %0;" : "+l"(d) : "l"(a), "l"(b));
}
__device__ __forceinline__ float wsum(float v){
    #pragma unroll
    for (int o=16;o;o>>=1) v += __shfl_xor_sync(0xffffffffu, v, o);
    return v;
}

// ---------------- mma.sync helpers (baseline sm_100 legal) ----------------
__device__ __forceinline__ uint32_t smem_u32(const void* p){
    uint32_t a;
    asm("{ .reg .u64 t; cvta.to.shared.u64 t, %1; cvt.u32.u64 %0, t; }" : "=r"(a) : "l"(p));
    return a;
}
__device__ __forceinline__ void ldm4(uint32_t* r, uint32_t addr){
    asm volatile("ldmatrix.sync.aligned.m8n8.x4.shared.b16 {%0,%1,%2,%3}, [%4];"
        : "=r"(r[0]),"=r"(r[1]),"=r"(r[2]),"=r"(r[3]) : "r"(addr));
}
__device__ __forceinline__ void mma_bf16(float* c, const uint32_t* a, uint32_t b0, uint32_t b1){
    asm volatile("mma.sync.aligned.m16n8k16.row.col.f32.bf16.bf16.f32 "
        "{%0,%1,%2,%3}, {%4,%5,%6,%7}, {%8,%9}, {%0,%1,%2,%3};"
        : "+f"(c[0]),"+f"(c[1]),"+f"(c[2]),"+f"(c[3])
        : "r"(a[0]),"r"(a[1]),"r"(a[2]),"r"(a[3]), "r"(b0),"r"(b1));
}
__device__ __forceinline__ void cpa16(uint32_t s, const void* g){
    asm volatile("cp.async.cg.shared.global [%0], [%1], 16;" :: "r"(s), "l"(g));
}
__device__ __forceinline__ void cpa_commit(){ asm volatile("cp.async.commit_group;" ::: "memory"); }
__device__ __forceinline__ void cpa_wait1(){ asm volatile("cp.async.wait_group 1;" ::: "memory"); }
__device__ __forceinline__ void cpa_wait0(){ asm volatile("cp.async.wait_group 0;" ::: "memory"); }

// ---------------- conversion kernels ----------------
__global__ void k_conv_a(const float* __restrict__ dec, const float* __restrict__ gls){
    size_t idx = ((size_t)blockIdx.x*blockDim.x + threadIdx.x) * 4;
    size_t r = idx / H2;
    int k = (int)(idx % H2);
    const float* src = (k < H) ? (dec + r*H + k) : (gls + r*H + (k - H));
    float4 a = *(const float4*)src;
    __nv_bfloat16 h0 = __float2bfloat16_rn(a.x);
    __nv_bfloat16 h1 = __float2bfloat16_rn(a.y);
    __nv_bfloat16 h2 = __float2bfloat16_rn(a.z);
    __nv_bfloat16 h3 = __float2bfloat16_rn(a.w);
    __nv_bfloat16 l0 = __float2bfloat16_rn(a.x - __bfloat162float(h0));
    __nv_bfloat16 l1 = __float2bfloat16_rn(a.y - __bfloat162float(h1));
    __nv_bfloat16 l2 = __float2bfloat16_rn(a.z - __bfloat162float(h2));
    __nv_bfloat16 l3 = __float2bfloat16_rn(a.w - __bfloat162float(h3));
    __nv_bfloat162* dh = (__nv_bfloat162*)(g_Ahi + idx);
    __nv_bfloat162* dl = (__nv_bfloat162*)(g_Alo + idx);
    dh[0] = __nv_bfloat162(h0,h1); dh[1] = __nv_bfloat162(h2,h3);
    dl[0] = __nv_bfloat162(l0,l1); dl[1] = __nv_bfloat162(l2,l3);
}

__global__ void k_conv_b(const float* __restrict__ W2, const float* __restrict__ V2){
    __shared__ float tile[32][33];
    int nb = blockIdx.x;   // 48 tiles over n
    int kb = blockIdx.y;   // 48 tiles over k
    int tx = threadIdx.x & 31, ty = threadIdx.x >> 5;   // 32 x 8
    const float* src = (nb < 24) ? W2 : V2;
    int col0 = (nb % 24) * 32;
    #pragma unroll
    for (int j=0;j<4;j++){
        int kk = ty + j*8;
        tile[tx][kk] = src[(size_t)(kb*32 + kk)*H + col0 + tx];
    }
    __syncthreads();
    int n0 = nb*32;
    #pragma unroll
    for (int j=0;j<4;j++){
        int c = ty + j*8;
        float v = tile[c][tx];
        __nv_bfloat16 hi = __float2bfloat16_rn(v);
        __nv_bfloat16 lo = __float2bfloat16_rn(v - __bfloat162float(hi));
        size_t di = (size_t)(n0 + c)*H2 + kb*32 + tx;
        g_Bhi[di] = hi;
        g_Blo[di] = lo;
    }
}

// ---------------- K1: pooled features + predicted-sense vectors ----------------
__global__ void k_pool(const float* __restrict__ dec, const float* __restrict__ gls,
                       const int* __restrict__ pred){
    int n = blockIdx.x;
    int p = pred[n];
    const float* db = dec + (size_t)n*KSEN*H;
    const float* gb = gls + (size_t)n*KSEN*H;
    for (int d = threadIdx.x; d < H; d += blockDim.x){
        float sd=0.f, sg=0.f;
        #pragma unroll
        for (int k=0;k<KSEN;k++){ sd += db[k*H+d]; sg += gb[k*H+d]; }
        float pd = db[p*H+d], pg = gb[p*H+d];
        g_feat[(size_t)n*H2 + d]      = pd - sd*(1.0f/16.0f);
        g_feat[(size_t)n*H2 + H + d]  = pg - sg*(1.0f/16.0f);
        g_predcat[(size_t)n*H2 + d]     = pd;
        g_predcat[(size_t)n*H2 + H + d] = pg;
    }
}

// ---------------- K2: h = relu(feat @ s1_w + s1_b)  (exact fp32; argmax safety) ----------------
__global__ void __launch_bounds__(256,2) k_gemm1(const float* __restrict__ B, const float* __restrict__ bias){
    __shared__ float As[16][129];
    __shared__ float Bs[16][128];
    int tid=threadIdx.x, bx=blockIdx.x, by=blockIdx.y;
    int tx=tid&15, ty=tid>>4;
    int arow=tid>>1, akc=(tid&1)*8;
    int bkr=tid>>4, bc0=(tid&15)*8;
    const float* Ap = g_feat + (size_t)(by*128+arow)*H2 + akc;
    const float* Bp = B + (size_t)bkr*H + bx*128 + bc0;
    unsigned long long acc[8][4];
    #pragma unroll
    for(int i=0;i<8;i++){
        #pragma unroll
        for(int j=0;j<4;j++) acc[i][j]=0ull;
    }
    for (int kt=0; kt<H2/16; kt++){
        float4 a0 = *(const float4*)(Ap + kt*16);
        float4 a1 = *(const float4*)(Ap + kt*16 + 4);
        As[akc+0][arow]=a0.x; As[akc+1][arow]=a0.y; As[akc+2][arow]=a0.z; As[akc+3][arow]=a0.w;
        As[akc+4][arow]=a1.x; As[akc+5][arow]=a1.y; As[akc+6][arow]=a1.z; As[akc+7][arow]=a1.w;
        const float* bsrc = Bp + (size_t)kt*16*H;
        *(float4*)&Bs[bkr][bc0]   = *(const float4*)(bsrc);
        *(float4*)&Bs[bkr][bc0+4] = *(const float4*)(bsrc+4);
        __syncthreads();
        #pragma unroll
        for (int k=0;k<16;k++){
            float ra[8];
            #pragma unroll
            for (int i=0;i<8;i++) ra[i]=As[k][ty*8+i];
            float4 bb0 = *(float4*)&Bs[k][tx*8];
            float4 bb1 = *(float4*)&Bs[k][tx*8+4];
            unsigned long long rb[4];
            rb[0]=pk2(bb0.x,bb0.y); rb[1]=pk2(bb0.z,bb0.w);
            rb[2]=pk2(bb1.x,bb1.y); rb[3]=pk2(bb1.z,bb1.w);
            #pragma unroll
            for (int i=0;i<8;i++){
                unsigned long long aa = pk2(ra[i],ra[i]);
                #pragma unroll
                for (int jp=0;jp<4;jp++) ffma2(acc[i][jp], aa, rb[jp]);
            }
        }
        __syncthreads();
    }
    int gc = bx*128 + tx*8;
    float bias8[8];
    #pragma unroll
    for (int j=0;j<8;j++) bias8[j]=bias[gc+j];
    #pragma unroll
    for (int i=0;i<8;i++){
        int row = by*128 + ty*8 + i;
        float v[8];
        #pragma unroll
        for (int jp=0;jp<4;jp++) up2(acc[i][jp], v[2*jp], v[2*jp+1]);
        float o[8];
        #pragma unroll
        for (int j=0;j<8;j++){ float t=v[j]+bias8[j]; o[j]= t>0.f? t : 0.f; }
        float4* dst=(float4*)(g_h + (size_t)row*H + gc);
        dst[0]=make_float4(o[0],o[1],o[2],o[3]);
        dst[1]=make_float4(o[4],o[5],o[6],o[7]);
    }
}

// ---------------- K3: score[n] = h[n] . s2_w + s2_b ----------------
__global__ void k_score(const float* __restrict__ s2w, const float* __restrict__ s2b){
    int w = (blockIdx.x*blockDim.x + threadIdx.x) >> 5;
    int lane = threadIdx.x & 31;
    if (w >= NI) return;
    const float* hr = g_h + (size_t)w*H;
    float s=0.f;
    for (int j=lane;j<H;j+=32) s += hr[j]*s2w[j];
    s = wsum(s);
    if (lane==0) g_score[w] = s + s2b[0];
}

// ---------------- K4: softmax over N + first-occurrence argmax ----------------
__global__ void k_softmax(float* __restrict__ probs){
    __shared__ float sv[1024];
    __shared__ int   si[1024];
    int tid=threadIdx.x;
    float a=g_score[tid], b=g_score[tid+1024];
    float m; int mi;
    if (a>=b){ m=a; mi=tid; } else { m=b; mi=tid+1024; }
    sv[tid]=m; si[tid]=mi;
    __syncthreads();
    for (int s=512;s>0;s>>=1){
        if (tid<s){
            float ov=sv[tid+s]; int oi=si[tid+s];
            if (ov>sv[tid] || (ov==sv[tid] && oi<si[tid])){ sv[tid]=ov; si[tid]=oi; }
        }
        __syncthreads();
    }
    float mx = sv[0]; int sel = si[0];
    if (tid==0) g_sel = sel;
    __syncthreads();
    float e0 = expf(a-mx), e1 = expf(b-mx);
    sv[tid] = e0+e1;
    __syncthreads();
    for (int s=512;s>0;s>>=1){ if (tid<s) sv[tid]+=sv[tid+s]; __syncthreads(); }
    float inv = 1.0f/sv[0];
    probs[tid]      = e0*inv;
    probs[tid+1024] = e1*inv;
}

// ---------------- K5a: M = U_w @ cls_w, c2 = U_b @ cls_w ----------------
__global__ void k_mcls(const float* __restrict__ Uw, const float* __restrict__ Ub,
                       const float* __restrict__ clsw){
    int j = blockIdx.x*128 + threadIdx.x;
    const float* ur = Uw + (size_t)j*H;
    float m0=0.f, m1=0.f;
    for (int t=0;t<H;t++){ float u=ur[t]; m0+=u*clsw[2*t]; m1+=u*clsw[2*t+1]; }
    g_M[2*j]=m0; g_M[2*j+1]=m1;
    if (blockIdx.x==0 && threadIdx.x<2){
        int c=threadIdx.x; float s=0.f;
        for (int t=0;t<H;t++) s += Ub[t]*clsw[2*t+c];
        g_c2[c]=s;
    }
}

// ---------------- K5b: sel-dependent bias vectors ----------------
__global__ void k_bias(const float* __restrict__ W1, const float* __restrict__ W1b, const float* __restrict__ W2b,
                       const float* __restrict__ V1, const float* __restrict__ V1b, const float* __restrict__ V2b){
    int half = (blockIdx.x < 6) ? 0 : 1;
    int j = ((half ? blockIdx.x-6 : blockIdx.x)*128) + threadIdx.x;
    int sel = g_sel;
    const float* m = half ? V1 : W1;
    const float* srow = g_predcat + (size_t)sel*H2;
    float s=0.f;
    for (int i=0;i<H2;i++) s += srow[i]*m[(size_t)i*H + j];
    if (half) g_bias_v[j]    = s + V1b[j] + V2b[j];
    else      g_bias_attn[j] = s + W1b[j] + W2b[j];
}

// ---------------- K6: mma.sync split-bf16 GEMM [32768,1536]@[1536,1536] + reduce ----------------
// grid (12, 256): cb = 128-col block (cb<6: W2, else V2), by = 128-row block.
// CTA 128x128, 256 thr, warps 4(M)x2(N), warp tile 32x64.
// SMEM per stage: Ahi | Alo | Bhi | Blo each 128 rows x 40 bf16 (pad) = 10240 B. 2 stages.
#define KB_ROWSTRIDE 40
#define KB_REGION 10240
#define KB_STAGE  40960
#define KB_SMEM   (2*KB_STAGE)
#define KB_ITERS  48

__device__ __forceinline__ void kb_load_stage(uint32_t sb, int stage, int by, int cb, int gk, int tid){
    uint32_t s0 = sb + stage*KB_STAGE;
    #pragma unroll
    for (int j=0;j<8;j++){
        int region = j >> 1;                // 0 Ahi, 1 Alo, 2 Bhi, 3 Blo
        int cl = (j&1)*256 + tid;           // 0..511
        int r  = cl >> 2;
        int kc = cl & 3;
        const __nv_bfloat16* gb;
        size_t grow;
        if (region < 2){
            gb = region ? g_Alo : g_Ahi;
            grow = (size_t)(by*128 + r);
        } else {
            gb = (region==2) ? g_Bhi : g_Blo;
            grow = (size_t)(cb*128 + r);
        }
        uint32_t soff = s0 + region*KB_REGION + r*(KB_ROWSTRIDE*2) + kc*16;
        cpa16(soff, gb + grow*H2 + gk + kc*8);
    }
}

__global__ void __launch_bounds__(256,1) k_big_mma(const float* __restrict__ Wa){
    extern __shared__ char smem[];
    uint32_t sb = smem_u32(smem);
    int tid = threadIdx.x;
    int cb = blockIdx.x, by = blockIdx.y;
    int warp = tid >> 5, lane = tid & 31;
    int wm = warp & 3, wn = warp >> 2;      // wm 0..3 (M), wn 0..1 (N)

    float acc[2][8][4];
    #pragma unroll
    for (int mt=0;mt<2;mt++)
        #pragma unroll
        for (int nt=0;nt<8;nt++)
            #pragma unroll
            for (int d=0;d<4;d++) acc[mt][nt][d] = 0.f;

    kb_load_stage(sb, 0, by, cb, 0, tid);
    cpa_commit();

    int m8 = lane >> 3, r8 = lane & 7;

    for (int it = 0; it < KB_ITERS; it++){
        int b = it & 1;
        if (it + 1 < KB_ITERS){
            kb_load_stage(sb, 1-b, by, cb, (it+1)*32, tid);
            cpa_commit();
            cpa_wait1();
        } else {
            cpa_wait0();
        }
        __syncthreads();

        uint32_t st = sb + b*KB_STAGE;
        #pragma unroll
        for (int kh=0; kh<2; kh++){
            int k0 = kh*16;
            uint32_t ah[2][4], al[2][4], bh[4][4], bl[4][4];
            #pragma unroll
            for (int mt=0;mt<2;mt++){
                int rowA = wm*32 + mt*16 + (m8&1)*8 + r8;
                int kA   = k0 + (m8>>1)*8;
                uint32_t aoff = rowA*(KB_ROWSTRIDE*2) + kA*2;
                ldm4(ah[mt], st + 0*KB_REGION + aoff);
                ldm4(al[mt], st + 1*KB_REGION + aoff);
            }
            #pragma unroll
            for (int ntp=0;ntp<4;ntp++){
                int rowB = wn*64 + ntp*16 + (m8>>1)*8 + r8;
                int kB   = k0 + (m8&1)*8;
                uint32_t boff = rowB*(KB_ROWSTRIDE*2) + kB*2;
                ldm4(bh[ntp], st + 2*KB_REGION + boff);
                ldm4(bl[ntp], st + 3*KB_REGION + boff);
            }
            #pragma unroll
            for (int mt=0;mt<2;mt++){
                #pragma unroll
                for (int nt=0;nt<8;nt++){
                    int ntp = nt >> 1, o = (nt&1)*2;
                    mma_bf16(acc[mt][nt], ah[mt], bh[ntp][o], bh[ntp][o+1]);
                    mma_bf16(acc[mt][nt], ah[mt], bl[ntp][o], bl[ntp][o+1]);
                    mma_bf16(acc[mt][nt], al[mt], bh[ntp][o], bh[ntp][o+1]);
                }
            }
        }
        __syncthreads();
    }

    // ---------------- epilogue: reduce over the 128 columns this CTA owns ----------------
    int quad = lane >> 2, qt = lane & 3;
    if (cb < 6){
        int colb = cb*128;
        #pragma unroll
        for (int mt=0;mt<2;mt++){
            float plo = 0.f, phi = 0.f;
            #pragma unroll
            for (int nt=0;nt<8;nt++){
                int g0 = colb + wn*64 + nt*8 + qt*2;
                float ba0 = g_bias_attn[g0],  ba1 = g_bias_attn[g0+1];
                float w0  = Wa[g0],           w1  = Wa[g0+1];
                plo += tanhf(acc[mt][nt][0]+ba0)*w0 + tanhf(acc[mt][nt][1]+ba1)*w1;
                phi += tanhf(acc[mt][nt][2]+ba0)*w0 + tanhf(acc[mt][nt][3]+ba1)*w1;
            }
            plo += __shfl_xor_sync(0xffffffffu, plo, 1);
            plo += __shfl_xor_sync(0xffffffffu, plo, 2);
            phi += __shfl_xor_sync(0xffffffffu, phi, 1);
            phi += __shfl_xor_sync(0xffffffffu, phi, 2);
            if (qt == 0){
                int rlo = by*128 + wm*32 + mt*16 + quad;
                g_logit_part[(size_t)rlo*12 + cb*2 + wn]     = plo;
                g_logit_part[(size_t)(rlo+8)*12 + cb*2 + wn] = phi;
            }
        }
    } else {
        int cbv = cb - 6, colb = cbv*128, slot = cbv*2 + wn;
        #pragma unroll
        for (int mt=0;mt<2;mt++){
            float p0l=0.f, p1l=0.f, p0h=0.f, p1h=0.f;
            #pragma unroll
            for (int nt=0;nt<8;nt++){
                int g0 = colb + wn*64 + nt*8 + qt*2;
                float bv0 = g_bias_v[g0], bv1 = g_bias_v[g0+1];
                float m00 = g_M[2*g0],   m01 = g_M[2*g0+1];
                float m10 = g_M[2*g0+2], m11 = g_M[2*g0+3];
                float x;
                x = acc[mt][nt][0]+bv0; x = x>0.f? x:0.f; p0l += x*m00; p1l += x*m01;
                x = acc[mt][nt][1]+bv1; x = x>0.f? x:0.f; p0l += x*m10; p1l += x*m11;
                x = acc[mt][nt][2]+bv0; x = x>0.f? x:0.f; p0h += x*m00; p1h += x*m01;
                x = acc[mt][nt][3]+bv1; x = x>0.f? x:0.f; p0h += x*m10; p1h += x*m11;
            }
            p0l += __shfl_xor_sync(0xffffffffu, p0l, 1); p0l += __shfl_xor_sync(0xffffffffu, p0l, 2);
            p1l += __shfl_xor_sync(0xffffffffu, p1l, 1); p1l += __shfl_xor_sync(0xffffffffu, p1l, 2);
            p0h += __shfl_xor_sync(0xffffffffu, p0h, 1); p0h += __shfl_xor_sync(0xffffffffu, p0h, 2);
            p1h += __shfl_xor_sync(0xffffffffu, p1h, 1); p1h += __shfl_xor_sync(0xffffffffu, p1h, 2);
            if (qt == 0){
                int rlo = by*128 + wm*32 + mt*16 + quad;
                g_rv_part[(size_t)rlo*24 + slot*2 + 0] = p0l;
                g_rv_part[(size_t)rlo*24 + slot*2 + 1] = p1l;
                g_rv_part[(size_t)(rlo+8)*24 + slot*2 + 0] = p0h;
                g_rv_part[(size_t)(rlo+8)*24 + slot*2 + 1] = p1h;
            }
        }
    }
}

// ---------------- K7: per-instance softmax over K senses ----------------
__global__ void k_attn(const float* __restrict__ Wab){
    int n = blockIdx.x, lane = threadIdx.x;
    float lg = -INFINITY;
    if (lane < KSEN){
        int r = n*KSEN + lane;
        float s = Wab[0];
        #pragma unroll
        for (int p=0;p<12;p++) s += g_logit_part[(size_t)r*12+p];
        lg = s;
    }
    float m = lg;
    #pragma unroll
    for (int o=16;o;o>>=1) m = fmaxf(m, __shfl_xor_sync(0xffffffffu, m, o));
    float e = (lane < KSEN) ? expf(lg - m) : 0.f;
    float t = wsum(e);
    if (lane < KSEN) g_attn[n*KSEN + lane] = e/t;
}

// ---------------- K8: final logits ----------------
__global__ void k_final(const float* __restrict__ dec, const float* __restrict__ clsw,
                        const float* __restrict__ clsb, float* __restrict__ out){
    int r = blockIdx.x*8 + (threadIdx.x>>5);
    int lane = threadIdx.x & 31;
    const float* drow = dec + (size_t)r*H;
    float a0=0.f, a1=0.f;
    for (int t=lane;t<H;t+=32){ float d=drow[t]; a0 += d*clsw[2*t]; a1 += d*clsw[2*t+1]; }
    a0=wsum(a0); a1=wsum(a1);
    if (lane==0){
        int n = r >> 4;
        float o0 = a0 + clsb[0], o1 = a1 + clsb[1];
        if (n != g_sel){
            float rv0=g_c2[0], rv1=g_c2[1];
            #pragma unroll
            for (int p=0;p<12;p++){ rv0 += g_rv_part[(size_t)r*24 + p*2]; rv1 += g_rv_part[(size_t)r*24 + p*2 + 1]; }
            float at = g_attn[r];
            o0 += at*rv0; o1 += at*rv1;
        }
        out[2*r]   = o0;
        out[2*r+1] = o1;
    }
}

// ---------------- launcher ----------------
extern "C" void kernel_launch(void* const* d_in, const int* in_sizes, int n_in,
                              void* d_out, int out_size){
    (void)n_in; (void)out_size;
    const float *dec,*gls,*s1w,*s1b,*s2w,*s2b,*W1w,*W1b,*W2w,*W2b,*Waw,*Wab,*V1w,*V1b,*V2w,*V2b,*Uw,*Ub,*clsw,*clsb;
    const int* pred;
    if (in_sizes[2] == NI){
        dec=(const float*)d_in[0]; gls=(const float*)d_in[1]; pred=(const int*)d_in[2];
        s1w=(const float*)d_in[3];  s1b=(const float*)d_in[4];
        s2w=(const float*)d_in[5];  s2b=(const float*)d_in[6];
        W1w=(const float*)d_in[7];  W1b=(const float*)d_in[8];
        W2w=(const float*)d_in[9];  W2b=(const float*)d_in[10];
        Waw=(const float*)d_in[11]; Wab=(const float*)d_in[12];
        V1w=(const float*)d_in[13]; V1b=(const float*)d_in[14];
        V2w=(const float*)d_in[15]; V2b=(const float*)d_in[16];
        Uw =(const float*)d_in[17]; Ub =(const float*)d_in[18];
        clsw=(const float*)d_in[19]; clsb=(const float*)d_in[20];
    } else {
        dec=(const float*)d_in[0]; gls=(const float*)d_in[1];
        s1w=(const float*)d_in[2];  s1b=(const float*)d_in[3];
        s2w=(const float*)d_in[4];  s2b=(const float*)d_in[5];
        W1w=(const float*)d_in[6];  W1b=(const float*)d_in[7];
        W2w=(const float*)d_in[8];  W2b=(const float*)d_in[9];
        Waw=(const float*)d_in[10]; Wab=(const float*)d_in[11];
        V1w=(const float*)d_in[12]; V1b=(const float*)d_in[13];
        V2w=(const float*)d_in[14]; V2b=(const float*)d_in[15];
        Uw =(const float*)d_in[16]; Ub =(const float*)d_in[17];
        clsw=(const float*)d_in[18]; clsb=(const float*)d_in[19];
        pred=(const int*)d_in[20];
    }
    float* out = (float*)d_out;

    cudaFuncSetAttribute(k_big_mma, cudaFuncAttributeMaxDynamicSharedMemorySize, KB_SMEM);

    k_conv_a <<<(size_t)RR*H2/4/256, 256>>>(dec, gls);
    k_conv_b <<<dim3(48,48), 256>>>(W2w, V2w);
    k_pool   <<<NI, 256>>>(dec, gls, pred);
    k_gemm1  <<<dim3(6,16), 256>>>(s1w, s1b);
    k_score  <<<256, 256>>>(s2w, s2b);
    k_softmax<<<1, 1024>>>(out + 2*RR);
    k_mcls   <<<6, 128>>>(Uw, Ub, clsw);
    k_bias   <<<12, 128>>>(W1w, W1b, W2b, V1w, V1b, V2b);
    k_big_mma<<<dim3(12, 256), 256, KB_SMEM>>>(Waw);
    k_attn   <<<NI, 32>>>(Wab);
    k_final  <<<RR/8, 256>>>(dec, clsw, clsb, out);
}

// round 6
// speedup vs baseline: 2.1855x; 1.1450x over previous
#include <cuda_runtime.h>
#include <cuda_fp16.h>
#include <math.h>
#include <stdint.h>

// Problem constants
#define NI 2048
#define KSEN 16
#define H 768
#define H2 1536
#define RR (NI*KSEN)   // 32768

// ---------------- device scratch (static; no allocations) ----------------
__device__ float g_feat[NI*H2];      // pooled concat features [N,2H]
__device__ float g_predcat[NI*H2];   // concat(pred_dec, pred_gls) [N,2H]
__device__ float g_h[NI*H];          // relu(feat@s1_w + s1_b)
__device__ float g_score[NI];
__device__ int   g_sel;
__device__ float g_bias_attn[H];     // sel_mg@W1 + W1_b + W2_b
__device__ float g_bias_v[H];        // sel_mg@V1 + V1_b + V2_b
__device__ float g_M[H*2];           // U_w @ cls_w
__device__ float g_c2[2];            // U_b @ cls_w
__device__ float g_logit_part[(size_t)RR*12];
__device__ float g_rv_part[(size_t)RR*24];  // [r][12][2]
__device__ float g_attn[RR];

// fp16 operands for the big GEMM (A single-rounded, B split hi+lo)
__device__ __half g_Ah[(size_t)RR*H2];       // ~100.7 MB
__device__ __half g_Bh[(size_t)H2*H2];       // [n][k], n<768: W2 col n; n>=768: V2 col n-768
__device__ __half g_Bl[(size_t)H2*H2];

// ---------------- fp32 packed helpers ----------------
__device__ __forceinline__ unsigned long long pk2(float lo, float hi){
    unsigned long long r;
    asm("mov.b64 %0, {%1, %2};" : "=l"(r) : "f"(lo), "f"(hi));
    return r;
}
__device__ __forceinline__ void up2(unsigned long long v, float& lo, float& hi){
    asm("mov.b64 {%0, %1}, %2;" : "=f"(lo), "=f"(hi) : "l"(v));
}
__device__ __forceinline__ void ffma2(unsigned long long& d, unsigned long long a, unsigned long long b){
    asm("fma.rn.f32x2 %0, %1, %2, %0;" : "+l"(d) : "l"(a), "l"(b));
}
__device__ __forceinline__ float wsum(float v){
    #pragma unroll
    for (int o=16;o;o>>=1) v += __shfl_xor_sync(0xffffffffu, v, o);
    return v;
}

// ---------------- mma.sync helpers (baseline sm_100 legal) ----------------
__device__ __forceinline__ uint32_t smem_u32(const void* p){
    uint32_t a;
    asm("{ .reg .u64 t; cvta.to.shared.u64 t, %1; cvt.u32.u64 %0, t; }" : "=r"(a) : "l"(p));
    return a;
}
__device__ __forceinline__ void ldm4(uint32_t* r, uint32_t addr){
    asm volatile("ldmatrix.sync.aligned.m8n8.x4.shared.b16 {%0,%1,%2,%3}, [%4];"
        : "=r"(r[0]),"=r"(r[1]),"=r"(r[2]),"=r"(r[3]) : "r"(addr));
}
__device__ __forceinline__ void mma_f16(float* c, const uint32_t* a, uint32_t b0, uint32_t b1){
    asm volatile("mma.sync.aligned.m16n8k16.row.col.f32.f16.f16.f32 "
        "{%0,%1,%2,%3}, {%4,%5,%6,%7}, {%8,%9}, {%0,%1,%2,%3};"
        : "+f"(c[0]),"+f"(c[1]),"+f"(c[2]),"+f"(c[3])
        : "r"(a[0]),"r"(a[1]),"r"(a[2]),"r"(a[3]), "r"(b0),"r"(b1));
}
__device__ __forceinline__ void cpa16(uint32_t s, const void* g){
    asm volatile("cp.async.cg.shared.global [%0], [%1], 16;" :: "r"(s), "l"(g));
}
__device__ __forceinline__ void cpa_commit(){ asm volatile("cp.async.commit_group;" ::: "memory"); }
__device__ __forceinline__ void cpa_wait3(){ asm volatile("cp.async.wait_group 3;" ::: "memory"); }

// ---------------- K1: pool + predicted vectors + A fp16 conversion (fused) ----------------
__global__ void k_pool(const float* __restrict__ dec, const float* __restrict__ gls,
                       const int* __restrict__ pred){
    int n = blockIdx.x;
    int p = pred[n];
    const float* db = dec + (size_t)n*KSEN*H;
    const float* gb = gls + (size_t)n*KSEN*H;
    for (int d = threadIdx.x; d < H; d += blockDim.x){
        float sd=0.f, sg=0.f;
        #pragma unroll
        for (int k=0;k<KSEN;k++){
            float vd = db[k*H+d];
            float vg = gb[k*H+d];
            sd += vd; sg += vg;
            size_t r = (size_t)(n*KSEN + k);
            g_Ah[r*H2 + d]     = __float2half_rn(vd);
            g_Ah[r*H2 + H + d] = __float2half_rn(vg);
        }
        float pd = db[p*H+d], pg = gb[p*H+d];
        g_feat[(size_t)n*H2 + d]      = pd - sd*(1.0f/16.0f);
        g_feat[(size_t)n*H2 + H + d]  = pg - sg*(1.0f/16.0f);
        g_predcat[(size_t)n*H2 + d]     = pd;
        g_predcat[(size_t)n*H2 + H + d] = pg;
    }
}

// ---------------- B transpose + fp16 split ----------------
__global__ void k_conv_b(const float* __restrict__ W2, const float* __restrict__ V2){
    __shared__ float tile[32][33];
    int nb = blockIdx.x;   // 48 tiles over n
    int kb = blockIdx.y;   // 48 tiles over k
    int tx = threadIdx.x & 31, ty = threadIdx.x >> 5;   // 32 x 8
    const float* src = (nb < 24) ? W2 : V2;
    int col0 = (nb % 24) * 32;
    #pragma unroll
    for (int j=0;j<4;j++){
        int kk = ty + j*8;
        tile[tx][kk] = src[(size_t)(kb*32 + kk)*H + col0 + tx];
    }
    __syncthreads();
    int n0 = nb*32;
    #pragma unroll
    for (int j=0;j<4;j++){
        int c = ty + j*8;
        float v = tile[c][tx];
        __half hi = __float2half_rn(v);
        __half lo = __float2half_rn(v - __half2float(hi));
        size_t di = (size_t)(n0 + c)*H2 + kb*32 + tx;
        g_Bh[di] = hi;
        g_Bl[di] = lo;
    }
}

// ---------------- K2: h = relu(feat @ s1_w + s1_b)  (exact fp32; argmax safety) ----------------
// 32x128 tiles, grid (6, 64) = 384 CTAs -> fills the chip.
__global__ void __launch_bounds__(256) k_gemm1(const float* __restrict__ B, const float* __restrict__ bias){
    __shared__ float As[16][33];
    __shared__ float Bs[16][128];
    int tid=threadIdx.x, bx=blockIdx.x, by=blockIdx.y;
    int tx=tid&15, ty=tid>>4;
    int arow=tid>>3, akc=(tid&7)*2;
    int bkr=tid>>4, bc0=(tid&15)*8;
    const float* Ap = g_feat + (size_t)(by*32+arow)*H2 + akc;
    const float* Bp = B + (size_t)bkr*H + bx*128 + bc0;
    unsigned long long acc[2][4];
    #pragma unroll
    for(int i=0;i<2;i++){
        #pragma unroll
        for(int j=0;j<4;j++) acc[i][j]=0ull;
    }
    for (int kt=0; kt<H2/16; kt++){
        float2 a0 = *(const float2*)(Ap + kt*16);
        As[akc  ][arow]=a0.x;
        As[akc+1][arow]=a0.y;
        const float* bsrc = Bp + (size_t)kt*16*H;
        *(float4*)&Bs[bkr][bc0]   = *(const float4*)(bsrc);
        *(float4*)&Bs[bkr][bc0+4] = *(const float4*)(bsrc+4);
        __syncthreads();
        #pragma unroll
        for (int k=0;k<16;k++){
            float ra[2];
            ra[0]=As[k][ty*2]; ra[1]=As[k][ty*2+1];
            float4 bb0 = *(float4*)&Bs[k][tx*8];
            float4 bb1 = *(float4*)&Bs[k][tx*8+4];
            unsigned long long rb[4];
            rb[0]=pk2(bb0.x,bb0.y); rb[1]=pk2(bb0.z,bb0.w);
            rb[2]=pk2(bb1.x,bb1.y); rb[3]=pk2(bb1.z,bb1.w);
            #pragma unroll
            for (int i=0;i<2;i++){
                unsigned long long aa = pk2(ra[i],ra[i]);
                #pragma unroll
                for (int jp=0;jp<4;jp++) ffma2(acc[i][jp], aa, rb[jp]);
            }
        }
        __syncthreads();
    }
    int gc = bx*128 + tx*8;
    float bias8[8];
    #pragma unroll
    for (int j=0;j<8;j++) bias8[j]=bias[gc+j];
    #pragma unroll
    for (int i=0;i<2;i++){
        int row = by*32 + ty*2 + i;
        float v[8];
        #pragma unroll
        for (int jp=0;jp<4;jp++) up2(acc[i][jp], v[2*jp], v[2*jp+1]);
        float o[8];
        #pragma unroll
        for (int j=0;j<8;j++){ float t=v[j]+bias8[j]; o[j]= t>0.f? t : 0.f; }
        float4* dst=(float4*)(g_h + (size_t)row*H + gc);
        dst[0]=make_float4(o[0],o[1],o[2],o[3]);
        dst[1]=make_float4(o[4],o[5],o[6],o[7]);
    }
}

// ---------------- K3: score[n] = h[n] . s2_w + s2_b ----------------
__global__ void k_score(const float* __restrict__ s2w, const float* __restrict__ s2b){
    int w = (blockIdx.x*blockDim.x + threadIdx.x) >> 5;
    int lane = threadIdx.x & 31;
    if (w >= NI) return;
    const float* hr = g_h + (size_t)w*H;
    float s=0.f;
    for (int j=lane;j<H;j+=32) s += hr[j]*s2w[j];
    s = wsum(s);
    if (lane==0) g_score[w] = s + s2b[0];
}

// ---------------- K4: softmax over N + first-occurrence argmax ----------------
__global__ void k_softmax(float* __restrict__ probs){
    __shared__ float sv[1024];
    __shared__ int   si[1024];
    int tid=threadIdx.x;
    float a=g_score[tid], b=g_score[tid+1024];
    float m; int mi;
    if (a>=b){ m=a; mi=tid; } else { m=b; mi=tid+1024; }
    sv[tid]=m; si[tid]=mi;
    __syncthreads();
    for (int s=512;s>0;s>>=1){
        if (tid<s){
            float ov=sv[tid+s]; int oi=si[tid+s];
            if (ov>sv[tid] || (ov==sv[tid] && oi<si[tid])){ sv[tid]=ov; si[tid]=oi; }
        }
        __syncthreads();
    }
    float mx = sv[0]; int sel = si[0];
    if (tid==0) g_sel = sel;
    __syncthreads();
    float e0 = expf(a-mx), e1 = expf(b-mx);
    sv[tid] = e0+e1;
    __syncthreads();
    for (int s=512;s>0;s>>=1){ if (tid<s) sv[tid]+=sv[tid+s]; __syncthreads(); }
    float inv = 1.0f/sv[0];
    probs[tid]      = e0*inv;
    probs[tid+1024] = e1*inv;
}

// ---------------- K5a: M = U_w @ cls_w, c2 = U_b @ cls_w ----------------
__global__ void k_mcls(const float* __restrict__ Uw, const float* __restrict__ Ub,
                       const float* __restrict__ clsw){
    int j = blockIdx.x*128 + threadIdx.x;
    const float* ur = Uw + (size_t)j*H;
    float m0=0.f, m1=0.f;
    for (int t=0;t<H;t++){ float u=ur[t]; m0+=u*clsw[2*t]; m1+=u*clsw[2*t+1]; }
    g_M[2*j]=m0; g_M[2*j+1]=m1;
    if (blockIdx.x==0 && threadIdx.x<2){
        int c=threadIdx.x; float s=0.f;
        for (int t=0;t<H;t++) s += Ub[t]*clsw[2*t+c];
        g_c2[c]=s;
    }
}

// ---------------- K5b: sel-dependent bias vectors ----------------
__global__ void k_bias(const float* __restrict__ W1, const float* __restrict__ W1b, const float* __restrict__ W2b,
                       const float* __restrict__ V1, const float* __restrict__ V1b, const float* __restrict__ V2b){
    int half = (blockIdx.x < 6) ? 0 : 1;
    int j = ((half ? blockIdx.x-6 : blockIdx.x)*128) + threadIdx.x;
    int sel = g_sel;
    const float* m = half ? V1 : W1;
    const float* srow = g_predcat + (size_t)sel*H2;
    float s=0.f;
    for (int i=0;i<H2;i++) s += srow[i]*m[(size_t)i*H + j];
    if (half) g_bias_v[j]    = s + V1b[j] + V2b[j];
    else      g_bias_attn[j] = s + W1b[j] + W2b[j];
}

// ---------------- K6: mma.sync fp16 2-product GEMM [32768,1536]@[1536,1536] + reduce ----------------
// grid (12, 256): cb = 128-col block (cb<6: W2, else V2), by = 128-row block.
// CTA 128x128, 256 thr, warps 4(M)x2(N), warp tile 32x64.
// SMEM per stage: A | Bh | Bl each 128 rows x 32 halfs (80B padded stride) = 10240 B. 4 stages.
#define KB_REGION 10240
#define KB_STAGE  30720
#define KB_SMEM   (4*KB_STAGE)
#define KB_ITERS  48

__device__ __forceinline__ void kb_load_stage(uint32_t sb, int stage, int by, int cb, int gk, int tid){
    uint32_t s0 = sb + stage*KB_STAGE;
    #pragma unroll
    for (int j=0;j<6;j++){
        int idx = j*256 + tid;        // 0..1535
        int region = idx >> 9;        // 0 A, 1 Bh, 2 Bl
        int cl = idx & 511;
        int r  = cl >> 2;
        int kc = cl & 3;
        const __half* g;
        size_t grow;
        if (region == 0){ g = g_Ah; grow = (size_t)(by*128 + r); }
        else if (region == 1){ g = g_Bh; grow = (size_t)(cb*128 + r); }
        else { g = g_Bl; grow = (size_t)(cb*128 + r); }
        cpa16(s0 + region*KB_REGION + r*80 + kc*16, g + grow*H2 + gk + kc*8);
    }
}

__global__ void __launch_bounds__(256,1) k_big_mma(const float* __restrict__ Wa){
    extern __shared__ char smem[];
    uint32_t sb = smem_u32(smem);
    int tid = threadIdx.x;
    int cb = blockIdx.x, by = blockIdx.y;
    int warp = tid >> 5, lane = tid & 31;
    int wm = warp & 3, wn = warp >> 2;      // wm 0..3 (M), wn 0..1 (N)

    float acc[2][8][4];
    #pragma unroll
    for (int mt=0;mt<2;mt++)
        #pragma unroll
        for (int nt=0;nt<8;nt++)
            #pragma unroll
            for (int d=0;d<4;d++) acc[mt][nt][d] = 0.f;

    kb_load_stage(sb, 0, by, cb, 0,  tid); cpa_commit();
    kb_load_stage(sb, 1, by, cb, 32, tid); cpa_commit();
    kb_load_stage(sb, 2, by, cb, 64, tid); cpa_commit();

    int m8 = lane >> 3, r8 = lane & 7;

    for (int it = 0; it < KB_ITERS; it++){
        if (it) __syncthreads();   // all warps done with stage (it-1)&3 before it is overwritten
        if (it + 3 < KB_ITERS) kb_load_stage(sb, (it+3)&3, by, cb, (it+3)*32, tid);
        cpa_commit();              // empty group at tail keeps wait_group count aligned
        cpa_wait3();
        __syncthreads();

        uint32_t st = sb + (it&3)*KB_STAGE;
        #pragma unroll
        for (int kh=0; kh<2; kh++){
            int k0 = kh*16;
            uint32_t ah[2][4], bh[4][4], bl[4][4];
            #pragma unroll
            for (int mt=0;mt<2;mt++){
                int rowA = wm*32 + mt*16 + (m8&1)*8 + r8;
                int kA   = k0 + (m8>>1)*8;
                ldm4(ah[mt], st + 0*KB_REGION + rowA*80 + kA*2);
            }
            #pragma unroll
            for (int ntp=0;ntp<4;ntp++){
                int rowB = wn*64 + ntp*16 + (m8>>1)*8 + r8;
                int kB   = k0 + (m8&1)*8;
                uint32_t boff = rowB*80 + kB*2;
                ldm4(bh[ntp], st + 1*KB_REGION + boff);
                ldm4(bl[ntp], st + 2*KB_REGION + boff);
            }
            // product 1: A * Bh  (16 independent accumulators)
            #pragma unroll
            for (int mt=0;mt<2;mt++)
                #pragma unroll
                for (int nt=0;nt<8;nt++)
                    mma_f16(acc[mt][nt], ah[mt], bh[nt>>1][(nt&1)*2], bh[nt>>1][(nt&1)*2+1]);
            // product 2: A * Bl
            #pragma unroll
            for (int mt=0;mt<2;mt++)
                #pragma unroll
                for (int nt=0;nt<8;nt++)
                    mma_f16(acc[mt][nt], ah[mt], bl[nt>>1][(nt&1)*2], bl[nt>>1][(nt&1)*2+1]);
        }
    }

    // ---------------- epilogue: reduce over the 128 columns this CTA owns ----------------
    int quad = lane >> 2, qt = lane & 3;
    if (cb < 6){
        int colb = cb*128;
        #pragma unroll
        for (int mt=0;mt<2;mt++){
            float plo = 0.f, phi = 0.f;
            #pragma unroll
            for (int nt=0;nt<8;nt++){
                int g0 = colb + wn*64 + nt*8 + qt*2;
                float ba0 = g_bias_attn[g0],  ba1 = g_bias_attn[g0+1];
                float w0  = Wa[g0],           w1  = Wa[g0+1];
                plo += tanhf(acc[mt][nt][0]+ba0)*w0 + tanhf(acc[mt][nt][1]+ba1)*w1;
                phi += tanhf(acc[mt][nt][2]+ba0)*w0 + tanhf(acc[mt][nt][3]+ba1)*w1;
            }
            plo += __shfl_xor_sync(0xffffffffu, plo, 1);
            plo += __shfl_xor_sync(0xffffffffu, plo, 2);
            phi += __shfl_xor_sync(0xffffffffu, phi, 1);
            phi += __shfl_xor_sync(0xffffffffu, phi, 2);
            if (qt == 0){
                int rlo = by*128 + wm*32 + mt*16 + quad;
                g_logit_part[(size_t)rlo*12 + cb*2 + wn]     = plo;
                g_logit_part[(size_t)(rlo+8)*12 + cb*2 + wn] = phi;
            }
        }
    } else {
        int cbv = cb - 6, colb = cbv*128, slot = cbv*2 + wn;
        #pragma unroll
        for (int mt=0;mt<2;mt++){
            float p0l=0.f, p1l=0.f, p0h=0.f, p1h=0.f;
            #pragma unroll
            for (int nt=0;nt<8;nt++){
                int g0 = colb + wn*64 + nt*8 + qt*2;
                float bv0 = g_bias_v[g0], bv1 = g_bias_v[g0+1];
                float m00 = g_M[2*g0],   m01 = g_M[2*g0+1];
                float m10 = g_M[2*g0+2], m11 = g_M[2*g0+3];
                float x;
                x = acc[mt][nt][0]+bv0; x = x>0.f? x:0.f; p0l += x*m00; p1l += x*m01;
                x = acc[mt][nt][1]+bv1; x = x>0.f? x:0.f; p0l += x*m10; p1l += x*m11;
                x = acc[mt][nt][2]+bv0; x = x>0.f? x:0.f; p0h += x*m00; p1h += x*m01;
                x = acc[mt][nt][3]+bv1; x = x>0.f? x:0.f; p0h += x*m10; p1h += x*m11;
            }
            p0l += __shfl_xor_sync(0xffffffffu, p0l, 1); p0l += __shfl_xor_sync(0xffffffffu, p0l, 2);
            p1l += __shfl_xor_sync(0xffffffffu, p1l, 1); p1l += __shfl_xor_sync(0xffffffffu, p1l, 2);
            p0h += __shfl_xor_sync(0xffffffffu, p0h, 1); p0h += __shfl_xor_sync(0xffffffffu, p0h, 2);
            p1h += __shfl_xor_sync(0xffffffffu, p1h, 1); p1h += __shfl_xor_sync(0xffffffffu, p1h, 2);
            if (qt == 0){
                int rlo = by*128 + wm*32 + mt*16 + quad;
                g_rv_part[(size_t)rlo*24 + slot*2 + 0] = p0l;
                g_rv_part[(size_t)rlo*24 + slot*2 + 1] = p1l;
                g_rv_part[(size_t)(rlo+8)*24 + slot*2 + 0] = p0h;
                g_rv_part[(size_t)(rlo+8)*24 + slot*2 + 1] = p1h;
            }
        }
    }
}

// ---------------- K7: per-instance softmax over K senses ----------------
__global__ void k_attn(const float* __restrict__ Wab){
    int n = blockIdx.x, lane = threadIdx.x;
    float lg = -INFINITY;
    if (lane < KSEN){
        int r = n*KSEN + lane;
        float s = Wab[0];
        #pragma unroll
        for (int p=0;p<12;p++) s += g_logit_part[(size_t)r*12+p];
        lg = s;
    }
    float m = lg;
    #pragma unroll
    for (int o=16;o;o>>=1) m = fmaxf(m, __shfl_xor_sync(0xffffffffu, m, o));
    float e = (lane < KSEN) ? expf(lg - m) : 0.f;
    float t = wsum(e);
    if (lane < KSEN) g_attn[n*KSEN + lane] = e/t;
}

// ---------------- K8: final logits ----------------
__global__ void k_final(const float* __restrict__ dec, const float* __restrict__ clsw,
                        const float* __restrict__ clsb, float* __restrict__ out){
    int r = blockIdx.x*8 + (threadIdx.x>>5);
    int lane = threadIdx.x & 31;
    const float* drow = dec + (size_t)r*H;
    float a0=0.f, a1=0.f;
    for (int t=lane;t<H;t+=32){ float d=drow[t]; a0 += d*clsw[2*t]; a1 += d*clsw[2*t+1]; }
    a0=wsum(a0); a1=wsum(a1);
    if (lane==0){
        int n = r >> 4;
        float o0 = a0 + clsb[0], o1 = a1 + clsb[1];
        if (n != g_sel){
            float rv0=g_c2[0], rv1=g_c2[1];
            #pragma unroll
            for (int p=0;p<12;p++){ rv0 += g_rv_part[(size_t)r*24 + p*2]; rv1 += g_rv_part[(size_t)r*24 + p*2 + 1]; }
            float at = g_attn[r];
            o0 += at*rv0; o1 += at*rv1;
        }
        out[2*r]   = o0;
        out[2*r+1] = o1;
    }
}

// ---------------- launcher ----------------
extern "C" void kernel_launch(void* const* d_in, const int* in_sizes, int n_in,
                              void* d_out, int out_size){
    (void)n_in; (void)out_size;
    const float *dec,*gls,*s1w,*s1b,*s2w,*s2b,*W1w,*W1b,*W2w,*W2b,*Waw,*Wab,*V1w,*V1b,*V2w,*V2b,*Uw,*Ub,*clsw,*clsb;
    const int* pred;
    if (in_sizes[2] == NI){
        dec=(const float*)d_in[0]; gls=(const float*)d_in[1]; pred=(const int*)d_in[2];
        s1w=(const float*)d_in[3];  s1b=(const float*)d_in[4];
        s2w=(const float*)d_in[5];  s2b=(const float*)d_in[6];
        W1w=(const float*)d_in[7];  W1b=(const float*)d_in[8];
        W2w=(const float*)d_in[9];  W2b=(const float*)d_in[10];
        Waw=(const float*)d_in[11]; Wab=(const float*)d_in[12];
        V1w=(const float*)d_in[13]; V1b=(const float*)d_in[14];
        V2w=(const float*)d_in[15]; V2b=(const float*)d_in[16];
        Uw =(const float*)d_in[17]; Ub =(const float*)d_in[18];
        clsw=(const float*)d_in[19]; clsb=(const float*)d_in[20];
    } else {
        dec=(const float*)d_in[0]; gls=(const float*)d_in[1];
        s1w=(const float*)d_in[2];  s1b=(const float*)d_in[3];
        s2w=(const float*)d_in[4];  s2b=(const float*)d_in[5];
        W1w=(const float*)d_in[6];  W1b=(const float*)d_in[7];
        W2w=(const float*)d_in[8];  W2b=(const float*)d_in[9];
        Waw=(const float*)d_in[10]; Wab=(const float*)d_in[11];
        V1w=(const float*)d_in[12]; V1b=(const float*)d_in[13];
        V2w=(const float*)d_in[14]; V2b=(const float*)d_in[15];
        Uw =(const float*)d_in[16]; Ub =(const float*)d_in[17];
        clsw=(const float*)d_in[18]; clsb=(const float*)d_in[19];
        pred=(const int*)d_in[20];
    }
    float* out = (float*)d_out;

    cudaFuncSetAttribute(k_big_mma, cudaFuncAttributeMaxDynamicSharedMemorySize, KB_SMEM);

    k_conv_b <<<dim3(48,48), 256>>>(W2w, V2w);
    k_pool   <<<NI, 256>>>(dec, gls, pred);
    k_gemm1  <<<dim3(6,64), 256>>>(s1w, s1b);
    k_score  <<<256, 256>>>(s2w, s2b);
    k_softmax<<<1, 1024>>>(out + 2*RR);
    k_mcls   <<<6, 128>>>(Uw, Ub, clsw);
    k_bias   <<<12, 128>>>(W1w, W1b, W2b, V1w, V1b, V2b);
    k_big_mma<<<dim3(12, 256), 256, KB_SMEM>>>(Waw);
    k_attn   <<<NI, 32>>>(Wab);
    k_final  <<<RR/8, 256>>>(dec, clsw, clsb, out);
}

// round 7
// speedup vs baseline: 2.7107x; 1.2404x over previous
#include <cuda_runtime.h>
#include <cuda_fp16.h>
#include <math.h>
#include <stdint.h>

// Problem constants
#define NI 2048
#define KSEN 16
#define H 768
#define H2 1536
#define RR (NI*KSEN)   // 32768

// ---------------- device scratch (static; no allocations) ----------------
__device__ float g_feat[NI*H2];      // pooled concat features [N,2H]
__device__ float g_predcat[NI*H2];   // concat(pred_dec, pred_gls) [N,2H]
__device__ float g_score[NI];
__device__ int   g_sel;
__device__ float g_bias_attn[H];     // sel_mg@W1 + W1_b + W2_b
__device__ float g_bias_v[H];        // sel_mg@V1 + V1_b + V2_b
__device__ float g_M[H*2];           // U_w @ cls_w
__device__ float g_c2[2];            // U_b @ cls_w
__device__ float g_logit_part[(size_t)RR*12];
__device__ float g_rv_part[(size_t)RR*24];  // [r][12][2]
__device__ float g_attn[RR];

// fp16 operands for the big GEMM (A single-rounded, B split hi+lo)
__device__ __half g_Ah[(size_t)RR*H2];       // ~100.7 MB
__device__ __half g_Bh[(size_t)H2*H2];       // [n][k], n<768: W2 col n; n>=768: V2 col n-768
__device__ __half g_Bl[(size_t)H2*H2];

// ---------------- fp32 packed helpers ----------------
__device__ __forceinline__ unsigned long long pk2(float lo, float hi){
    unsigned long long r;
    asm("mov.b64 %0, {%1, %2};" : "=l"(r) : "f"(lo), "f"(hi));
    return r;
}
__device__ __forceinline__ void up2(unsigned long long v, float& lo, float& hi){
    asm("mov.b64 {%0, %1}, %2;" : "=f"(lo), "=f"(hi) : "l"(v));
}
__device__ __forceinline__ void ffma2(unsigned long long& d, unsigned long long a, unsigned long long b){
    asm("fma.rn.f32x2 %0, %1, %2, %0;" : "+l"(d) : "l"(a), "l"(b));
}
__device__ __forceinline__ float wsum(float v){
    #pragma unroll
    for (int o=16;o;o>>=1) v += __shfl_xor_sync(0xffffffffu, v, o);
    return v;
}

// ---------------- mma.sync helpers (baseline sm_100 legal) ----------------
__device__ __forceinline__ uint32_t smem_u32(const void* p){
    uint32_t a;
    asm("{ .reg .u64 t; cvta.to.shared.u64 t, %1; cvt.u32.u64 %0, t; }" : "=r"(a) : "l"(p));
    return a;
}
__device__ __forceinline__ void ldm4(uint32_t* r, uint32_t addr){
    asm volatile("ldmatrix.sync.aligned.m8n8.x4.shared.b16 {%0,%1,%2,%3}, [%4];"
        : "=r"(r[0]),"=r"(r[1]),"=r"(r[2]),"=r"(r[3]) : "r"(addr));
}
__device__ __forceinline__ void mma_f16(float* c, const uint32_t* a, uint32_t b0, uint32_t b1){
    asm volatile("mma.sync.aligned.m16n8k16.row.col.f32.f16.f16.f32 "
        "{%0,%1,%2,%3}, {%4,%5,%6,%7}, {%8,%9}, {%0,%1,%2,%3};"
        : "+f"(c[0]),"+f"(c[1]),"+f"(c[2]),"+f"(c[3])
        : "r"(a[0]),"r"(a[1]),"r"(a[2]),"r"(a[3]), "r"(b0),"r"(b1));
}
__device__ __forceinline__ void cpa16(uint32_t s, const void* g){
    asm volatile("cp.async.cg.shared.global [%0], [%1], 16;" :: "r"(s), "l"(g));
}
__device__ __forceinline__ void cpa_commit(){ asm volatile("cp.async.commit_group;" ::: "memory"); }
__device__ __forceinline__ void cpa_wait2(){ asm volatile("cp.async.wait_group 2;" ::: "memory"); }

// ---------------- K1: pool + predicted vectors + A fp16 conversion + score zeroing ----------------
__global__ void k_pool(const float* __restrict__ dec, const float* __restrict__ gls,
                       const int* __restrict__ pred){
    int n = blockIdx.x;
    int p = pred[n];
    if (threadIdx.x == 0) g_score[n] = 0.f;
    const float* db = dec + (size_t)n*KSEN*H;
    const float* gb = gls + (size_t)n*KSEN*H;
    for (int d = threadIdx.x; d < H; d += blockDim.x){
        float sd=0.f, sg=0.f;
        #pragma unroll
        for (int k=0;k<KSEN;k++){
            float vd = db[k*H+d];
            float vg = gb[k*H+d];
            sd += vd; sg += vg;
            size_t r = (size_t)(n*KSEN + k);
            g_Ah[r*H2 + d]     = __float2half_rn(vd);
            g_Ah[r*H2 + H + d] = __float2half_rn(vg);
        }
        float pd = db[p*H+d], pg = gb[p*H+d];
        g_feat[(size_t)n*H2 + d]      = pd - sd*(1.0f/16.0f);
        g_feat[(size_t)n*H2 + H + d]  = pg - sg*(1.0f/16.0f);
        g_predcat[(size_t)n*H2 + d]     = pd;
        g_predcat[(size_t)n*H2 + H + d] = pg;
    }
}

// ---------------- K2: h=relu(feat@s1_w+s1_b); fused score atomics (s2_b dropped: shift-inv) ----------------
__global__ void __launch_bounds__(256) k_gemm1(const float* __restrict__ B, const float* __restrict__ bias,
                                               const float* __restrict__ s2w){
    __shared__ float As[16][33];
    __shared__ float Bs[16][128];
    int tid=threadIdx.x, bx=blockIdx.x, by=blockIdx.y;
    int tx=tid&15, ty=tid>>4;
    int arow=tid>>3, akc=(tid&7)*2;
    int bkr=tid>>4, bc0=(tid&15)*8;
    const float* Ap = g_feat + (size_t)(by*32+arow)*H2 + akc;
    const float* Bp = B + (size_t)bkr*H + bx*128 + bc0;
    unsigned long long acc[2][4];
    #pragma unroll
    for(int i=0;i<2;i++){
        #pragma unroll
        for(int j=0;j<4;j++) acc[i][j]=0ull;
    }
    for (int kt=0; kt<H2/16; kt++){
        float2 a0 = *(const float2*)(Ap + kt*16);
        As[akc  ][arow]=a0.x;
        As[akc+1][arow]=a0.y;
        const float* bsrc = Bp + (size_t)kt*16*H;
        *(float4*)&Bs[bkr][bc0]   = *(const float4*)(bsrc);
        *(float4*)&Bs[bkr][bc0+4] = *(const float4*)(bsrc+4);
        __syncthreads();
        #pragma unroll
        for (int k=0;k<16;k++){
            float ra[2];
            ra[0]=As[k][ty*2]; ra[1]=As[k][ty*2+1];
            float4 bb0 = *(float4*)&Bs[k][tx*8];
            float4 bb1 = *(float4*)&Bs[k][tx*8+4];
            unsigned long long rb[4];
            rb[0]=pk2(bb0.x,bb0.y); rb[1]=pk2(bb0.z,bb0.w);
            rb[2]=pk2(bb1.x,bb1.y); rb[3]=pk2(bb1.z,bb1.w);
            #pragma unroll
            for (int i=0;i<2;i++){
                unsigned long long aa = pk2(ra[i],ra[i]);
                #pragma unroll
                for (int jp=0;jp<4;jp++) ffma2(acc[i][jp], aa, rb[jp]);
            }
        }
        __syncthreads();
    }
    int gc = bx*128 + tx*8;
    float bias8[8], sw8[8];
    #pragma unroll
    for (int j=0;j<8;j++){ bias8[j]=bias[gc+j]; sw8[j]=s2w[gc+j]; }
    #pragma unroll
    for (int i=0;i<2;i++){
        int row = by*32 + ty*2 + i;
        float v[8];
        #pragma unroll
        for (int jp=0;jp<4;jp++) up2(acc[i][jp], v[2*jp], v[2*jp+1]);
        float o[8], p = 0.f;
        #pragma unroll
        for (int j=0;j<8;j++){ float t=v[j]+bias8[j]; o[j]= t>0.f? t : 0.f; p += o[j]*sw8[j]; }
        // 16-lane reduce over tx (lanes [0,16) and [16,32) are independent ty groups)
        p += __shfl_xor_sync(0xffffffffu, p, 1);
        p += __shfl_xor_sync(0xffffffffu, p, 2);
        p += __shfl_xor_sync(0xffffffffu, p, 4);
        p += __shfl_xor_sync(0xffffffffu, p, 8);
        if (tx == 0) atomicAdd(&g_score[row], p);
    }
}

// ---------------- K3: softmax over N + first-occurrence argmax ----------------
__global__ void k_softmax(float* __restrict__ probs){
    __shared__ float sv[1024];
    __shared__ int   si[1024];
    int tid=threadIdx.x;
    float a=g_score[tid], b=g_score[tid+1024];
    float m; int mi;
    if (a>=b){ m=a; mi=tid; } else { m=b; mi=tid+1024; }
    sv[tid]=m; si[tid]=mi;
    __syncthreads();
    for (int s=512;s>0;s>>=1){
        if (tid<s){
            float ov=sv[tid+s]; int oi=si[tid+s];
            if (ov>sv[tid] || (ov==sv[tid] && oi<si[tid])){ sv[tid]=ov; si[tid]=oi; }
        }
        __syncthreads();
    }
    float mx = sv[0]; int sel = si[0];
    if (tid==0) g_sel = sel;
    __syncthreads();
    float e0 = expf(a-mx), e1 = expf(b-mx);
    sv[tid] = e0+e1;
    __syncthreads();
    for (int s=512;s>0;s>>=1){ if (tid<s) sv[tid]+=sv[tid+s]; __syncthreads(); }
    float inv = 1.0f/sv[0];
    probs[tid]      = e0*inv;
    probs[tid+1024] = e1*inv;
}

// ---------------- K4: fused sel-dependent biases + M = U_w@cls_w ----------------
// blocks 0..11: bias vectors; blocks 12..17: M / c2
__global__ void k_biasmcls(const float* __restrict__ W1, const float* __restrict__ W1b, const float* __restrict__ W2b,
                           const float* __restrict__ V1, const float* __restrict__ V1b, const float* __restrict__ V2b,
                           const float* __restrict__ Uw, const float* __restrict__ Ub,
                           const float* __restrict__ clsw){
    int blk = blockIdx.x;
    if (blk < 12){
        int half = (blk < 6) ? 0 : 1;
        int j = ((half ? blk-6 : blk)*128) + threadIdx.x;
        int sel = g_sel;
        const float* m = half ? V1 : W1;
        const float* srow = g_predcat + (size_t)sel*H2;
        float s=0.f;
        for (int i=0;i<H2;i++) s += srow[i]*m[(size_t)i*H + j];
        if (half) g_bias_v[j]    = s + V1b[j] + V2b[j];
        else      g_bias_attn[j] = s + W1b[j] + W2b[j];
    } else {
        int j = (blk-12)*128 + threadIdx.x;
        const float* ur = Uw + (size_t)j*H;
        float m0=0.f, m1=0.f;
        for (int t=0;t<H;t++){ float u=ur[t]; m0+=u*clsw[2*t]; m1+=u*clsw[2*t+1]; }
        g_M[2*j]=m0; g_M[2*j+1]=m1;
        if (blk==12 && threadIdx.x<2){
            int c=threadIdx.x; float s=0.f;
            for (int t=0;t<H;t++) s += Ub[t]*clsw[2*t+c];
            g_c2[c]=s;
        }
    }
}

// ---------------- K5: B transpose + fp16 split ----------------
__global__ void k_conv_b(const float* __restrict__ W2, const float* __restrict__ V2){
    __shared__ float tile[32][33];
    int nb = blockIdx.x;   // 48 tiles over n
    int kb = blockIdx.y;   // 48 tiles over k
    int tx = threadIdx.x & 31, ty = threadIdx.x >> 5;   // 32 x 8
    const float* src = (nb < 24) ? W2 : V2;
    int col0 = (nb % 24) * 32;
    #pragma unroll
    for (int j=0;j<4;j++){
        int kk = ty + j*8;
        tile[tx][kk] = src[(size_t)(kb*32 + kk)*H + col0 + tx];
    }
    __syncthreads();
    int n0 = nb*32;
    #pragma unroll
    for (int j=0;j<4;j++){
        int c = ty + j*8;
        float v = tile[c][tx];
        __half hi = __float2half_rn(v);
        __half lo = __float2half_rn(v - __half2float(hi));
        size_t di = (size_t)(n0 + c)*H2 + kb*32 + tx;
        g_Bh[di] = hi;
        g_Bl[di] = lo;
    }
}

// ---------------- K6: mma.sync fp16 2-product GEMM [32768,1536]@[1536,1536] + reduce ----------------
// grid (12, 256), CTA 128x128, 256 thr, warps 4(M)x2(N), warp tile 32x64.
// 3-stage cp.async pipeline, occupancy 2.
#define KB_REGION 10240
#define KB_STAGE  30720
#define KB_SMEM   (3*KB_STAGE)
#define KB_ITERS  48

__device__ __forceinline__ void kb_load_stage(uint32_t sb, int stage, int by, int cb, int gk, int tid){
    uint32_t s0 = sb + stage*KB_STAGE;
    #pragma unroll
    for (int j=0;j<6;j++){
        int idx = j*256 + tid;        // 0..1535
        int region = idx >> 9;        // 0 A, 1 Bh, 2 Bl
        int cl = idx & 511;
        int r  = cl >> 2;
        int kc = cl & 3;
        const __half* g;
        size_t grow;
        if (region == 0){ g = g_Ah; grow = (size_t)(by*128 + r); }
        else if (region == 1){ g = g_Bh; grow = (size_t)(cb*128 + r); }
        else { g = g_Bl; grow = (size_t)(cb*128 + r); }
        cpa16(s0 + region*KB_REGION + r*80 + kc*16, g + grow*H2 + gk + kc*8);
    }
}

__global__ void __launch_bounds__(256,2) k_big_mma(const float* __restrict__ Wa){
    extern __shared__ char smem[];
    uint32_t sb = smem_u32(smem);
    int tid = threadIdx.x;
    int cb = blockIdx.x, by = blockIdx.y;
    int warp = tid >> 5, lane = tid & 31;
    int wm = warp & 3, wn = warp >> 2;      // wm 0..3 (M), wn 0..1 (N)

    float acc[2][8][4];
    #pragma unroll
    for (int mt=0;mt<2;mt++)
        #pragma unroll
        for (int nt=0;nt<8;nt++)
            #pragma unroll
            for (int d=0;d<4;d++) acc[mt][nt][d] = 0.f;

    kb_load_stage(sb, 0, by, cb, 0,  tid); cpa_commit();
    kb_load_stage(sb, 1, by, cb, 32, tid); cpa_commit();

    int m8 = lane >> 3, r8 = lane & 7;

    for (int it = 0; it < KB_ITERS; it++){
        int s_now = it % 3;
        if (it) __syncthreads();   // all warps done with stage (it-1)%3 == (it+2)%3 before overwrite
        if (it + 2 < KB_ITERS) kb_load_stage(sb, (it+2)%3, by, cb, (it+2)*32, tid);
        cpa_commit();              // empty group at tail keeps wait count aligned
        cpa_wait2();               // stage s_now complete
        __syncthreads();

        uint32_t st = sb + s_now*KB_STAGE;
        #pragma unroll
        for (int kh=0; kh<2; kh++){
            int k0 = kh*16;
            uint32_t ah[2][4], bb[4][4];
            #pragma unroll
            for (int mt=0;mt<2;mt++){
                int rowA = wm*32 + mt*16 + (m8&1)*8 + r8;
                int kA   = k0 + (m8>>1)*8;
                ldm4(ah[mt], st + 0*KB_REGION + rowA*80 + kA*2);
            }
            int rowB = wn*64 + (m8>>1)*8 + r8;
            int kB   = k0 + (m8&1)*8;
            uint32_t boff = rowB*80 + kB*2;
            // product 1: A * Bh
            #pragma unroll
            for (int ntp=0;ntp<4;ntp++) ldm4(bb[ntp], st + 1*KB_REGION + boff + ntp*16*80);
            #pragma unroll
            for (int mt=0;mt<2;mt++)
                #pragma unroll
                for (int nt=0;nt<8;nt++)
                    mma_f16(acc[mt][nt], ah[mt], bb[nt>>1][(nt&1)*2], bb[nt>>1][(nt&1)*2+1]);
            // product 2: A * Bl (reuse fragment registers)
            #pragma unroll
            for (int ntp=0;ntp<4;ntp++) ldm4(bb[ntp], st + 2*KB_REGION + boff + ntp*16*80);
            #pragma unroll
            for (int mt=0;mt<2;mt++)
                #pragma unroll
                for (int nt=0;nt<8;nt++)
                    mma_f16(acc[mt][nt], ah[mt], bb[nt>>1][(nt&1)*2], bb[nt>>1][(nt&1)*2+1]);
        }
    }

    // ---------------- epilogue: reduce over the 128 columns this CTA owns ----------------
    int quad = lane >> 2, qt = lane & 3;
    if (cb < 6){
        int colb = cb*128;
        #pragma unroll
        for (int mt=0;mt<2;mt++){
            float plo = 0.f, phi = 0.f;
            #pragma unroll
            for (int nt=0;nt<8;nt++){
                int g0 = colb + wn*64 + nt*8 + qt*2;
                float ba0 = g_bias_attn[g0],  ba1 = g_bias_attn[g0+1];
                float w0  = Wa[g0],           w1  = Wa[g0+1];
                plo += tanhf(acc[mt][nt][0]+ba0)*w0 + tanhf(acc[mt][nt][1]+ba1)*w1;
                phi += tanhf(acc[mt][nt][2]+ba0)*w0 + tanhf(acc[mt][nt][3]+ba1)*w1;
            }
            plo += __shfl_xor_sync(0xffffffffu, plo, 1);
            plo += __shfl_xor_sync(0xffffffffu, plo, 2);
            phi += __shfl_xor_sync(0xffffffffu, phi, 1);
            phi += __shfl_xor_sync(0xffffffffu, phi, 2);
            if (qt == 0){
                int rlo = by*128 + wm*32 + mt*16 + quad;
                g_logit_part[(size_t)rlo*12 + cb*2 + wn]     = plo;
                g_logit_part[(size_t)(rlo+8)*12 + cb*2 + wn] = phi;
            }
        }
    } else {
        int cbv = cb - 6, colb = cbv*128, slot = cbv*2 + wn;
        #pragma unroll
        for (int mt=0;mt<2;mt++){
            float p0l=0.f, p1l=0.f, p0h=0.f, p1h=0.f;
            #pragma unroll
            for (int nt=0;nt<8;nt++){
                int g0 = colb + wn*64 + nt*8 + qt*2;
                float bv0 = g_bias_v[g0], bv1 = g_bias_v[g0+1];
                float m00 = g_M[2*g0],   m01 = g_M[2*g0+1];
                float m10 = g_M[2*g0+2], m11 = g_M[2*g0+3];
                float x;
                x = acc[mt][nt][0]+bv0; x = x>0.f? x:0.f; p0l += x*m00; p1l += x*m01;
                x = acc[mt][nt][1]+bv1; x = x>0.f? x:0.f; p0l += x*m10; p1l += x*m11;
                x = acc[mt][nt][2]+bv0; x = x>0.f? x:0.f; p0h += x*m00; p1h += x*m01;
                x = acc[mt][nt][3]+bv1; x = x>0.f? x:0.f; p0h += x*m10; p1h += x*m11;
            }
            p0l += __shfl_xor_sync(0xffffffffu, p0l, 1); p0l += __shfl_xor_sync(0xffffffffu, p0l, 2);
            p1l += __shfl_xor_sync(0xffffffffu, p1l, 1); p1l += __shfl_xor_sync(0xffffffffu, p1l, 2);
            p0h += __shfl_xor_sync(0xffffffffu, p0h, 1); p0h += __shfl_xor_sync(0xffffffffu, p0h, 2);
            p1h += __shfl_xor_sync(0xffffffffu, p1h, 1); p1h += __shfl_xor_sync(0xffffffffu, p1h, 2);
            if (qt == 0){
                int rlo = by*128 + wm*32 + mt*16 + quad;
                g_rv_part[(size_t)rlo*24 + slot*2 + 0] = p0l;
                g_rv_part[(size_t)rlo*24 + slot*2 + 1] = p1l;
                g_rv_part[(size_t)(rlo+8)*24 + slot*2 + 0] = p0h;
                g_rv_part[(size_t)(rlo+8)*24 + slot*2 + 1] = p1h;
            }
        }
    }
}

// ---------------- K7: per-instance softmax over K senses ----------------
__global__ void k_attn(const float* __restrict__ Wab){
    int n = blockIdx.x, lane = threadIdx.x;
    float lg = -INFINITY;
    if (lane < KSEN){
        int r = n*KSEN + lane;
        float s = Wab[0];
        #pragma unroll
        for (int p=0;p<12;p++) s += g_logit_part[(size_t)r*12+p];
        lg = s;
    }
    float m = lg;
    #pragma unroll
    for (int o=16;o;o>>=1) m = fmaxf(m, __shfl_xor_sync(0xffffffffu, m, o));
    float e = (lane < KSEN) ? expf(lg - m) : 0.f;
    float t = wsum(e);
    if (lane < KSEN) g_attn[n*KSEN + lane] = e/t;
}

// ---------------- K8: final logits ----------------
__global__ void k_final(const float* __restrict__ dec, const float* __restrict__ clsw,
                        const float* __restrict__ clsb, float* __restrict__ out){
    int r = blockIdx.x*8 + (threadIdx.x>>5);
    int lane = threadIdx.x & 31;
    const float* drow = dec + (size_t)r*H;
    float a0=0.f, a1=0.f;
    for (int t=lane;t<H;t+=32){ float d=drow[t]; a0 += d*clsw[2*t]; a1 += d*clsw[2*t+1]; }
    a0=wsum(a0); a1=wsum(a1);
    if (lane==0){
        int n = r >> 4;
        float o0 = a0 + clsb[0], o1 = a1 + clsb[1];
        if (n != g_sel){
            float rv0=g_c2[0], rv1=g_c2[1];
            #pragma unroll
            for (int p=0;p<12;p++){ rv0 += g_rv_part[(size_t)r*24 + p*2]; rv1 += g_rv_part[(size_t)r*24 + p*2 + 1]; }
            float at = g_attn[r];
            o0 += at*rv0; o1 += at*rv1;
        }
        out[2*r]   = o0;
        out[2*r+1] = o1;
    }
}

// ---------------- launcher ----------------
extern "C" void kernel_launch(void* const* d_in, const int* in_sizes, int n_in,
                              void* d_out, int out_size){
    (void)n_in; (void)out_size;
    const float *dec,*gls,*s1w,*s1b,*s2w,*s2b,*W1w,*W1b,*W2w,*W2b,*Waw,*Wab,*V1w,*V1b,*V2w,*V2b,*Uw,*Ub,*clsw,*clsb;
    const int* pred;
    if (in_sizes[2] == NI){
        dec=(const float*)d_in[0]; gls=(const float*)d_in[1]; pred=(const int*)d_in[2];
        s1w=(const float*)d_in[3];  s1b=(const float*)d_in[4];
        s2w=(const float*)d_in[5];  s2b=(const float*)d_in[6];
        W1w=(const float*)d_in[7];  W1b=(const float*)d_in[8];
        W2w=(const float*)d_in[9];  W2b=(const float*)d_in[10];
        Waw=(const float*)d_in[11]; Wab=(const float*)d_in[12];
        V1w=(const float*)d_in[13]; V1b=(const float*)d_in[14];
        V2w=(const float*)d_in[15]; V2b=(const float*)d_in[16];
        Uw =(const float*)d_in[17]; Ub =(const float*)d_in[18];
        clsw=(const float*)d_in[19]; clsb=(const float*)d_in[20];
    } else {
        dec=(const float*)d_in[0]; gls=(const float*)d_in[1];
        s1w=(const float*)d_in[2];  s1b=(const float*)d_in[3];
        s2w=(const float*)d_in[4];  s2b=(const float*)d_in[5];
        W1w=(const float*)d_in[6];  W1b=(const float*)d_in[7];
        W2w=(const float*)d_in[8];  W2b=(const float*)d_in[9];
        Waw=(const float*)d_in[10]; Wab=(const float*)d_in[11];
        V1w=(const float*)d_in[12]; V1b=(const float*)d_in[13];
        V2w=(const float*)d_in[14]; V2b=(const float*)d_in[15];
        Uw =(const float*)d_in[16]; Ub =(const float*)d_in[17];
        clsw=(const float*)d_in[18]; clsb=(const float*)d_in[19];
        pred=(const int*)d_in[20];
    }
    (void)s2b;
    float* out = (float*)d_out;

    cudaFuncSetAttribute(k_big_mma, cudaFuncAttributeMaxDynamicSharedMemorySize, KB_SMEM);

    k_pool    <<<NI, 256>>>(dec, gls, pred);
    k_gemm1   <<<dim3(6,64), 256>>>(s1w, s1b, s2w);
    k_softmax <<<1, 1024>>>(out + 2*RR);
    k_biasmcls<<<18, 128>>>(W1w, W1b, W2b, V1w, V1b, V2b, Uw, Ub, clsw);
    k_conv_b  <<<dim3(48,48), 256>>>(W2w, V2w);
    k_big_mma <<<dim3(12, 256), 256, KB_SMEM>>>(Waw);   // launch #6 -> profiled by ncu -s 5 -c 1
    k_attn    <<<NI, 32>>>(Wab);
    k_final   <<<RR/8, 256>>>(dec, clsw, clsb, out);
}

// round 8
// speedup vs baseline: 2.9331x; 1.0820x over previous
#include <cuda_runtime.h>
#include <cuda_fp16.h>
#include <math.h>
#include <stdint.h>

// Problem constants
#define NI 2048
#define KSEN 16
#define H 768
#define H2 1536
#define RR (NI*KSEN)   // 32768

// ---------------- device scratch (static; no allocations) ----------------
__device__ float g_feat[NI*H2];      // pooled concat features [N,2H]
__device__ float g_predcat[NI*H2];   // concat(pred_dec, pred_gls) [N,2H]
__device__ float g_score[NI];
__device__ int   g_sel;
__device__ int   g_flag;
__device__ float g_bias_attn[H];     // sel_mg@W1 + W1_b + W2_b
__device__ float g_bias_v[H];        // sel_mg@V1 + V1_b + V2_b
__device__ float g_M[H*2];           // U_w @ cls_w
__device__ float g_c2[2];            // U_b @ cls_w
__device__ float g_logit_part[(size_t)RR*12];
__device__ float g_rv_part[(size_t)RR*24];  // [r][12][2]
__device__ float g_attn[RR];

// fp16 operands for the big GEMM (A single-rounded, B split hi+lo)
__device__ __half g_Ah[(size_t)RR*H2];       // ~100.7 MB
__device__ __half g_Bh[(size_t)H2*H2];       // [n][k], n<768: W2 col n; n>=768: V2 col n-768
__device__ __half g_Bl[(size_t)H2*H2];

// ---------------- fp32 packed helpers ----------------
__device__ __forceinline__ unsigned long long pk2(float lo, float hi){
    unsigned long long r;
    asm("mov.b64 %0, {%1, %2};" : "=l"(r) : "f"(lo), "f"(hi));
    return r;
}
__device__ __forceinline__ void up2(unsigned long long v, float& lo, float& hi){
    asm("mov.b64 {%0, %1}, %2;" : "=f"(lo), "=f"(hi) : "l"(v));
}
__device__ __forceinline__ void ffma2(unsigned long long& d, unsigned long long a, unsigned long long b){
    asm("fma.rn.f32x2 %0, %1, %2, %0;" : "+l"(d) : "l"(a), "l"(b));
}
__device__ __forceinline__ float wsum(float v){
    #pragma unroll
    for (int o=16;o;o>>=1) v += __shfl_xor_sync(0xffffffffu, v, o);
    return v;
}

// ---------------- mma.sync helpers (baseline sm_100 legal) ----------------
__device__ __forceinline__ uint32_t smem_u32(const void* p){
    uint32_t a;
    asm("{ .reg .u64 t; cvta.to.shared.u64 t, %1; cvt.u32.u64 %0, t; }" : "=r"(a) : "l"(p));
    return a;
}
__device__ __forceinline__ void ldm4(uint32_t* r, uint32_t addr){
    asm volatile("ldmatrix.sync.aligned.m8n8.x4.shared.b16 {%0,%1,%2,%3}, [%4];"
        : "=r"(r[0]),"=r"(r[1]),"=r"(r[2]),"=r"(r[3]) : "r"(addr));
}
__device__ __forceinline__ void mma_f16(float* c, const uint32_t* a, uint32_t b0, uint32_t b1){
    asm volatile("mma.sync.aligned.m16n8k16.row.col.f32.f16.f16.f32 "
        "{%0,%1,%2,%3}, {%4,%5,%6,%7}, {%8,%9}, {%0,%1,%2,%3};"
        : "+f"(c[0]),"+f"(c[1]),"+f"(c[2]),"+f"(c[3])
        : "r"(a[0]),"r"(a[1]),"r"(a[2]),"r"(a[3]), "r"(b0),"r"(b1));
}
__device__ __forceinline__ void cpa16(uint32_t s, const void* g){
    asm volatile("cp.async.cg.shared.global [%0], [%1], 16;" :: "r"(s), "l"(g));
}
__device__ __forceinline__ void cpa_commit(){ asm volatile("cp.async.commit_group;" ::: "memory"); }
__device__ __forceinline__ void cpa_wait1(){ asm volatile("cp.async.wait_group 1;" ::: "memory"); }

// ---------------- L1: fused pool(+A conv) / B transpose+split ----------------
__global__ void k_pool_conv(const float* __restrict__ dec, const float* __restrict__ gls,
                            const int* __restrict__ pred,
                            const float* __restrict__ W2, const float* __restrict__ V2){
    int bid = blockIdx.x;
    if (bid == 0 && threadIdx.x == 0) g_flag = 0;
    if (bid < NI){
        int n = bid;
        int p = pred[n];
        if (threadIdx.x == 0) g_score[n] = 0.f;
        const float* db = dec + (size_t)n*KSEN*H;
        const float* gb = gls + (size_t)n*KSEN*H;
        for (int d = threadIdx.x; d < H; d += blockDim.x){
            float sd=0.f, sg=0.f;
            #pragma unroll
            for (int k=0;k<KSEN;k++){
                float vd = db[k*H+d];
                float vg = gb[k*H+d];
                sd += vd; sg += vg;
                size_t r = (size_t)(n*KSEN + k);
                g_Ah[r*H2 + d]     = __float2half_rn(vd);
                g_Ah[r*H2 + H + d] = __float2half_rn(vg);
            }
            float pd = db[p*H+d], pg = gb[p*H+d];
            g_feat[(size_t)n*H2 + d]      = pd - sd*(1.0f/16.0f);
            g_feat[(size_t)n*H2 + H + d]  = pg - sg*(1.0f/16.0f);
            g_predcat[(size_t)n*H2 + d]     = pd;
            g_predcat[(size_t)n*H2 + H + d] = pg;
        }
    } else {
        __shared__ float tile[32][33];
        int cbid = bid - NI;
        int nb = cbid / 48;   // 48 tiles over n
        int kb = cbid % 48;   // 48 tiles over k
        int tx = threadIdx.x & 31, ty = threadIdx.x >> 5;   // 32 x 8
        const float* src = (nb < 24) ? W2 : V2;
        int col0 = (nb % 24) * 32;
        #pragma unroll
        for (int j=0;j<4;j++){
            int kk = ty + j*8;
            tile[tx][kk] = src[(size_t)(kb*32 + kk)*H + col0 + tx];
        }
        __syncthreads();
        int n0 = nb*32;
        #pragma unroll
        for (int j=0;j<4;j++){
            int c = ty + j*8;
            float v = tile[c][tx];
            __half hi = __float2half_rn(v);
            __half lo = __float2half_rn(v - __half2float(hi));
            size_t di = (size_t)(n0 + c)*H2 + kb*32 + tx;
            g_Bh[di] = hi;
            g_Bl[di] = lo;
        }
    }
}

// ---------------- L2: h=relu(feat@s1_w+s1_b); fused score atomics (s2_b dropped: shift-inv) ----------------
__global__ void __launch_bounds__(256) k_gemm1(const float* __restrict__ B, const float* __restrict__ bias,
                                               const float* __restrict__ s2w){
    __shared__ float As[16][33];
    __shared__ float Bs[16][128];
    int tid=threadIdx.x, bx=blockIdx.x, by=blockIdx.y;
    int tx=tid&15, ty=tid>>4;
    int arow=tid>>3, akc=(tid&7)*2;
    int bkr=tid>>4, bc0=(tid&15)*8;
    const float* Ap = g_feat + (size_t)(by*32+arow)*H2 + akc;
    const float* Bp = B + (size_t)bkr*H + bx*128 + bc0;
    unsigned long long acc[2][4];
    #pragma unroll
    for(int i=0;i<2;i++){
        #pragma unroll
        for(int j=0;j<4;j++) acc[i][j]=0ull;
    }
    for (int kt=0; kt<H2/16; kt++){
        float2 a0 = *(const float2*)(Ap + kt*16);
        As[akc  ][arow]=a0.x;
        As[akc+1][arow]=a0.y;
        const float* bsrc = Bp + (size_t)kt*16*H;
        *(float4*)&Bs[bkr][bc0]   = *(const float4*)(bsrc);
        *(float4*)&Bs[bkr][bc0+4] = *(const float4*)(bsrc+4);
        __syncthreads();
        #pragma unroll
        for (int k=0;k<16;k++){
            float ra[2];
            ra[0]=As[k][ty*2]; ra[1]=As[k][ty*2+1];
            float4 bb0 = *(float4*)&Bs[k][tx*8];
            float4 bb1 = *(float4*)&Bs[k][tx*8+4];
            unsigned long long rb[4];
            rb[0]=pk2(bb0.x,bb0.y); rb[1]=pk2(bb0.z,bb0.w);
            rb[2]=pk2(bb1.x,bb1.y); rb[3]=pk2(bb1.z,bb1.w);
            #pragma unroll
            for (int i=0;i<2;i++){
                unsigned long long aa = pk2(ra[i],ra[i]);
                #pragma unroll
                for (int jp=0;jp<4;jp++) ffma2(acc[i][jp], aa, rb[jp]);
            }
        }
        __syncthreads();
    }
    int gc = bx*128 + tx*8;
    float bias8[8], sw8[8];
    #pragma unroll
    for (int j=0;j<8;j++){ bias8[j]=bias[gc+j]; sw8[j]=s2w[gc+j]; }
    #pragma unroll
    for (int i=0;i<2;i++){
        int row = by*32 + ty*2 + i;
        float v[8];
        #pragma unroll
        for (int jp=0;jp<4;jp++) up2(acc[i][jp], v[2*jp], v[2*jp+1]);
        float o[8], p = 0.f;
        #pragma unroll
        for (int j=0;j<8;j++){ float t=v[j]+bias8[j]; o[j]= t>0.f? t : 0.f; p += o[j]*sw8[j]; }
        p += __shfl_xor_sync(0xffffffffu, p, 1);
        p += __shfl_xor_sync(0xffffffffu, p, 2);
        p += __shfl_xor_sync(0xffffffffu, p, 4);
        p += __shfl_xor_sync(0xffffffffu, p, 8);
        if (tx == 0) atomicAdd(&g_score[row], p);
    }
}

// ---------------- L3: softmax (block 0) + sel-dependent biases + M (blocks 1..36) ----------------
// block 0 computes probs/sel then releases g_flag; other blocks spin (all 37 blocks co-resident).
__global__ void __launch_bounds__(1024) k_softmax_bias(
    float* __restrict__ probs,
    const float* __restrict__ W1, const float* __restrict__ W1b, const float* __restrict__ W2b,
    const float* __restrict__ V1, const float* __restrict__ V1b, const float* __restrict__ V2b,
    const float* __restrict__ Uw, const float* __restrict__ Ub,
    const float* __restrict__ clsw){
    int b = blockIdx.x, tid = threadIdx.x;
    if (b == 0){
        __shared__ float sv[1024];
        __shared__ int   si[1024];
        float a=g_score[tid], bb=g_score[tid+1024];
        float m; int mi;
        if (a>=bb){ m=a; mi=tid; } else { m=bb; mi=tid+1024; }
        sv[tid]=m; si[tid]=mi;
        __syncthreads();
        for (int s=512;s>0;s>>=1){
            if (tid<s){
                float ov=sv[tid+s]; int oi=si[tid+s];
                if (ov>sv[tid] || (ov==sv[tid] && oi<si[tid])){ sv[tid]=ov; si[tid]=oi; }
            }
            __syncthreads();
        }
        float mx = sv[0]; int sel = si[0];
        if (tid==0) g_sel = sel;
        __syncthreads();
        float e0 = expf(a-mx), e1 = expf(bb-mx);
        sv[tid] = e0+e1;
        __syncthreads();
        for (int s=512;s>0;s>>=1){ if (tid<s) sv[tid]+=sv[tid+s]; __syncthreads(); }
        float inv = 1.0f/sv[0];
        probs[tid]      = e0*inv;
        probs[tid+1024] = e1*inv;
        __threadfence();
        __syncthreads();
        if (tid==0) atomicExch(&g_flag, 1);
        return;
    }
    // spin until sel is published
    if (tid == 0){ while (atomicAdd(&g_flag, 0) == 0) __nanosleep(64); }
    __syncthreads();
    __threadfence();
    if (b <= 12){
        // bias groups: g in [0,12); 1024 threads = 128 j x 8 chunks of 192 i
        __shared__ float red[8][128];
        int g = b - 1;
        int half = (g >= 6);
        int jbase = (half ? g-6 : g) * 128;
        int jj = tid & 127, c = tid >> 7;
        int sel = g_sel;
        const float* m = half ? V1 : W1;
        const float* srow = g_predcat + (size_t)sel*H2;
        int j = jbase + jj;
        float s = 0.f;
        int i0 = c*192;
        #pragma unroll 4
        for (int i=i0; i<i0+192; i++) s += srow[i]*m[(size_t)i*H + j];
        red[c][jj] = s;
        __syncthreads();
        if (c == 0){
            float t = 0.f;
            #pragma unroll
            for (int cc=0; cc<8; cc++) t += red[cc][jj];
            if (half) g_bias_v[j]    = t + V1b[j] + V2b[j];
            else      g_bias_attn[j] = t + W1b[j] + W2b[j];
        }
    } else {
        // M rows: warp-per-j, 32 warps per block, blocks 13..36 -> j in [0,768)
        int w = tid >> 5, lane = tid & 31;
        int j = (b-13)*32 + w;
        const float* ur = Uw + (size_t)j*H;
        float m0=0.f, m1=0.f;
        for (int t=lane; t<H; t+=32){ float u=ur[t]; m0+=u*clsw[2*t]; m1+=u*clsw[2*t+1]; }
        m0 = wsum(m0); m1 = wsum(m1);
        if (lane==0){ g_M[2*j]=m0; g_M[2*j+1]=m1; }
        if (b==13 && w==1){
            float s0=0.f, s1=0.f;
            for (int t=lane; t<H; t+=32){ float u=Ub[t]; s0+=u*clsw[2*t]; s1+=u*clsw[2*t+1]; }
            s0 = wsum(s0); s1 = wsum(s1);
            if (lane==0){ g_c2[0]=s0; g_c2[1]=s1; }
        }
    }
}

// ---------------- L4: mma.sync fp16 2-product GEMM + reduce (single barrier / iter) ----------------
// grid (12, 256), CTA 128x128, 256 thr, warps 4(M)x2(N), warp tile 32x64.
// 3-stage cp.async pipeline, occupancy 2, one __syncthreads per iteration:
//   wait_group 1 (stage it done) -> barrier (visibility + all compute(it-1) done)
//   -> issue loads for stage it+2 (safe: overwrites (it-1)%3, finished before barrier)
//   -> compute stage it
#define KB_REGION 10240
#define KB_STAGE  30720
#define KB_SMEM   (3*KB_STAGE)
#define KB_ITERS  48

__device__ __forceinline__ void kb_load_stage(uint32_t sb, int stage, int by, int cb, int gk, int tid){
    uint32_t s0 = sb + stage*KB_STAGE;
    #pragma unroll
    for (int j=0;j<6;j++){
        int idx = j*256 + tid;        // 0..1535
        int region = idx >> 9;        // 0 A, 1 Bh, 2 Bl
        int cl = idx & 511;
        int r  = cl >> 2;
        int kc = cl & 3;
        const __half* g;
        size_t grow;
        if (region == 0){ g = g_Ah; grow = (size_t)(by*128 + r); }
        else if (region == 1){ g = g_Bh; grow = (size_t)(cb*128 + r); }
        else { g = g_Bl; grow = (size_t)(cb*128 + r); }
        cpa16(s0 + region*KB_REGION + r*80 + kc*16, g + grow*H2 + gk + kc*8);
    }
}

__global__ void __launch_bounds__(256,2) k_big_mma(const float* __restrict__ Wa){
    extern __shared__ char smem[];
    uint32_t sb = smem_u32(smem);
    int tid = threadIdx.x;
    int cb = blockIdx.x, by = blockIdx.y;
    int warp = tid >> 5, lane = tid & 31;
    int wm = warp & 3, wn = warp >> 2;      // wm 0..3 (M), wn 0..1 (N)

    float acc[2][8][4];
    #pragma unroll
    for (int mt=0;mt<2;mt++)
        #pragma unroll
        for (int nt=0;nt<8;nt++)
            #pragma unroll
            for (int d=0;d<4;d++) acc[mt][nt][d] = 0.f;

    kb_load_stage(sb, 0, by, cb, 0,  tid); cpa_commit();
    kb_load_stage(sb, 1, by, cb, 32, tid); cpa_commit();

    int m8 = lane >> 3, r8 = lane & 7;

    for (int it = 0; it < KB_ITERS; it++){
        cpa_wait1();               // own copies of stage it complete
        __syncthreads();           // cross-thread visibility; all compute(it-1) done
        if (it + 2 < KB_ITERS) kb_load_stage(sb, (it+2)%3, by, cb, (it+2)*32, tid);
        cpa_commit();              // empty group at tail keeps wait count aligned

        uint32_t st = sb + (it%3)*KB_STAGE;
        #pragma unroll
        for (int kh=0; kh<2; kh++){
            int k0 = kh*16;
            uint32_t ah[2][4], bb[4][4];
            #pragma unroll
            for (int mt=0;mt<2;mt++){
                int rowA = wm*32 + mt*16 + (m8&1)*8 + r8;
                int kA   = k0 + (m8>>1)*8;
                ldm4(ah[mt], st + 0*KB_REGION + rowA*80 + kA*2);
            }
            int rowB = wn*64 + (m8>>1)*8 + r8;
            int kB   = k0 + (m8&1)*8;
            uint32_t boff = rowB*80 + kB*2;
            // product 1: A * Bh
            #pragma unroll
            for (int ntp=0;ntp<4;ntp++) ldm4(bb[ntp], st + 1*KB_REGION + boff + ntp*16*80);
            #pragma unroll
            for (int mt=0;mt<2;mt++)
                #pragma unroll
                for (int nt=0;nt<8;nt++)
                    mma_f16(acc[mt][nt], ah[mt], bb[nt>>1][(nt&1)*2], bb[nt>>1][(nt&1)*2+1]);
            // product 2: A * Bl (reuse fragment registers)
            #pragma unroll
            for (int ntp=0;ntp<4;ntp++) ldm4(bb[ntp], st + 2*KB_REGION + boff + ntp*16*80);
            #pragma unroll
            for (int mt=0;mt<2;mt++)
                #pragma unroll
                for (int nt=0;nt<8;nt++)
                    mma_f16(acc[mt][nt], ah[mt], bb[nt>>1][(nt&1)*2], bb[nt>>1][(nt&1)*2+1]);
        }
    }

    // ---------------- epilogue: reduce over the 128 columns this CTA owns ----------------
    int quad = lane >> 2, qt = lane & 3;
    if (cb < 6){
        int colb = cb*128;
        #pragma unroll
        for (int mt=0;mt<2;mt++){
            float plo = 0.f, phi = 0.f;
            #pragma unroll
            for (int nt=0;nt<8;nt++){
                int g0 = colb + wn*64 + nt*8 + qt*2;
                float ba0 = g_bias_attn[g0],  ba1 = g_bias_attn[g0+1];
                float w0  = Wa[g0],           w1  = Wa[g0+1];
                plo += tanhf(acc[mt][nt][0]+ba0)*w0 + tanhf(acc[mt][nt][1]+ba1)*w1;
                phi += tanhf(acc[mt][nt][2]+ba0)*w0 + tanhf(acc[mt][nt][3]+ba1)*w1;
            }
            plo += __shfl_xor_sync(0xffffffffu, plo, 1);
            plo += __shfl_xor_sync(0xffffffffu, plo, 2);
            phi += __shfl_xor_sync(0xffffffffu, phi, 1);
            phi += __shfl_xor_sync(0xffffffffu, phi, 2);
            if (qt == 0){
                int rlo = by*128 + wm*32 + mt*16 + quad;
                g_logit_part[(size_t)rlo*12 + cb*2 + wn]     = plo;
                g_logit_part[(size_t)(rlo+8)*12 + cb*2 + wn] = phi;
            }
        }
    } else {
        int cbv = cb - 6, colb = cbv*128, slot = cbv*2 + wn;
        #pragma unroll
        for (int mt=0;mt<2;mt++){
            float p0l=0.f, p1l=0.f, p0h=0.f, p1h=0.f;
            #pragma unroll
            for (int nt=0;nt<8;nt++){
                int g0 = colb + wn*64 + nt*8 + qt*2;
                float bv0 = g_bias_v[g0], bv1 = g_bias_v[g0+1];
                float m00 = g_M[2*g0],   m01 = g_M[2*g0+1];
                float m10 = g_M[2*g0+2], m11 = g_M[2*g0+3];
                float x;
                x = acc[mt][nt][0]+bv0; x = x>0.f? x:0.f; p0l += x*m00; p1l += x*m01;
                x = acc[mt][nt][1]+bv1; x = x>0.f? x:0.f; p0l += x*m10; p1l += x*m11;
                x = acc[mt][nt][2]+bv0; x = x>0.f? x:0.f; p0h += x*m00; p1h += x*m01;
                x = acc[mt][nt][3]+bv1; x = x>0.f? x:0.f; p0h += x*m10; p1h += x*m11;
            }
            p0l += __shfl_xor_sync(0xffffffffu, p0l, 1); p0l += __shfl_xor_sync(0xffffffffu, p0l, 2);
            p1l += __shfl_xor_sync(0xffffffffu, p1l, 1); p1l += __shfl_xor_sync(0xffffffffu, p1l, 2);
            p0h += __shfl_xor_sync(0xffffffffu, p0h, 1); p0h += __shfl_xor_sync(0xffffffffu, p0h, 2);
            p1h += __shfl_xor_sync(0xffffffffu, p1h, 1); p1h += __shfl_xor_sync(0xffffffffu, p1h, 2);
            if (qt == 0){
                int rlo = by*128 + wm*32 + mt*16 + quad;
                g_rv_part[(size_t)rlo*24 + slot*2 + 0] = p0l;
                g_rv_part[(size_t)rlo*24 + slot*2 + 1] = p1l;
                g_rv_part[(size_t)(rlo+8)*24 + slot*2 + 0] = p0h;
                g_rv_part[(size_t)(rlo+8)*24 + slot*2 + 1] = p1h;
            }
        }
    }
}

// ---------------- L5: per-instance softmax over K senses ----------------
__global__ void k_attn(const float* __restrict__ Wab){
    int n = blockIdx.x, lane = threadIdx.x;
    float lg = -INFINITY;
    if (lane < KSEN){
        int r = n*KSEN + lane;
        float s = Wab[0];
        #pragma unroll
        for (int p=0;p<12;p++) s += g_logit_part[(size_t)r*12+p];
        lg = s;
    }
    float m = lg;
    #pragma unroll
    for (int o=16;o;o>>=1) m = fmaxf(m, __shfl_xor_sync(0xffffffffu, m, o));
    float e = (lane < KSEN) ? expf(lg - m) : 0.f;
    float t = wsum(e);
    if (lane < KSEN) g_attn[n*KSEN + lane] = e/t;
}

// ---------------- L6: final logits ----------------
__global__ void k_final(const float* __restrict__ dec, const float* __restrict__ clsw,
                        const float* __restrict__ clsb, float* __restrict__ out){
    int r = blockIdx.x*8 + (threadIdx.x>>5);
    int lane = threadIdx.x & 31;
    const float* drow = dec + (size_t)r*H;
    float a0=0.f, a1=0.f;
    for (int t=lane;t<H;t+=32){ float d=drow[t]; a0 += d*clsw[2*t]; a1 += d*clsw[2*t+1]; }
    a0=wsum(a0); a1=wsum(a1);
    if (lane==0){
        int n = r >> 4;
        float o0 = a0 + clsb[0], o1 = a1 + clsb[1];
        if (n != g_sel){
            float rv0=g_c2[0], rv1=g_c2[1];
            #pragma unroll
            for (int p=0;p<12;p++){ rv0 += g_rv_part[(size_t)r*24 + p*2]; rv1 += g_rv_part[(size_t)r*24 + p*2 + 1]; }
            float at = g_attn[r];
            o0 += at*rv0; o1 += at*rv1;
        }
        out[2*r]   = o0;
        out[2*r+1] = o1;
    }
}

// ---------------- launcher ----------------
extern "C" void kernel_launch(void* const* d_in, const int* in_sizes, int n_in,
                              void* d_out, int out_size){
    (void)n_in; (void)out_size;
    const float *dec,*gls,*s1w,*s1b,*s2w,*s2b,*W1w,*W1b,*W2w,*W2b,*Waw,*Wab,*V1w,*V1b,*V2w,*V2b,*Uw,*Ub,*clsw,*clsb;
    const int* pred;
    if (in_sizes[2] == NI){
        dec=(const float*)d_in[0]; gls=(const float*)d_in[1]; pred=(const int*)d_in[2];
        s1w=(const float*)d_in[3];  s1b=(const float*)d_in[4];
        s2w=(const float*)d_in[5];  s2b=(const float*)d_in[6];
        W1w=(const float*)d_in[7];  W1b=(const float*)d_in[8];
        W2w=(const float*)d_in[9];  W2b=(const float*)d_in[10];
        Waw=(const float*)d_in[11]; Wab=(const float*)d_in[12];
        V1w=(const float*)d_in[13]; V1b=(const float*)d_in[14];
        V2w=(const float*)d_in[15]; V2b=(const float*)d_in[16];
        Uw =(const float*)d_in[17]; Ub =(const float*)d_in[18];
        clsw=(const float*)d_in[19]; clsb=(const float*)d_in[20];
    } else {
        dec=(const float*)d_in[0]; gls=(const float*)d_in[1];
        s1w=(const float*)d_in[2];  s1b=(const float*)d_in[3];
        s2w=(const float*)d_in[4];  s2b=(const float*)d_in[5];
        W1w=(const float*)d_in[6];  W1b=(const float*)d_in[7];
        W2w=(const float*)d_in[8];  W2b=(const float*)d_in[9];
        Waw=(const float*)d_in[10]; Wab=(const float*)d_in[11];
        V1w=(const float*)d_in[12]; V1b=(const float*)d_in[13];
        V2w=(const float*)d_in[14]; V2b=(const float*)d_in[15];
        Uw =(const float*)d_in[16]; Ub =(const float*)d_in[17];
        clsw=(const float*)d_in[18]; clsb=(const float*)d_in[19];
        pred=(const int*)d_in[20];
    }
    (void)s2b;
    float* out = (float*)d_out;

    cudaFuncSetAttribute(k_big_mma, cudaFuncAttributeMaxDynamicSharedMemorySize, KB_SMEM);

    k_pool_conv   <<<NI + 48*48, 256>>>(dec, gls, pred, W2w, V2w);
    k_gemm1       <<<dim3(6,64), 256>>>(s1w, s1b, s2w);
    k_softmax_bias<<<37, 1024>>>(out + 2*RR, W1w, W1b, W2b, V1w, V1b, V2b, Uw, Ub, clsw);
    k_big_mma     <<<dim3(12, 256), 256, KB_SMEM>>>(Waw);   // launch #4 -> profiled
    k_attn        <<<NI, 32>>>(Wab);
    k_final       <<<RR/8, 256>>>(dec, clsw, clsb, out);
}

// round 9
// speedup vs baseline: 3.9435x; 1.3445x over previous
#include <cuda_runtime.h>
#include <cuda_fp16.h>
#include <math.h>
#include <stdint.h>

// Problem constants
#define NI 2048
#define KSEN 16
#define H 768
#define H2 1536
#define RR (NI*KSEN)   // 32768

// ---------------- device scratch (static; no allocations) ----------------
__device__ float g_feat[NI*H2];      // pooled concat features [N,2H]
__device__ float g_predcat[NI*H2];   // concat(pred_dec, pred_gls) [N,2H]
__device__ float g_score[NI];
__device__ int   g_sel;
__device__ int   g_flag;
__device__ float g_bias_attn[H];     // sel_mg@W1 + W1_b + W2_b
__device__ float g_bias_v[H];        // sel_mg@V1 + V1_b + V2_b
__device__ float g_M[H*2];           // U_w @ cls_w
__device__ float g_c2[2];            // U_b @ cls_w
__device__ float g_logit_part[(size_t)RR*12];
__device__ float g_rv_part[(size_t)RR*24];  // [r][12][2]
__device__ float g_attn[RR];

// fp16 operands for the big GEMM (both single-rounded)
__device__ __half g_Ah[(size_t)RR*H2];       // ~100.7 MB
__device__ __half g_Bh[(size_t)H2*H2];       // [n][k], n<768: W2 col n; n>=768: V2 col n-768

// ---------------- fp32 packed helpers ----------------
__device__ __forceinline__ unsigned long long pk2(float lo, float hi){
    unsigned long long r;
    asm("mov.b64 %0, {%1, %2};" : "=l"(r) : "f"(lo), "f"(hi));
    return r;
}
__device__ __forceinline__ void up2(unsigned long long v, float& lo, float& hi){
    asm("mov.b64 {%0, %1}, %2;" : "=f"(lo), "=f"(hi) : "l"(v));
}
__device__ __forceinline__ void ffma2(unsigned long long& d, unsigned long long a, unsigned long long b){
    asm("fma.rn.f32x2 %0, %1, %2, %0;" : "+l"(d) : "l"(a), "l"(b));
}
__device__ __forceinline__ float wsum(float v){
    #pragma unroll
    for (int o=16;o;o>>=1) v += __shfl_xor_sync(0xffffffffu, v, o);
    return v;
}

// ---------------- mma.sync helpers (baseline sm_100 legal) ----------------
__device__ __forceinline__ uint32_t smem_u32(const void* p){
    uint32_t a;
    asm("{ .reg .u64 t; cvta.to.shared.u64 t, %1; cvt.u32.u64 %0, t; }" : "=r"(a) : "l"(p));
    return a;
}
__device__ __forceinline__ void ldm4(uint32_t* r, uint32_t addr){
    asm volatile("ldmatrix.sync.aligned.m8n8.x4.shared.b16 {%0,%1,%2,%3}, [%4];"
        : "=r"(r[0]),"=r"(r[1]),"=r"(r[2]),"=r"(r[3]) : "r"(addr));
}
__device__ __forceinline__ void mma_f16(float* c, const uint32_t* a, uint32_t b0, uint32_t b1){
    asm volatile("mma.sync.aligned.m16n8k16.row.col.f32.f16.f16.f32 "
        "{%0,%1,%2,%3}, {%4,%5,%6,%7}, {%8,%9}, {%0,%1,%2,%3};"
        : "+f"(c[0]),"+f"(c[1]),"+f"(c[2]),"+f"(c[3])
        : "r"(a[0]),"r"(a[1]),"r"(a[2]),"r"(a[3]), "r"(b0),"r"(b1));
}
__device__ __forceinline__ void cpa16(uint32_t s, const void* g){
    asm volatile("cp.async.cg.shared.global [%0], [%1], 16;" :: "r"(s), "l"(g));
}
__device__ __forceinline__ void cpa_commit(){ asm volatile("cp.async.commit_group;" ::: "memory"); }
__device__ __forceinline__ void cpa_wait1(){ asm volatile("cp.async.wait_group 1;" ::: "memory"); }

// ---------------- L1: fused pool(+A conv) / B transpose+convert ----------------
__global__ void k_pool_conv(const float* __restrict__ dec, const float* __restrict__ gls,
                            const int* __restrict__ pred,
                            const float* __restrict__ W2, const float* __restrict__ V2){
    int bid = blockIdx.x;
    if (bid == 0 && threadIdx.x == 0) g_flag = 0;
    if (bid < NI){
        int n = bid;
        int p = pred[n];
        if (threadIdx.x == 0) g_score[n] = 0.f;
        const float* db = dec + (size_t)n*KSEN*H;
        const float* gb = gls + (size_t)n*KSEN*H;
        for (int d = threadIdx.x; d < H; d += blockDim.x){
            float sd=0.f, sg=0.f;
            #pragma unroll
            for (int k=0;k<KSEN;k++){
                float vd = db[k*H+d];
                float vg = gb[k*H+d];
                sd += vd; sg += vg;
                size_t r = (size_t)(n*KSEN + k);
                g_Ah[r*H2 + d]     = __float2half_rn(vd);
                g_Ah[r*H2 + H + d] = __float2half_rn(vg);
            }
            float pd = db[p*H+d], pg = gb[p*H+d];
            g_feat[(size_t)n*H2 + d]      = pd - sd*(1.0f/16.0f);
            g_feat[(size_t)n*H2 + H + d]  = pg - sg*(1.0f/16.0f);
            g_predcat[(size_t)n*H2 + d]     = pd;
            g_predcat[(size_t)n*H2 + H + d] = pg;
        }
    } else {
        __shared__ float tile[32][33];
        int cbid = bid - NI;
        int nb = cbid / 48;   // 48 tiles over n
        int kb = cbid % 48;   // 48 tiles over k
        int tx = threadIdx.x & 31, ty = threadIdx.x >> 5;   // 32 x 8
        const float* src = (nb < 24) ? W2 : V2;
        int col0 = (nb % 24) * 32;
        #pragma unroll
        for (int j=0;j<4;j++){
            int kk = ty + j*8;
            tile[tx][kk] = src[(size_t)(kb*32 + kk)*H + col0 + tx];
        }
        __syncthreads();
        int n0 = nb*32;
        #pragma unroll
        for (int j=0;j<4;j++){
            int c = ty + j*8;
            size_t di = (size_t)(n0 + c)*H2 + kb*32 + tx;
            g_Bh[di] = __float2half_rn(tile[c][tx]);
        }
    }
}

// ---------------- L2: h=relu(feat@s1_w+s1_b); fused score atomics (s2_b dropped: shift-inv) ----------------
__global__ void __launch_bounds__(256) k_gemm1(const float* __restrict__ B, const float* __restrict__ bias,
                                               const float* __restrict__ s2w){
    __shared__ float As[16][33];
    __shared__ float Bs[16][128];
    int tid=threadIdx.x, bx=blockIdx.x, by=blockIdx.y;
    int tx=tid&15, ty=tid>>4;
    int arow=tid>>3, akc=(tid&7)*2;
    int bkr=tid>>4, bc0=(tid&15)*8;
    const float* Ap = g_feat + (size_t)(by*32+arow)*H2 + akc;
    const float* Bp = B + (size_t)bkr*H + bx*128 + bc0;
    unsigned long long acc[2][4];
    #pragma unroll
    for(int i=0;i<2;i++){
        #pragma unroll
        for(int j=0;j<4;j++) acc[i][j]=0ull;
    }
    for (int kt=0; kt<H2/16; kt++){
        float2 a0 = *(const float2*)(Ap + kt*16);
        As[akc  ][arow]=a0.x;
        As[akc+1][arow]=a0.y;
        const float* bsrc = Bp + (size_t)kt*16*H;
        *(float4*)&Bs[bkr][bc0]   = *(const float4*)(bsrc);
        *(float4*)&Bs[bkr][bc0+4] = *(const float4*)(bsrc+4);
        __syncthreads();
        #pragma unroll
        for (int k=0;k<16;k++){
            float ra[2];
            ra[0]=As[k][ty*2]; ra[1]=As[k][ty*2+1];
            float4 bb0 = *(float4*)&Bs[k][tx*8];
            float4 bb1 = *(float4*)&Bs[k][tx*8+4];
            unsigned long long rb[4];
            rb[0]=pk2(bb0.x,bb0.y); rb[1]=pk2(bb0.z,bb0.w);
            rb[2]=pk2(bb1.x,bb1.y); rb[3]=pk2(bb1.z,bb1.w);
            #pragma unroll
            for (int i=0;i<2;i++){
                unsigned long long aa = pk2(ra[i],ra[i]);
                #pragma unroll
                for (int jp=0;jp<4;jp++) ffma2(acc[i][jp], aa, rb[jp]);
            }
        }
        __syncthreads();
    }
    int gc = bx*128 + tx*8;
    float bias8[8], sw8[8];
    #pragma unroll
    for (int j=0;j<8;j++){ bias8[j]=bias[gc+j]; sw8[j]=s2w[gc+j]; }
    #pragma unroll
    for (int i=0;i<2;i++){
        int row = by*32 + ty*2 + i;
        float v[8];
        #pragma unroll
        for (int jp=0;jp<4;jp++) up2(acc[i][jp], v[2*jp], v[2*jp+1]);
        float o[8], p = 0.f;
        #pragma unroll
        for (int j=0;j<8;j++){ float t=v[j]+bias8[j]; o[j]= t>0.f? t : 0.f; p += o[j]*sw8[j]; }
        p += __shfl_xor_sync(0xffffffffu, p, 1);
        p += __shfl_xor_sync(0xffffffffu, p, 2);
        p += __shfl_xor_sync(0xffffffffu, p, 4);
        p += __shfl_xor_sync(0xffffffffu, p, 8);
        if (tx == 0) atomicAdd(&g_score[row], p);
    }
}

// ---------------- L3: softmax (block 0) + sel-dependent biases + M (blocks 1..36) ----------------
__global__ void __launch_bounds__(1024) k_softmax_bias(
    float* __restrict__ probs,
    const float* __restrict__ W1, const float* __restrict__ W1b, const float* __restrict__ W2b,
    const float* __restrict__ V1, const float* __restrict__ V1b, const float* __restrict__ V2b,
    const float* __restrict__ Uw, const float* __restrict__ Ub,
    const float* __restrict__ clsw){
    int b = blockIdx.x, tid = threadIdx.x;
    if (b == 0){
        __shared__ float sv[1024];
        __shared__ int   si[1024];
        float a=g_score[tid], bb=g_score[tid+1024];
        float m; int mi;
        if (a>=bb){ m=a; mi=tid; } else { m=bb; mi=tid+1024; }
        sv[tid]=m; si[tid]=mi;
        __syncthreads();
        for (int s=512;s>0;s>>=1){
            if (tid<s){
                float ov=sv[tid+s]; int oi=si[tid+s];
                if (ov>sv[tid] || (ov==sv[tid] && oi<si[tid])){ sv[tid]=ov; si[tid]=oi; }
            }
            __syncthreads();
        }
        float mx = sv[0]; int sel = si[0];
        if (tid==0) g_sel = sel;
        __syncthreads();
        float e0 = expf(a-mx), e1 = expf(bb-mx);
        sv[tid] = e0+e1;
        __syncthreads();
        for (int s=512;s>0;s>>=1){ if (tid<s) sv[tid]+=sv[tid+s]; __syncthreads(); }
        float inv = 1.0f/sv[0];
        probs[tid]      = e0*inv;
        probs[tid+1024] = e1*inv;
        __threadfence();
        __syncthreads();
        if (tid==0) atomicExch(&g_flag, 1);
        return;
    }
    if (tid == 0){ while (atomicAdd(&g_flag, 0) == 0) __nanosleep(64); }
    __syncthreads();
    __threadfence();
    if (b <= 12){
        __shared__ float red[8][128];
        int g = b - 1;
        int half = (g >= 6);
        int jbase = (half ? g-6 : g) * 128;
        int jj = tid & 127, c = tid >> 7;
        int sel = g_sel;
        const float* m = half ? V1 : W1;
        const float* srow = g_predcat + (size_t)sel*H2;
        int j = jbase + jj;
        float s = 0.f;
        int i0 = c*192;
        #pragma unroll 4
        for (int i=i0; i<i0+192; i++) s += srow[i]*m[(size_t)i*H + j];
        red[c][jj] = s;
        __syncthreads();
        if (c == 0){
            float t = 0.f;
            #pragma unroll
            for (int cc=0; cc<8; cc++) t += red[cc][jj];
            if (half) g_bias_v[j]    = t + V1b[j] + V2b[j];
            else      g_bias_attn[j] = t + W1b[j] + W2b[j];
        }
    } else {
        int w = tid >> 5, lane = tid & 31;
        int j = (b-13)*32 + w;
        const float* ur = Uw + (size_t)j*H;
        float m0=0.f, m1=0.f;
        for (int t=lane; t<H; t+=32){ float u=ur[t]; m0+=u*clsw[2*t]; m1+=u*clsw[2*t+1]; }
        m0 = wsum(m0); m1 = wsum(m1);
        if (lane==0){ g_M[2*j]=m0; g_M[2*j+1]=m1; }
        if (b==13 && w==1){
            float s0=0.f, s1=0.f;
            for (int t=lane; t<H; t+=32){ float u=Ub[t]; s0+=u*clsw[2*t]; s1+=u*clsw[2*t+1]; }
            s0 = wsum(s0); s1 = wsum(s1);
            if (lane==0){ g_c2[0]=s0; g_c2[1]=s1; }
        }
    }
}

// ---------------- L4: mma.sync fp16 single-product GEMM + reduce ----------------
// grid (12, 256), CTA 128x128, 256 thr, warps 4(M)x2(N), warp tile 32x64.
// 3-stage cp.async pipeline (A | Bh per stage), occupancy 2, one barrier/iter.
#define KB_REGION 10240
#define KB_STAGE  20480
#define KB_SMEM   (3*KB_STAGE)
#define KB_ITERS  48

__device__ __forceinline__ void kb_load_stage(uint32_t sb, int stage, int by, int cb, int gk, int tid){
    uint32_t s0 = sb + stage*KB_STAGE;
    #pragma unroll
    for (int j=0;j<4;j++){
        int idx = j*256 + tid;        // 0..1023
        int region = idx >> 9;        // 0 A, 1 Bh
        int cl = idx & 511;
        int r  = cl >> 2;
        int kc = cl & 3;
        const __half* g = region ? g_Bh : g_Ah;
        size_t grow = region ? (size_t)(cb*128 + r) : (size_t)(by*128 + r);
        cpa16(s0 + region*KB_REGION + r*80 + kc*16, g + grow*H2 + gk + kc*8);
    }
}

__global__ void __launch_bounds__(256,2) k_big_mma(const float* __restrict__ Wa){
    extern __shared__ char smem[];
    uint32_t sb = smem_u32(smem);
    int tid = threadIdx.x;
    int cb = blockIdx.x, by = blockIdx.y;
    int warp = tid >> 5, lane = tid & 31;
    int wm = warp & 3, wn = warp >> 2;      // wm 0..3 (M), wn 0..1 (N)

    float acc[2][8][4];
    #pragma unroll
    for (int mt=0;mt<2;mt++)
        #pragma unroll
        for (int nt=0;nt<8;nt++)
            #pragma unroll
            for (int d=0;d<4;d++) acc[mt][nt][d] = 0.f;

    kb_load_stage(sb, 0, by, cb, 0,  tid); cpa_commit();
    kb_load_stage(sb, 1, by, cb, 32, tid); cpa_commit();

    int m8 = lane >> 3, r8 = lane & 7;

    for (int it = 0; it < KB_ITERS; it++){
        cpa_wait1();               // own copies of stage it complete
        __syncthreads();           // visibility; all compute(it-1) done
        if (it + 2 < KB_ITERS) kb_load_stage(sb, (it+2)%3, by, cb, (it+2)*32, tid);
        cpa_commit();              // empty group at tail keeps wait count aligned

        uint32_t st = sb + (it%3)*KB_STAGE;
        #pragma unroll
        for (int kh=0; kh<2; kh++){
            int k0 = kh*16;
            uint32_t ah[2][4], bb[4][4];
            #pragma unroll
            for (int mt=0;mt<2;mt++){
                int rowA = wm*32 + mt*16 + (m8&1)*8 + r8;
                int kA   = k0 + (m8>>1)*8;
                ldm4(ah[mt], st + 0*KB_REGION + rowA*80 + kA*2);
            }
            int rowB = wn*64 + (m8>>1)*8 + r8;
            int kB   = k0 + (m8&1)*8;
            uint32_t boff = rowB*80 + kB*2;
            #pragma unroll
            for (int ntp=0;ntp<4;ntp++) ldm4(bb[ntp], st + 1*KB_REGION + boff + ntp*16*80);
            #pragma unroll
            for (int mt=0;mt<2;mt++)
                #pragma unroll
                for (int nt=0;nt<8;nt++)
                    mma_f16(acc[mt][nt], ah[mt], bb[nt>>1][(nt&1)*2], bb[nt>>1][(nt&1)*2+1]);
        }
    }

    // ---------------- epilogue: reduce over the 128 columns this CTA owns ----------------
    int quad = lane >> 2, qt = lane & 3;
    if (cb < 6){
        int colb = cb*128;
        #pragma unroll
        for (int mt=0;mt<2;mt++){
            float plo = 0.f, phi = 0.f;
            #pragma unroll
            for (int nt=0;nt<8;nt++){
                int g0 = colb + wn*64 + nt*8 + qt*2;
                float ba0 = g_bias_attn[g0],  ba1 = g_bias_attn[g0+1];
                float w0  = Wa[g0],           w1  = Wa[g0+1];
                plo += tanhf(acc[mt][nt][0]+ba0)*w0 + tanhf(acc[mt][nt][1]+ba1)*w1;
                phi += tanhf(acc[mt][nt][2]+ba0)*w0 + tanhf(acc[mt][nt][3]+ba1)*w1;
            }
            plo += __shfl_xor_sync(0xffffffffu, plo, 1);
            plo += __shfl_xor_sync(0xffffffffu, plo, 2);
            phi += __shfl_xor_sync(0xffffffffu, phi, 1);
            phi += __shfl_xor_sync(0xffffffffu, phi, 2);
            if (qt == 0){
                int rlo = by*128 + wm*32 + mt*16 + quad;
                g_logit_part[(size_t)rlo*12 + cb*2 + wn]     = plo;
                g_logit_part[(size_t)(rlo+8)*12 + cb*2 + wn] = phi;
            }
        }
    } else {
        int cbv = cb - 6, colb = cbv*128, slot = cbv*2 + wn;
        #pragma unroll
        for (int mt=0;mt<2;mt++){
            float p0l=0.f, p1l=0.f, p0h=0.f, p1h=0.f;
            #pragma unroll
            for (int nt=0;nt<8;nt++){
                int g0 = colb + wn*64 + nt*8 + qt*2;
                float bv0 = g_bias_v[g0], bv1 = g_bias_v[g0+1];
                float m00 = g_M[2*g0],   m01 = g_M[2*g0+1];
                float m10 = g_M[2*g0+2], m11 = g_M[2*g0+3];
                float x;
                x = acc[mt][nt][0]+bv0; x = x>0.f? x:0.f; p0l += x*m00; p1l += x*m01;
                x = acc[mt][nt][1]+bv1; x = x>0.f? x:0.f; p0l += x*m10; p1l += x*m11;
                x = acc[mt][nt][2]+bv0; x = x>0.f? x:0.f; p0h += x*m00; p1h += x*m01;
                x = acc[mt][nt][3]+bv1; x = x>0.f? x:0.f; p0h += x*m10; p1h += x*m11;
            }
            p0l += __shfl_xor_sync(0xffffffffu, p0l, 1); p0l += __shfl_xor_sync(0xffffffffu, p0l, 2);
            p1l += __shfl_xor_sync(0xffffffffu, p1l, 1); p1l += __shfl_xor_sync(0xffffffffu, p1l, 2);
            p0h += __shfl_xor_sync(0xffffffffu, p0h, 1); p0h += __shfl_xor_sync(0xffffffffu, p0h, 2);
            p1h += __shfl_xor_sync(0xffffffffu, p1h, 1); p1h += __shfl_xor_sync(0xffffffffu, p1h, 2);
            if (qt == 0){
                int rlo = by*128 + wm*32 + mt*16 + quad;
                g_rv_part[(size_t)rlo*24 + slot*2 + 0] = p0l;
                g_rv_part[(size_t)rlo*24 + slot*2 + 1] = p1l;
                g_rv_part[(size_t)(rlo+8)*24 + slot*2 + 0] = p0h;
                g_rv_part[(size_t)(rlo+8)*24 + slot*2 + 1] = p1h;
            }
        }
    }
}

// ---------------- L5: per-instance softmax over K senses ----------------
__global__ void k_attn(const float* __restrict__ Wab){
    int n = blockIdx.x, lane = threadIdx.x;
    float lg = -INFINITY;
    if (lane < KSEN){
        int r = n*KSEN + lane;
        float s = Wab[0];
        #pragma unroll
        for (int p=0;p<12;p++) s += g_logit_part[(size_t)r*12+p];
        lg = s;
    }
    float m = lg;
    #pragma unroll
    for (int o=16;o;o>>=1) m = fmaxf(m, __shfl_xor_sync(0xffffffffu, m, o));
    float e = (lane < KSEN) ? expf(lg - m) : 0.f;
    float t = wsum(e);
    if (lane < KSEN) g_attn[n*KSEN + lane] = e/t;
}

// ---------------- L6: final logits ----------------
__global__ void k_final(const float* __restrict__ dec, const float* __restrict__ clsw,
                        const float* __restrict__ clsb, float* __restrict__ out){
    int r = blockIdx.x*8 + (threadIdx.x>>5);
    int lane = threadIdx.x & 31;
    const float* drow = dec + (size_t)r*H;
    float a0=0.f, a1=0.f;
    for (int t=lane;t<H;t+=32){ float d=drow[t]; a0 += d*clsw[2*t]; a1 += d*clsw[2*t+1]; }
    a0=wsum(a0); a1=wsum(a1);
    if (lane==0){
        int n = r >> 4;
        float o0 = a0 + clsb[0], o1 = a1 + clsb[1];
        if (n != g_sel){
            float rv0=g_c2[0], rv1=g_c2[1];
            #pragma unroll
            for (int p=0;p<12;p++){ rv0 += g_rv_part[(size_t)r*24 + p*2]; rv1 += g_rv_part[(size_t)r*24 + p*2 + 1]; }
            float at = g_attn[r];
            o0 += at*rv0; o1 += at*rv1;
        }
        out[2*r]   = o0;
        out[2*r+1] = o1;
    }
}

// ---------------- launcher ----------------
extern "C" void kernel_launch(void* const* d_in, const int* in_sizes, int n_in,
                              void* d_out, int out_size){
    (void)n_in; (void)out_size;
    const float *dec,*gls,*s1w,*s1b,*s2w,*s2b,*W1w,*W1b,*W2w,*W2b,*Waw,*Wab,*V1w,*V1b,*V2w,*V2b,*Uw,*Ub,*clsw,*clsb;
    const int* pred;
    if (in_sizes[2] == NI){
        dec=(const float*)d_in[0]; gls=(const float*)d_in[1]; pred=(const int*)d_in[2];
        s1w=(const float*)d_in[3];  s1b=(const float*)d_in[4];
        s2w=(const float*)d_in[5];  s2b=(const float*)d_in[6];
        W1w=(const float*)d_in[7];  W1b=(const float*)d_in[8];
        W2w=(const float*)d_in[9];  W2b=(const float*)d_in[10];
        Waw=(const float*)d_in[11]; Wab=(const float*)d_in[12];
        V1w=(const float*)d_in[13]; V1b=(const float*)d_in[14];
        V2w=(const float*)d_in[15]; V2b=(const float*)d_in[16];
        Uw =(const float*)d_in[17]; Ub =(const float*)d_in[18];
        clsw=(const float*)d_in[19]; clsb=(const float*)d_in[20];
    } else {
        dec=(const float*)d_in[0]; gls=(const float*)d_in[1];
        s1w=(const float*)d_in[2];  s1b=(const float*)d_in[3];
        s2w=(const float*)d_in[4];  s2b=(const float*)d_in[5];
        W1w=(const float*)d_in[6];  W1b=(const float*)d_in[7];
        W2w=(const float*)d_in[8];  W2b=(const float*)d_in[9];
        Waw=(const float*)d_in[10]; Wab=(const float*)d_in[11];
        V1w=(const float*)d_in[12]; V1b=(const float*)d_in[13];
        V2w=(const float*)d_in[14]; V2b=(const float*)d_in[15];
        Uw =(const float*)d_in[16]; Ub =(const float*)d_in[17];
        clsw=(const float*)d_in[18]; clsb=(const float*)d_in[19];
        pred=(const int*)d_in[20];
    }
    (void)s2b;
    float* out = (float*)d_out;

    cudaFuncSetAttribute(k_big_mma, cudaFuncAttributeMaxDynamicSharedMemorySize, KB_SMEM);

    k_pool_conv   <<<NI + 48*48, 256>>>(dec, gls, pred, W2w, V2w);
    k_gemm1       <<<dim3(6,64), 256>>>(s1w, s1b, s2w);
    k_softmax_bias<<<37, 1024>>>(out + 2*RR, W1w, W1b, W2b, V1w, V1b, V2b, Uw, Ub, clsw);
    k_big_mma     <<<dim3(12, 256), 256, KB_SMEM>>>(Waw);   // launch #4 -> profiled
    k_attn        <<<NI, 32>>>(Wab);
    k_final       <<<RR/8, 256>>>(dec, clsw, clsb, out);
}

// round 11
// speedup vs baseline: 4.2159x; 1.0691x over previous
#include <cuda_runtime.h>
#include <cuda_fp16.h>
#include <math.h>
#include <stdint.h>

// Problem constants
#define NI 2048
#define KSEN 16
#define H 768
#define H2 1536
#define RR (NI*KSEN)   // 32768

// ---------------- device scratch (static; no allocations) ----------------
__device__ float g_feat[NI*H2];      // pooled concat features [N,2H]
__device__ float g_predcat[NI*H2];   // concat(pred_dec, pred_gls) [N,2H]
__device__ float g_score[NI];
__device__ int   g_sel;
__device__ int   g_flag;
__device__ float g_bias_attn[H];     // sel_mg@W1 + W1_b + W2_b
__device__ float g_bias_v[H];        // sel_mg@V1 + V1_b + V2_b
__device__ float g_M[H*2];           // U_w @ cls_w
__device__ float g_c2[2];            // U_b @ cls_w
__device__ float g_logit_part[(size_t)RR*12];
__device__ float g_rv_part[(size_t)RR*24];  // [r][12][2]

// fp16 operands for the big GEMM (both single-rounded)
__device__ __half g_Ah[(size_t)RR*H2];       // ~100.7 MB
__device__ __half g_Bh[(size_t)H2*H2];       // [n][k], n<768: W2 col n; n>=768: V2 col n-768

// ---------------- fp32 packed helpers ----------------
__device__ __forceinline__ unsigned long long pk2(float lo, float hi){
    unsigned long long r;
    asm("mov.b64 %0, {%1, %2};" : "=l"(r) : "f"(lo), "f"(hi));
    return r;
}
__device__ __forceinline__ void up2(unsigned long long v, float& lo, float& hi){
    asm("mov.b64 {%0, %1}, %2;" : "=f"(lo), "=f"(hi) : "l"(v));
}
__device__ __forceinline__ void ffma2(unsigned long long& d, unsigned long long a, unsigned long long b){
    asm("fma.rn.f32x2 %0, %1, %2, %0;" : "+l"(d) : "l"(a), "l"(b));
}
__device__ __forceinline__ float wsum(float v){
    #pragma unroll
    for (int o=16;o;o>>=1) v += __shfl_xor_sync(0xffffffffu, v, o);
    return v;
}

// ---------------- mma.sync helpers (baseline sm_100 legal) ----------------
__device__ __forceinline__ uint32_t smem_u32(const void* p){
    uint32_t a;
    asm("{ .reg .u64 t; cvta.to.shared.u64 t, %1; cvt.u32.u64 %0, t; }" : "=r"(a) : "l"(p));
    return a;
}
__device__ __forceinline__ void ldm4(uint32_t* r, uint32_t addr){
    asm volatile("ldmatrix.sync.aligned.m8n8.x4.shared.b16 {%0,%1,%2,%3}, [%4];"
        : "=r"(r[0]),"=r"(r[1]),"=r"(r[2]),"=r"(r[3]) : "r"(addr));
}
__device__ __forceinline__ void mma_f16(float* c, const uint32_t* a, uint32_t b0, uint32_t b1){
    asm volatile("mma.sync.aligned.m16n8k16.row.col.f32.f16.f16.f32 "
        "{%0,%1,%2,%3}, {%4,%5,%6,%7}, {%8,%9}, {%0,%1,%2,%3};"
        : "+f"(c[0]),"+f"(c[1]),"+f"(c[2]),"+f"(c[3])
        : "r"(a[0]),"r"(a[1]),"r"(a[2]),"r"(a[3]), "r"(b0),"r"(b1));
}
__device__ __forceinline__ void cpa16(uint32_t s, const void* g){
    asm volatile("cp.async.cg.shared.global [%0], [%1], 16;" :: "r"(s), "l"(g));
}
__device__ __forceinline__ void cpa_commit(){ asm volatile("cp.async.commit_group;" ::: "memory"); }
__device__ __forceinline__ void cpa_wait1(){ asm volatile("cp.async.wait_group 1;" ::: "memory"); }

// ---------------- L1: fused pool(+A conv) / B transpose+convert ----------------
__global__ void k_pool_conv(const float* __restrict__ dec, const float* __restrict__ gls,
                            const int* __restrict__ pred,
                            const float* __restrict__ W2, const float* __restrict__ V2){
    int bid = blockIdx.x;
    if (bid == 0 && threadIdx.x == 0) g_flag = 0;
    if (bid < NI){
        int n = bid;
        int p = pred[n];
        if (threadIdx.x == 0) g_score[n] = 0.f;
        const float* db = dec + (size_t)n*KSEN*H;
        const float* gb = gls + (size_t)n*KSEN*H;
        for (int d = threadIdx.x; d < H; d += blockDim.x){
            float sd=0.f, sg=0.f;
            #pragma unroll
            for (int k=0;k<KSEN;k++){
                float vd = db[k*H+d];
                float vg = gb[k*H+d];
                sd += vd; sg += vg;
                size_t r = (size_t)(n*KSEN + k);
                g_Ah[r*H2 + d]     = __float2half_rn(vd);
                g_Ah[r*H2 + H + d] = __float2half_rn(vg);
            }
            float pd = db[p*H+d], pg = gb[p*H+d];
            g_feat[(size_t)n*H2 + d]      = pd - sd*(1.0f/16.0f);
            g_feat[(size_t)n*H2 + H + d]  = pg - sg*(1.0f/16.0f);
            g_predcat[(size_t)n*H2 + d]     = pd;
            g_predcat[(size_t)n*H2 + H + d] = pg;
        }
    } else {
        __shared__ float tile[32][33];
        int cbid = bid - NI;
        int nb = cbid / 48;   // 48 tiles over n
        int kb = cbid % 48;   // 48 tiles over k
        int tx = threadIdx.x & 31, ty = threadIdx.x >> 5;   // 32 x 8
        const float* src = (nb < 24) ? W2 : V2;
        int col0 = (nb % 24) * 32;
        #pragma unroll
        for (int j=0;j<4;j++){
            int kk = ty + j*8;
            tile[tx][kk] = src[(size_t)(kb*32 + kk)*H + col0 + tx];
        }
        __syncthreads();
        int n0 = nb*32;
        #pragma unroll
        for (int j=0;j<4;j++){
            int c = ty + j*8;
            size_t di = (size_t)(n0 + c)*H2 + kb*32 + tx;
            g_Bh[di] = __float2half_rn(tile[c][tx]);
        }
    }
}

// ---------------- L2: h=relu(feat@s1_w+s1_b); fused score atomics (s2_b dropped: shift-inv) ----------------
__global__ void __launch_bounds__(256) k_gemm1(const float* __restrict__ B, const float* __restrict__ bias,
                                               const float* __restrict__ s2w){
    __shared__ float As[16][33];
    __shared__ float Bs[16][128];
    int tid=threadIdx.x, bx=blockIdx.x, by=blockIdx.y;
    int tx=tid&15, ty=tid>>4;
    int arow=tid>>3, akc=(tid&7)*2;
    int bkr=tid>>4, bc0=(tid&15)*8;
    const float* Ap = g_feat + (size_t)(by*32+arow)*H2 + akc;
    const float* Bp = B + (size_t)bkr*H + bx*128 + bc0;
    unsigned long long acc[2][4];
    #pragma unroll
    for(int i=0;i<2;i++){
        #pragma unroll
        for(int j=0;j<4;j++) acc[i][j]=0ull;
    }
    for (int kt=0; kt<H2/16; kt++){
        float2 a0 = *(const float2*)(Ap + kt*16);
        As[akc  ][arow]=a0.x;
        As[akc+1][arow]=a0.y;
        const float* bsrc = Bp + (size_t)kt*16*H;
        *(float4*)&Bs[bkr][bc0]   = *(const float4*)(bsrc);
        *(float4*)&Bs[bkr][bc0+4] = *(const float4*)(bsrc+4);
        __syncthreads();
        #pragma unroll
        for (int k=0;k<16;k++){
            float ra[2];
            ra[0]=As[k][ty*2]; ra[1]=As[k][ty*2+1];
            float4 bb0 = *(float4*)&Bs[k][tx*8];
            float4 bb1 = *(float4*)&Bs[k][tx*8+4];
            unsigned long long rb[4];
            rb[0]=pk2(bb0.x,bb0.y); rb[1]=pk2(bb0.z,bb0.w);
            rb[2]=pk2(bb1.x,bb1.y); rb[3]=pk2(bb1.z,bb1.w);
            #pragma unroll
            for (int i=0;i<2;i++){
                unsigned long long aa = pk2(ra[i],ra[i]);
                #pragma unroll
                for (int jp=0;jp<4;jp++) ffma2(acc[i][jp], aa, rb[jp]);
            }
        }
        __syncthreads();
    }
    int gc = bx*128 + tx*8;
    float bias8[8], sw8[8];
    #pragma unroll
    for (int j=0;j<8;j++){ bias8[j]=bias[gc+j]; sw8[j]=s2w[gc+j]; }
    #pragma unroll
    for (int i=0;i<2;i++){
        int row = by*32 + ty*2 + i;
        float v[8];
        #pragma unroll
        for (int jp=0;jp<4;jp++) up2(acc[i][jp], v[2*jp], v[2*jp+1]);
        float o[8], p = 0.f;
        #pragma unroll
        for (int j=0;j<8;j++){ float t=v[j]+bias8[j]; o[j]= t>0.f? t : 0.f; p += o[j]*sw8[j]; }
        p += __shfl_xor_sync(0xffffffffu, p, 1);
        p += __shfl_xor_sync(0xffffffffu, p, 2);
        p += __shfl_xor_sync(0xffffffffu, p, 4);
        p += __shfl_xor_sync(0xffffffffu, p, 8);
        if (tx == 0) atomicAdd(&g_score[row], p);
    }
}

// ---------------- L3: softmax (block 0) + sel-dependent biases + M (blocks 1..36) ----------------
__global__ void __launch_bounds__(1024) k_softmax_bias(
    float* __restrict__ probs,
    const float* __restrict__ W1, const float* __restrict__ W1b, const float* __restrict__ W2b,
    const float* __restrict__ V1, const float* __restrict__ V1b, const float* __restrict__ V2b,
    const float* __restrict__ Uw, const float* __restrict__ Ub,
    const float* __restrict__ clsw){
    int b = blockIdx.x, tid = threadIdx.x;
    if (b == 0){
        __shared__ float sv[1024];
        __shared__ int   si[1024];
        float a=g_score[tid], bb=g_score[tid+1024];
        float m; int mi;
        if (a>=bb){ m=a; mi=tid; } else { m=bb; mi=tid+1024; }
        sv[tid]=m; si[tid]=mi;
        __syncthreads();
        for (int s=512;s>0;s>>=1){
            if (tid<s){
                float ov=sv[tid+s]; int oi=si[tid+s];
                if (ov>sv[tid] || (ov==sv[tid] && oi<si[tid])){ sv[tid]=ov; si[tid]=oi; }
            }
            __syncthreads();
        }
        float mx = sv[0]; int sel = si[0];
        if (tid==0) g_sel = sel;
        __syncthreads();
        float e0 = expf(a-mx), e1 = expf(bb-mx);
        sv[tid] = e0+e1;
        __syncthreads();
        for (int s=512;s>0;s>>=1){ if (tid<s) sv[tid]+=sv[tid+s]; __syncthreads(); }
        float inv = 1.0f/sv[0];
        probs[tid]      = e0*inv;
        probs[tid+1024] = e1*inv;
        __threadfence();
        __syncthreads();
        if (tid==0) atomicExch(&g_flag, 1);
        return;
    }
    if (tid == 0){ while (atomicAdd(&g_flag, 0) == 0) __nanosleep(64); }
    __syncthreads();
    __threadfence();
    if (b <= 12){
        __shared__ float red[8][128];
        int g = b - 1;
        int half = (g >= 6);
        int jbase = (half ? g-6 : g) * 128;
        int jj = tid & 127, c = tid >> 7;
        int sel = g_sel;
        const float* m = half ? V1 : W1;
        const float* srow = g_predcat + (size_t)sel*H2;
        int j = jbase + jj;
        float s = 0.f;
        int i0 = c*192;
        #pragma unroll 4
        for (int i=i0; i<i0+192; i++) s += srow[i]*m[(size_t)i*H + j];
        red[c][jj] = s;
        __syncthreads();
        if (c == 0){
            float t = 0.f;
            #pragma unroll
            for (int cc=0; cc<8; cc++) t += red[cc][jj];
            if (half) g_bias_v[j]    = t + V1b[j] + V2b[j];
            else      g_bias_attn[j] = t + W1b[j] + W2b[j];
        }
    } else {
        int w = tid >> 5, lane = tid & 31;
        int j = (b-13)*32 + w;
        const float* ur = Uw + (size_t)j*H;
        float m0=0.f, m1=0.f;
        for (int t=lane; t<H; t+=32){ float u=ur[t]; m0+=u*clsw[2*t]; m1+=u*clsw[2*t+1]; }
        m0 = wsum(m0); m1 = wsum(m1);
        if (lane==0){ g_M[2*j]=m0; g_M[2*j+1]=m1; }
        if (b==13 && w==1){
            float s0=0.f, s1=0.f;
            for (int t=lane; t<H; t+=32){ float u=Ub[t]; s0+=u*clsw[2*t]; s1+=u*clsw[2*t+1]; }
            s0 = wsum(s0); s1 = wsum(s1);
            if (lane==0){ g_c2[0]=s0; g_c2[1]=s1; }
        }
    }
}

// ---------------- L4: mma.sync fp16 single-product GEMM + reduce (K64 stages) ----------------
// grid (12, 256), CTA 128x128, 256 thr, warps 4(M)x2(N), warp tile 32x64.
// 3-stage cp.async pipeline, K-chunk 64 per stage (24 iters), occupancy 2, one barrier/iter.
// Region row stride 144B (9x16B) keeps ldmatrix 8-row phases distinct -> conflict-free.
#define KB_REGION 18432
#define KB_STAGE  36864
#define KB_SMEM   (3*KB_STAGE)
#define KB_ITERS  24

__device__ __forceinline__ void kb_load_stage(uint32_t sb, int stage, int by, int cb, int gk, int tid){
    uint32_t s0 = sb + stage*KB_STAGE;
    #pragma unroll
    for (int j=0;j<8;j++){
        int idx = j*256 + tid;        // 0..2047
        int region = idx >> 10;       // 0 A, 1 Bh
        int cl = idx & 1023;
        int r  = cl >> 3;
        int kc = cl & 7;
        const __half* g = region ? g_Bh : g_Ah;
        size_t grow = region ? (size_t)(cb*128 + r) : (size_t)(by*128 + r);
        cpa16(s0 + region*KB_REGION + r*144 + kc*16, g + grow*H2 + gk + kc*8);
    }
}

__global__ void __launch_bounds__(256,2) k_big_mma(const float* __restrict__ Wa){
    extern __shared__ char smem[];
    uint32_t sb = smem_u32(smem);
    int tid = threadIdx.x;
    int cb = blockIdx.x, by = blockIdx.y;
    int warp = tid >> 5, lane = tid & 31;
    int wm = warp & 3, wn = warp >> 2;      // wm 0..3 (M), wn 0..1 (N)

    float acc[2][8][4];
    #pragma unroll
    for (int mt=0;mt<2;mt++)
        #pragma unroll
        for (int nt=0;nt<8;nt++)
            #pragma unroll
            for (int d=0;d<4;d++) acc[mt][nt][d] = 0.f;

    kb_load_stage(sb, 0, by, cb, 0,  tid); cpa_commit();
    kb_load_stage(sb, 1, by, cb, 64, tid); cpa_commit();

    int m8 = lane >> 3, r8 = lane & 7;

    for (int it = 0; it < KB_ITERS; it++){
        cpa_wait1();               // own copies of stage it complete
        __syncthreads();           // visibility; all compute(it-1) done
        if (it + 2 < KB_ITERS) kb_load_stage(sb, (it+2)%3, by, cb, (it+2)*64, tid);
        cpa_commit();              // empty group at tail keeps wait count aligned

        uint32_t st = sb + (it%3)*KB_STAGE;
        #pragma unroll
        for (int kh=0; kh<4; kh++){
            int k0 = kh*16;
            uint32_t ah[2][4], bb[4][4];
            #pragma unroll
            for (int mt=0;mt<2;mt++){
                int rowA = wm*32 + mt*16 + (m8&1)*8 + r8;
                int kA   = k0 + (m8>>1)*8;
                ldm4(ah[mt], st + 0*KB_REGION + rowA*144 + kA*2);
            }
            int rowB = wn*64 + (m8>>1)*8 + r8;
            int kB   = k0 + (m8&1)*8;
            uint32_t boff = rowB*144 + kB*2;
            #pragma unroll
            for (int ntp=0;ntp<4;ntp++) ldm4(bb[ntp], st + 1*KB_REGION + boff + ntp*16*144);
            #pragma unroll
            for (int mt=0;mt<2;mt++)
                #pragma unroll
                for (int nt=0;nt<8;nt++)
                    mma_f16(acc[mt][nt], ah[mt], bb[nt>>1][(nt&1)*2], bb[nt>>1][(nt&1)*2+1]);
        }
    }

    // ---------------- epilogue: reduce over the 128 columns this CTA owns ----------------
    int quad = lane >> 2, qt = lane & 3;
    if (cb < 6){
        int colb = cb*128;
        #pragma unroll
        for (int mt=0;mt<2;mt++){
            float plo = 0.f, phi = 0.f;
            #pragma unroll
            for (int nt=0;nt<8;nt++){
                int g0 = colb + wn*64 + nt*8 + qt*2;
                float ba0 = g_bias_attn[g0],  ba1 = g_bias_attn[g0+1];
                float w0  = Wa[g0],           w1  = Wa[g0+1];
                plo += tanhf(acc[mt][nt][0]+ba0)*w0 + tanhf(acc[mt][nt][1]+ba1)*w1;
                phi += tanhf(acc[mt][nt][2]+ba0)*w0 + tanhf(acc[mt][nt][3]+ba1)*w1;
            }
            plo += __shfl_xor_sync(0xffffffffu, plo, 1);
            plo += __shfl_xor_sync(0xffffffffu, plo, 2);
            phi += __shfl_xor_sync(0xffffffffu, phi, 1);
            phi += __shfl_xor_sync(0xffffffffu, phi, 2);
            if (qt == 0){
                int rlo = by*128 + wm*32 + mt*16 + quad;
                g_logit_part[(size_t)rlo*12 + cb*2 + wn]     = plo;
                g_logit_part[(size_t)(rlo+8)*12 + cb*2 + wn] = phi;
            }
        }
    } else {
        int cbv = cb - 6, colb = cbv*128, slot = cbv*2 + wn;
        #pragma unroll
        for (int mt=0;mt<2;mt++){
            float p0l=0.f, p1l=0.f, p0h=0.f, p1h=0.f;
            #pragma unroll
            for (int nt=0;nt<8;nt++){
                int g0 = colb + wn*64 + nt*8 + qt*2;
                float bv0 = g_bias_v[g0], bv1 = g_bias_v[g0+1];
                float m00 = g_M[2*g0],   m01 = g_M[2*g0+1];
                float m10 = g_M[2*g0+2], m11 = g_M[2*g0+3];
                float x;
                x = acc[mt][nt][0]+bv0; x = x>0.f? x:0.f; p0l += x*m00; p1l += x*m01;
                x = acc[mt][nt][1]+bv1; x = x>0.f? x:0.f; p0l += x*m10; p1l += x*m11;
                x = acc[mt][nt][2]+bv0; x = x>0.f? x:0.f; p0h += x*m00; p1h += x*m01;
                x = acc[mt][nt][3]+bv1; x = x>0.f? x:0.f; p0h += x*m10; p1h += x*m11;
            }
            p0l += __shfl_xor_sync(0xffffffffu, p0l, 1); p0l += __shfl_xor_sync(0xffffffffu, p0l, 2);
            p1l += __shfl_xor_sync(0xffffffffu, p1l, 1); p1l += __shfl_xor_sync(0xffffffffu, p1l, 2);
            p0h += __shfl_xor_sync(0xffffffffu, p0h, 1); p0h += __shfl_xor_sync(0xffffffffu, p0h, 2);
            p1h += __shfl_xor_sync(0xffffffffu, p1h, 1); p1h += __shfl_xor_sync(0xffffffffu, p1h, 2);
            if (qt == 0){
                int rlo = by*128 + wm*32 + mt*16 + quad;
                g_rv_part[(size_t)rlo*24 + slot*2 + 0] = p0l;
                g_rv_part[(size_t)rlo*24 + slot*2 + 1] = p1l;
                g_rv_part[(size_t)(rlo+8)*24 + slot*2 + 0] = p0h;
                g_rv_part[(size_t)(rlo+8)*24 + slot*2 + 1] = p1h;
            }
        }
    }
}

// ---------------- L5: fused per-instance attn softmax + final logits ----------------
// One block per instance (512 thr = 16 warps, warp w = sense row). Wa_b dropped
// (uniform across K -> cancels in softmax).
__global__ void __launch_bounds__(512) k_attn_final(const float* __restrict__ dec,
                                                    const float* __restrict__ clsw,
                                                    const float* __restrict__ clsb,
                                                    float* __restrict__ out){
    __shared__ float slg[16];
    __shared__ float sat[16];
    int n = blockIdx.x;
    int w = threadIdx.x >> 5, lane = threadIdx.x & 31;
    int r = n*KSEN + w;
    const float* drow = dec + (size_t)r*H;
    float a0=0.f, a1=0.f;
    #pragma unroll 4
    for (int t=lane;t<H;t+=32){ float d=drow[t]; a0 += d*clsw[2*t]; a1 += d*clsw[2*t+1]; }
    a0 = wsum(a0); a1 = wsum(a1);
    float lgp = (lane < 12) ? g_logit_part[(size_t)r*12 + lane] : 0.f;
    float lg = wsum(lgp);
    if (lane == 0) slg[w] = lg;
    __syncthreads();
    if (w == 0){
        float v = (lane < 16) ? slg[lane] : -INFINITY;
        float m = v;
        #pragma unroll
        for (int o=16;o;o>>=1) m = fmaxf(m, __shfl_xor_sync(0xffffffffu, m, o));
        float e = (lane < 16) ? expf(v - m) : 0.f;
        float s = wsum(e);
        if (lane < 16) sat[lane] = e/s;
    }
    float rv0p = (lane < 12) ? g_rv_part[(size_t)r*24 + lane*2]     : 0.f;
    float rv1p = (lane < 12) ? g_rv_part[(size_t)r*24 + lane*2 + 1] : 0.f;
    float rv0 = wsum(rv0p), rv1 = wsum(rv1p);
    __syncthreads();
    if (lane == 0){
        float o0 = a0 + clsb[0], o1 = a1 + clsb[1];
        if (n != g_sel){
            float at = sat[w];
            o0 += at*(rv0 + g_c2[0]);
            o1 += at*(rv1 + g_c2[1]);
        }
        out[2*r]   = o0;
        out[2*r+1] = o1;
    }
}

// ---------------- launcher ----------------
extern "C" void kernel_launch(void* const* d_in, const int* in_sizes, int n_in,
                              void* d_out, int out_size){
    (void)n_in; (void)out_size;
    const float *dec,*gls,*s1w,*s1b,*s2w,*s2b,*W1w,*W1b,*W2w,*W2b,*Waw,*Wab,*V1w,*V1b,*V2w,*V2b,*Uw,*Ub,*clsw,*clsb;
    const int* pred;
    if (in_sizes[2] == NI){
        dec=(const float*)d_in[0]; gls=(const float*)d_in[1]; pred=(const int*)d_in[2];
        s1w=(const float*)d_in[3];  s1b=(const float*)d_in[4];
        s2w=(const float*)d_in[5];  s2b=(const float*)d_in[6];
        W1w=(const float*)d_in[7];  W1b=(const float*)d_in[8];
        W2w=(const float*)d_in[9];  W2b=(const float*)d_in[10];
        Waw=(const float*)d_in[11]; Wab=(const float*)d_in[12];
        V1w=(const float*)d_in[13]; V1b=(const float*)d_in[14];
        V2w=(const float*)d_in[15]; V2b=(const float*)d_in[16];
        Uw =(const float*)d_in[17]; Ub =(const float*)d_in[18];
        clsw=(const float*)d_in[19]; clsb=(const float*)d_in[20];
    } else {
        dec=(const float*)d_in[0]; gls=(const float*)d_in[1];
        s1w=(const float*)d_in[2];  s1b=(const float*)d_in[3];
        s2w=(const float*)d_in[4];  s2b=(const float*)d_in[5];
        W1w=(const float*)d_in[6];  W1b=(const float*)d_in[7];
        W2w=(const float*)d_in[8];  W2b=(const float*)d_in[9];
        Waw=(const float*)d_in[10]; Wab=(const float*)d_in[11];
        V1w=(const float*)d_in[12]; V1b=(const float*)d_in[13];
        V2w=(const float*)d_in[14]; V2b=(const float*)d_in[15];
        Uw =(const float*)d_in[16]; Ub =(const float*)d_in[17];
        clsw=(const float*)d_in[18]; clsb=(const float*)d_in[19];
        pred=(const int*)d_in[20];
    }
    (void)s2b; (void)Wab;
    float* out = (float*)d_out;

    cudaFuncSetAttribute(k_big_mma, cudaFuncAttributeMaxDynamicSharedMemorySize, KB_SMEM);

    k_pool_conv   <<<NI + 48*48, 256>>>(dec, gls, pred, W2w, V2w);
    k_gemm1       <<<dim3(6,64), 256>>>(s1w, s1b, s2w);
    k_softmax_bias<<<37, 1024>>>(out + 2*RR, W1w, W1b, W2b, V1w, V1b, V2b, Uw, Ub, clsw);
    k_big_mma     <<<dim3(12, 256), 256, KB_SMEM>>>(Waw);   // launch #4 -> profiled
    k_attn_final  <<<NI, 512>>>(dec, clsw, clsb, out);
}

// round 12
// speedup vs baseline: 6.4728x; 1.5353x over previous
#include <cuda_runtime.h>
#include <cuda_fp16.h>
#include <math.h>
#include <stdint.h>

// Problem constants
#define NI 2048
#define KSEN 16
#define H 768
#define H2 1536
#define RR (NI*KSEN)   // 32768

// ---------------- device scratch (static; no allocations) ----------------
__device__ float g_predcat[NI*H2];   // concat(pred_dec, pred_gls) [N,2H]
__device__ float g_score[NI];
__device__ int   g_sel;
__device__ int   g_flag;
__device__ float g_bias_attn[H];     // sel_mg@W1 + W1_b + W2_b
__device__ float g_bias_v[H];        // sel_mg@V1 + V1_b + V2_b
__device__ float g_M[H*2];           // U_w @ cls_w
__device__ float g_c2[2];            // U_b @ cls_w
__device__ float g_logit_part[(size_t)RR*12];
__device__ float g_rv_part[(size_t)RR*24];  // [r][12][2]

// fp16 operands
__device__ __half g_Ah[(size_t)RR*H2];       // big-GEMM A (~100.7 MB)
__device__ __half g_Bh[(size_t)H2*H2];       // big-GEMM B [n][k]; n<768: W2 col n, else V2 col n-768
__device__ __half g_Fh[(size_t)NI*H2];       // feat hi  [n][k]
__device__ __half g_Fl[(size_t)NI*H2];       // feat lo
__device__ __half g_S1h[(size_t)H*H2];       // s1_w^T hi [o][i]
__device__ __half g_S1l[(size_t)H*H2];       // s1_w^T lo

// ---------------- helpers ----------------
__device__ __forceinline__ float wsum(float v){
    #pragma unroll
    for (int o=16;o;o>>=1) v += __shfl_xor_sync(0xffffffffu, v, o);
    return v;
}
__device__ __forceinline__ uint32_t smem_u32(const void* p){
    uint32_t a;
    asm("{ .reg .u64 t; cvta.to.shared.u64 t, %1; cvt.u32.u64 %0, t; }" : "=r"(a) : "l"(p));
    return a;
}
__device__ __forceinline__ void ldm4(uint32_t* r, uint32_t addr){
    asm volatile("ldmatrix.sync.aligned.m8n8.x4.shared.b16 {%0,%1,%2,%3}, [%4];"
        : "=r"(r[0]),"=r"(r[1]),"=r"(r[2]),"=r"(r[3]) : "r"(addr));
}
__device__ __forceinline__ void mma_f16(float* c, const uint32_t* a, uint32_t b0, uint32_t b1){
    asm volatile("mma.sync.aligned.m16n8k16.row.col.f32.f16.f16.f32 "
        "{%0,%1,%2,%3}, {%4,%5,%6,%7}, {%8,%9}, {%0,%1,%2,%3};"
        : "+f"(c[0]),"+f"(c[1]),"+f"(c[2]),"+f"(c[3])
        : "r"(a[0]),"r"(a[1]),"r"(a[2]),"r"(a[3]), "r"(b0),"r"(b1));
}
__device__ __forceinline__ void cpa16(uint32_t s, const void* g){
    asm volatile("cp.async.cg.shared.global [%0], [%1], 16;" :: "r"(s), "l"(g));
}
__device__ __forceinline__ void cpa_commit(){ asm volatile("cp.async.commit_group;" ::: "memory"); }
__device__ __forceinline__ void cpa_wait1(){ asm volatile("cp.async.wait_group 1;" ::: "memory"); }

// ---------------- L1: pool(+conversions) / W2|V2 transpose / s1_w transpose+split ----------------
// blocks [0,NI): instances; [NI, NI+2304): Bh tiles; [NI+2304, NI+2304+1152): s1w tiles
__global__ void k_pool_conv(const float* __restrict__ dec, const float* __restrict__ gls,
                            const int* __restrict__ pred,
                            const float* __restrict__ W2, const float* __restrict__ V2,
                            const float* __restrict__ s1w){
    int bid = blockIdx.x;
    if (bid == 0 && threadIdx.x == 0) g_flag = 0;
    if (bid < NI){
        int n = bid;
        int p = pred[n];
        if (threadIdx.x == 0) g_score[n] = 0.f;
        const float* db = dec + (size_t)n*KSEN*H;
        const float* gb = gls + (size_t)n*KSEN*H;
        for (int dp = threadIdx.x; dp < H/2; dp += blockDim.x){
            int d = dp*2;
            float sd0=0.f, sd1=0.f, sg0=0.f, sg1=0.f;
            #pragma unroll
            for (int k=0;k<KSEN;k++){
                float2 vd = *(const float2*)(db + k*H + d);
                float2 vg = *(const float2*)(gb + k*H + d);
                sd0 += vd.x; sd1 += vd.y; sg0 += vg.x; sg1 += vg.y;
                size_t r = (size_t)(n*KSEN + k);
                *(__half2*)(g_Ah + r*H2 + d)     = __floats2half2_rn(vd.x, vd.y);
                *(__half2*)(g_Ah + r*H2 + H + d) = __floats2half2_rn(vg.x, vg.y);
            }
            float2 pd = *(const float2*)(db + p*H + d);
            float2 pg = *(const float2*)(gb + p*H + d);
            float f0 = pd.x - sd0*(1.0f/16.0f), f1 = pd.y - sd1*(1.0f/16.0f);
            float h0 = pg.x - sg0*(1.0f/16.0f), h1 = pg.y - sg1*(1.0f/16.0f);
            __half fh0 = __float2half_rn(f0), fh1 = __float2half_rn(f1);
            __half hh0 = __float2half_rn(h0), hh1 = __float2half_rn(h1);
            size_t fb = (size_t)n*H2;
            *(__half2*)(g_Fh + fb + d)     = __half2(fh0, fh1);
            *(__half2*)(g_Fh + fb + H + d) = __half2(hh0, hh1);
            *(__half2*)(g_Fl + fb + d)     = __floats2half2_rn(f0-__half2float(fh0), f1-__half2float(fh1));
            *(__half2*)(g_Fl + fb + H + d) = __floats2half2_rn(h0-__half2float(hh0), h1-__half2float(hh1));
            *(float2*)(g_predcat + fb + d)     = pd;
            *(float2*)(g_predcat + fb + H + d) = pg;
        }
    } else if (bid < NI + 2304){
        __shared__ float tile[32][33];
        int cbid = bid - NI;
        int nb = cbid / 48;   // 48 tiles over n
        int kb = cbid % 48;   // 48 tiles over k
        int tx = threadIdx.x & 31, ty = threadIdx.x >> 5;   // 32 x 8
        const float* src = (nb < 24) ? W2 : V2;
        int col0 = (nb % 24) * 32;
        #pragma unroll
        for (int j=0;j<4;j++){
            int kk = ty + j*8;
            tile[tx][kk] = src[(size_t)(kb*32 + kk)*H + col0 + tx];
        }
        __syncthreads();
        int n0 = nb*32;
        #pragma unroll
        for (int j=0;j<4;j++){
            int c = ty + j*8;
            size_t di = (size_t)(n0 + c)*H2 + kb*32 + tx;
            g_Bh[di] = __float2half_rn(tile[c][tx]);
        }
    } else {
        // s1w transpose + hi/lo split: s1w [i=1536][o=768] -> g_S1h/l [o][i]
        __shared__ float tile[32][33];
        int cbid = bid - NI - 2304;
        int ob = cbid / 48;   // 24 tiles over o
        int kb = cbid % 48;   // 48 tiles over i
        int tx = threadIdx.x & 31, ty = threadIdx.x >> 5;
        int o0 = ob*32;
        #pragma unroll
        for (int j=0;j<4;j++){
            int kk = ty + j*8;
            tile[tx][kk] = s1w[(size_t)(kb*32 + kk)*H + o0 + tx];
        }
        __syncthreads();
        #pragma unroll
        for (int j=0;j<4;j++){
            int c = ty + j*8;
            float v = tile[c][tx];
            __half hi = __float2half_rn(v);
            size_t di = (size_t)(o0 + c)*H2 + kb*32 + tx;
            g_S1h[di] = hi;
            g_S1l[di] = __float2half_rn(v - __half2float(hi));
        }
    }
}

// ---------------- L2: tensor-core gemm1: score partials via 3-product fp16 split ----------------
// grid (6, 16): cb = 128-col block of s1w outputs, by = 128-instance block.
// Regions per stage: Fh | Fl | S1h | S1l, each 128 rows x 64 k, row stride 144B.
#define G1_REGION 18432
#define G1_STAGE  73728
#define G1_SMEM   (3*G1_STAGE)
#define G1_ITERS  24

__device__ __forceinline__ void g1_load_stage(uint32_t sb, int stage, int by, int cb, int gk, int tid){
    uint32_t s0 = sb + stage*G1_STAGE;
    #pragma unroll
    for (int j=0;j<16;j++){
        int idx = j*256 + tid;        // 0..4095
        int region = idx >> 10;       // 0 Fh, 1 Fl, 2 S1h, 3 S1l
        int cl = idx & 1023;
        int r  = cl >> 3;
        int kc = cl & 7;
        const __half* g;
        size_t grow;
        if (region == 0){ g = g_Fh;  grow = (size_t)(by*128 + r); }
        else if (region == 1){ g = g_Fl;  grow = (size_t)(by*128 + r); }
        else if (region == 2){ g = g_S1h; grow = (size_t)(cb*128 + r); }
        else { g = g_S1l; grow = (size_t)(cb*128 + r); }
        cpa16(s0 + region*G1_REGION + r*144 + kc*16, g + grow*H2 + gk + kc*8);
    }
}

__global__ void __launch_bounds__(256,1) k_gemm1t(const float* __restrict__ s1b,
                                                  const float* __restrict__ s2w){
    extern __shared__ char smem[];
    uint32_t sb = smem_u32(smem);
    int tid = threadIdx.x;
    int cb = blockIdx.x, by = blockIdx.y;
    int warp = tid >> 5, lane = tid & 31;
    int wm = warp & 3, wn = warp >> 2;

    float acc[2][8][4];
    #pragma unroll
    for (int mt=0;mt<2;mt++)
        #pragma unroll
        for (int nt=0;nt<8;nt++)
            #pragma unroll
            for (int d=0;d<4;d++) acc[mt][nt][d] = 0.f;

    g1_load_stage(sb, 0, by, cb, 0,  tid); cpa_commit();
    g1_load_stage(sb, 1, by, cb, 64, tid); cpa_commit();

    int m8 = lane >> 3, r8 = lane & 7;

    for (int it = 0; it < G1_ITERS; it++){
        cpa_wait1();
        __syncthreads();
        if (it + 2 < G1_ITERS) g1_load_stage(sb, (it+2)%3, by, cb, (it+2)*64, tid);
        cpa_commit();

        uint32_t st = sb + (it%3)*G1_STAGE;
        #pragma unroll
        for (int kh=0; kh<4; kh++){
            int k0 = kh*16;
            uint32_t ah[2][4], al[2][4], bb[4][4];
            #pragma unroll
            for (int mt=0;mt<2;mt++){
                int rowA = wm*32 + mt*16 + (m8&1)*8 + r8;
                int kA   = k0 + (m8>>1)*8;
                uint32_t aoff = rowA*144 + kA*2;
                ldm4(ah[mt], st + 0*G1_REGION + aoff);
                ldm4(al[mt], st + 1*G1_REGION + aoff);
            }
            int rowB = wn*64 + (m8>>1)*8 + r8;
            int kB   = k0 + (m8&1)*8;
            uint32_t boff = rowB*144 + kB*2;
            // S1h: products Fh*S1h and Fl*S1h
            #pragma unroll
            for (int ntp=0;ntp<4;ntp++) ldm4(bb[ntp], st + 2*G1_REGION + boff + ntp*16*144);
            #pragma unroll
            for (int mt=0;mt<2;mt++)
                #pragma unroll
                for (int nt=0;nt<8;nt++)
                    mma_f16(acc[mt][nt], ah[mt], bb[nt>>1][(nt&1)*2], bb[nt>>1][(nt&1)*2+1]);
            #pragma unroll
            for (int mt=0;mt<2;mt++)
                #pragma unroll
                for (int nt=0;nt<8;nt++)
                    mma_f16(acc[mt][nt], al[mt], bb[nt>>1][(nt&1)*2], bb[nt>>1][(nt&1)*2+1]);
            // S1l: product Fh*S1l
            #pragma unroll
            for (int ntp=0;ntp<4;ntp++) ldm4(bb[ntp], st + 3*G1_REGION + boff + ntp*16*144);
            #pragma unroll
            for (int mt=0;mt<2;mt++)
                #pragma unroll
                for (int nt=0;nt<8;nt++)
                    mma_f16(acc[mt][nt], ah[mt], bb[nt>>1][(nt&1)*2], bb[nt>>1][(nt&1)*2+1]);
        }
    }

    // epilogue: relu(acc + s1b) . s2w over this CTA's 128 cols -> score atomics
    int quad = lane >> 2, qt = lane & 3;
    int colb = cb*128;
    #pragma unroll
    for (int mt=0;mt<2;mt++){
        float plo = 0.f, phi = 0.f;
        #pragma unroll
        for (int nt=0;nt<8;nt++){
            int g0 = colb + wn*64 + nt*8 + qt*2;
            float b0 = s1b[g0], b1 = s1b[g0+1];
            float w0 = s2w[g0], w1 = s2w[g0+1];
            float x;
            x = acc[mt][nt][0]+b0; x = x>0.f? x:0.f; plo += x*w0;
            x = acc[mt][nt][1]+b1; x = x>0.f? x:0.f; plo += x*w1;
            x = acc[mt][nt][2]+b0; x = x>0.f? x:0.f; phi += x*w0;
            x = acc[mt][nt][3]+b1; x = x>0.f? x:0.f; phi += x*w1;
        }
        plo += __shfl_xor_sync(0xffffffffu, plo, 1);
        plo += __shfl_xor_sync(0xffffffffu, plo, 2);
        phi += __shfl_xor_sync(0xffffffffu, phi, 1);
        phi += __shfl_xor_sync(0xffffffffu, phi, 2);
        if (qt == 0){
            int rlo = by*128 + wm*32 + mt*16 + quad;
            atomicAdd(&g_score[rlo],   plo);
            atomicAdd(&g_score[rlo+8], phi);
        }
    }
}

// ---------------- L3: softmax (block 0) + sel-dependent biases + M (blocks 1..36) ----------------
__global__ void __launch_bounds__(1024) k_softmax_bias(
    float* __restrict__ probs,
    const float* __restrict__ W1, const float* __restrict__ W1b, const float* __restrict__ W2b,
    const float* __restrict__ V1, const float* __restrict__ V1b, const float* __restrict__ V2b,
    const float* __restrict__ Uw, const float* __restrict__ Ub,
    const float* __restrict__ clsw){
    int b = blockIdx.x, tid = threadIdx.x;
    if (b == 0){
        __shared__ float sv[1024];
        __shared__ int   si[1024];
        float a=g_score[tid], bb=g_score[tid+1024];
        float m; int mi;
        if (a>=bb){ m=a; mi=tid; } else { m=bb; mi=tid+1024; }
        sv[tid]=m; si[tid]=mi;
        __syncthreads();
        for (int s=512;s>0;s>>=1){
            if (tid<s){
                float ov=sv[tid+s]; int oi=si[tid+s];
                if (ov>sv[tid] || (ov==sv[tid] && oi<si[tid])){ sv[tid]=ov; si[tid]=oi; }
            }
            __syncthreads();
        }
        float mx = sv[0]; int sel = si[0];
        if (tid==0) g_sel = sel;
        __syncthreads();
        float e0 = expf(a-mx), e1 = expf(bb-mx);
        sv[tid] = e0+e1;
        __syncthreads();
        for (int s=512;s>0;s>>=1){ if (tid<s) sv[tid]+=sv[tid+s]; __syncthreads(); }
        float inv = 1.0f/sv[0];
        probs[tid]      = e0*inv;
        probs[tid+1024] = e1*inv;
        __threadfence();
        __syncthreads();
        if (tid==0) atomicExch(&g_flag, 1);
        return;
    }
    if (tid == 0){ while (atomicAdd(&g_flag, 0) == 0) __nanosleep(64); }
    __syncthreads();
    __threadfence();
    if (b <= 12){
        __shared__ float red[8][128];
        int g = b - 1;
        int half = (g >= 6);
        int jbase = (half ? g-6 : g) * 128;
        int jj = tid & 127, c = tid >> 7;
        int sel = g_sel;
        const float* m = half ? V1 : W1;
        const float* srow = g_predcat + (size_t)sel*H2;
        int j = jbase + jj;
        float s = 0.f;
        int i0 = c*192;
        #pragma unroll 4
        for (int i=i0; i<i0+192; i++) s += srow[i]*m[(size_t)i*H + j];
        red[c][jj] = s;
        __syncthreads();
        if (c == 0){
            float t = 0.f;
            #pragma unroll
            for (int cc=0; cc<8; cc++) t += red[cc][jj];
            if (half) g_bias_v[j]    = t + V1b[j] + V2b[j];
            else      g_bias_attn[j] = t + W1b[j] + W2b[j];
        }
    } else {
        int w = tid >> 5, lane = tid & 31;
        int j = (b-13)*32 + w;
        const float* ur = Uw + (size_t)j*H;
        float m0=0.f, m1=0.f;
        for (int t=lane; t<H; t+=32){ float u=ur[t]; m0+=u*clsw[2*t]; m1+=u*clsw[2*t+1]; }
        m0 = wsum(m0); m1 = wsum(m1);
        if (lane==0){ g_M[2*j]=m0; g_M[2*j+1]=m1; }
        if (b==13 && w==1){
            float s0=0.f, s1=0.f;
            for (int t=lane; t<H; t+=32){ float u=Ub[t]; s0+=u*clsw[2*t]; s1+=u*clsw[2*t+1]; }
            s0 = wsum(s0); s1 = wsum(s1);
            if (lane==0){ g_c2[0]=s0; g_c2[1]=s1; }
        }
    }
}

// ---------------- L4: mma.sync fp16 single-product GEMM + reduce (K64 stages) ----------------
#define KB_REGION 18432
#define KB_STAGE  36864
#define KB_SMEM   (3*KB_STAGE)
#define KB_ITERS  24

__device__ __forceinline__ void kb_load_stage(uint32_t sb, int stage, int by, int cb, int gk, int tid){
    uint32_t s0 = sb + stage*KB_STAGE;
    #pragma unroll
    for (int j=0;j<8;j++){
        int idx = j*256 + tid;
        int region = idx >> 10;
        int cl = idx & 1023;
        int r  = cl >> 3;
        int kc = cl & 7;
        const __half* g = region ? g_Bh : g_Ah;
        size_t grow = region ? (size_t)(cb*128 + r) : (size_t)(by*128 + r);
        cpa16(s0 + region*KB_REGION + r*144 + kc*16, g + grow*H2 + gk + kc*8);
    }
}

__global__ void __launch_bounds__(256,2) k_big_mma(const float* __restrict__ Wa){
    extern __shared__ char smem[];
    uint32_t sb = smem_u32(smem);
    int tid = threadIdx.x;
    int cb = blockIdx.x, by = blockIdx.y;
    int warp = tid >> 5, lane = tid & 31;
    int wm = warp & 3, wn = warp >> 2;

    float acc[2][8][4];
    #pragma unroll
    for (int mt=0;mt<2;mt++)
        #pragma unroll
        for (int nt=0;nt<8;nt++)
            #pragma unroll
            for (int d=0;d<4;d++) acc[mt][nt][d] = 0.f;

    kb_load_stage(sb, 0, by, cb, 0,  tid); cpa_commit();
    kb_load_stage(sb, 1, by, cb, 64, tid); cpa_commit();

    int m8 = lane >> 3, r8 = lane & 7;

    for (int it = 0; it < KB_ITERS; it++){
        cpa_wait1();
        __syncthreads();
        if (it + 2 < KB_ITERS) kb_load_stage(sb, (it+2)%3, by, cb, (it+2)*64, tid);
        cpa_commit();

        uint32_t st = sb + (it%3)*KB_STAGE;
        #pragma unroll
        for (int kh=0; kh<4; kh++){
            int k0 = kh*16;
            uint32_t ah[2][4], bb[4][4];
            #pragma unroll
            for (int mt=0;mt<2;mt++){
                int rowA = wm*32 + mt*16 + (m8&1)*8 + r8;
                int kA   = k0 + (m8>>1)*8;
                ldm4(ah[mt], st + 0*KB_REGION + rowA*144 + kA*2);
            }
            int rowB = wn*64 + (m8>>1)*8 + r8;
            int kB   = k0 + (m8&1)*8;
            uint32_t boff = rowB*144 + kB*2;
            #pragma unroll
            for (int ntp=0;ntp<4;ntp++) ldm4(bb[ntp], st + 1*KB_REGION + boff + ntp*16*144);
            #pragma unroll
            for (int mt=0;mt<2;mt++)
                #pragma unroll
                for (int nt=0;nt<8;nt++)
                    mma_f16(acc[mt][nt], ah[mt], bb[nt>>1][(nt&1)*2], bb[nt>>1][(nt&1)*2+1]);
        }
    }

    int quad = lane >> 2, qt = lane & 3;
    if (cb < 6){
        int colb = cb*128;
        #pragma unroll
        for (int mt=0;mt<2;mt++){
            float plo = 0.f, phi = 0.f;
            #pragma unroll
            for (int nt=0;nt<8;nt++){
                int g0 = colb + wn*64 + nt*8 + qt*2;
                float ba0 = g_bias_attn[g0],  ba1 = g_bias_attn[g0+1];
                float w0  = Wa[g0],           w1  = Wa[g0+1];
                plo += tanhf(acc[mt][nt][0]+ba0)*w0 + tanhf(acc[mt][nt][1]+ba1)*w1;
                phi += tanhf(acc[mt][nt][2]+ba0)*w0 + tanhf(acc[mt][nt][3]+ba1)*w1;
            }
            plo += __shfl_xor_sync(0xffffffffu, plo, 1);
            plo += __shfl_xor_sync(0xffffffffu, plo, 2);
            phi += __shfl_xor_sync(0xffffffffu, phi, 1);
            phi += __shfl_xor_sync(0xffffffffu, phi, 2);
            if (qt == 0){
                int rlo = by*128 + wm*32 + mt*16 + quad;
                g_logit_part[(size_t)rlo*12 + cb*2 + wn]     = plo;
                g_logit_part[(size_t)(rlo+8)*12 + cb*2 + wn] = phi;
            }
        }
    } else {
        int cbv = cb - 6, colb = cbv*128, slot = cbv*2 + wn;
        #pragma unroll
        for (int mt=0;mt<2;mt++){
            float p0l=0.f, p1l=0.f, p0h=0.f, p1h=0.f;
            #pragma unroll
            for (int nt=0;nt<8;nt++){
                int g0 = colb + wn*64 + nt*8 + qt*2;
                float bv0 = g_bias_v[g0], bv1 = g_bias_v[g0+1];
                float m00 = g_M[2*g0],   m01 = g_M[2*g0+1];
                float m10 = g_M[2*g0+2], m11 = g_M[2*g0+3];
                float x;
                x = acc[mt][nt][0]+bv0; x = x>0.f? x:0.f; p0l += x*m00; p1l += x*m01;
                x = acc[mt][nt][1]+bv1; x = x>0.f? x:0.f; p0l += x*m10; p1l += x*m11;
                x = acc[mt][nt][2]+bv0; x = x>0.f? x:0.f; p0h += x*m00; p1h += x*m01;
                x = acc[mt][nt][3]+bv1; x = x>0.f? x:0.f; p0h += x*m10; p1h += x*m11;
            }
            p0l += __shfl_xor_sync(0xffffffffu, p0l, 1); p0l += __shfl_xor_sync(0xffffffffu, p0l, 2);
            p1l += __shfl_xor_sync(0xffffffffu, p1l, 1); p1l += __shfl_xor_sync(0xffffffffu, p1l, 2);
            p0h += __shfl_xor_sync(0xffffffffu, p0h, 1); p0h += __shfl_xor_sync(0xffffffffu, p0h, 2);
            p1h += __shfl_xor_sync(0xffffffffu, p1h, 1); p1h += __shfl_xor_sync(0xffffffffu, p1h, 2);
            if (qt == 0){
                int rlo = by*128 + wm*32 + mt*16 + quad;
                g_rv_part[(size_t)rlo*24 + slot*2 + 0] = p0l;
                g_rv_part[(size_t)rlo*24 + slot*2 + 1] = p1l;
                g_rv_part[(size_t)(rlo+8)*24 + slot*2 + 0] = p0h;
                g_rv_part[(size_t)(rlo+8)*24 + slot*2 + 1] = p1h;
            }
        }
    }
}

// ---------------- L5: fused per-instance attn softmax + final logits ----------------
__global__ void __launch_bounds__(512) k_attn_final(const float* __restrict__ dec,
                                                    const float* __restrict__ clsw,
                                                    const float* __restrict__ clsb,
                                                    float* __restrict__ out){
    __shared__ float slg[16];
    __shared__ float sat[16];
    int n = blockIdx.x;
    int w = threadIdx.x >> 5, lane = threadIdx.x & 31;
    int r = n*KSEN + w;
    const float* drow = dec + (size_t)r*H;
    float a0=0.f, a1=0.f;
    #pragma unroll 4
    for (int t=lane;t<H;t+=32){ float d=drow[t]; a0 += d*clsw[2*t]; a1 += d*clsw[2*t+1]; }
    a0 = wsum(a0); a1 = wsum(a1);
    float lgp = (lane < 12) ? g_logit_part[(size_t)r*12 + lane] : 0.f;
    float lg = wsum(lgp);
    if (lane == 0) slg[w] = lg;
    __syncthreads();
    if (w == 0){
        float v = (lane < 16) ? slg[lane] : -INFINITY;
        float m = v;
        #pragma unroll
        for (int o=16;o;o>>=1) m = fmaxf(m, __shfl_xor_sync(0xffffffffu, m, o));
        float e = (lane < 16) ? expf(v - m) : 0.f;
        float s = wsum(e);
        if (lane < 16) sat[lane] = e/s;
    }
    float rv0p = (lane < 12) ? g_rv_part[(size_t)r*24 + lane*2]     : 0.f;
    float rv1p = (lane < 12) ? g_rv_part[(size_t)r*24 + lane*2 + 1] : 0.f;
    float rv0 = wsum(rv0p), rv1 = wsum(rv1p);
    __syncthreads();
    if (lane == 0){
        float o0 = a0 + clsb[0], o1 = a1 + clsb[1];
        if (n != g_sel){
            float at = sat[w];
            o0 += at*(rv0 + g_c2[0]);
            o1 += at*(rv1 + g_c2[1]);
        }
        out[2*r]   = o0;
        out[2*r+1] = o1;
    }
}

// ---------------- launcher ----------------
extern "C" void kernel_launch(void* const* d_in, const int* in_sizes, int n_in,
                              void* d_out, int out_size){
    (void)n_in; (void)out_size;
    const float *dec,*gls,*s1w,*s1b,*s2w,*s2b,*W1w,*W1b,*W2w,*W2b,*Waw,*Wab,*V1w,*V1b,*V2w,*V2b,*Uw,*Ub,*clsw,*clsb;
    const int* pred;
    if (in_sizes[2] == NI){
        dec=(const float*)d_in[0]; gls=(const float*)d_in[1]; pred=(const int*)d_in[2];
        s1w=(const float*)d_in[3];  s1b=(const float*)d_in[4];
        s2w=(const float*)d_in[5];  s2b=(const float*)d_in[6];
        W1w=(const float*)d_in[7];  W1b=(const float*)d_in[8];
        W2w=(const float*)d_in[9];  W2b=(const float*)d_in[10];
        Waw=(const float*)d_in[11]; Wab=(const float*)d_in[12];
        V1w=(const float*)d_in[13]; V1b=(const float*)d_in[14];
        V2w=(const float*)d_in[15]; V2b=(const float*)d_in[16];
        Uw =(const float*)d_in[17]; Ub =(const float*)d_in[18];
        clsw=(const float*)d_in[19]; clsb=(const float*)d_in[20];
    } else {
        dec=(const float*)d_in[0]; gls=(const float*)d_in[1];
        s1w=(const float*)d_in[2];  s1b=(const float*)d_in[3];
        s2w=(const float*)d_in[4];  s2b=(const float*)d_in[5];
        W1w=(const float*)d_in[6];  W1b=(const float*)d_in[7];
        W2w=(const float*)d_in[8];  W2b=(const float*)d_in[9];
        Waw=(const float*)d_in[10]; Wab=(const float*)d_in[11];
        V1w=(const float*)d_in[12]; V1b=(const float*)d_in[13];
        V2w=(const float*)d_in[14]; V2b=(const float*)d_in[15];
        Uw =(const float*)d_in[16]; Ub =(const float*)d_in[17];
        clsw=(const float*)d_in[18]; clsb=(const float*)d_in[19];
        pred=(const int*)d_in[20];
    }
    (void)s2b; (void)Wab;
    float* out = (float*)d_out;

    cudaFuncSetAttribute(k_gemm1t,  cudaFuncAttributeMaxDynamicSharedMemorySize, G1_SMEM);
    cudaFuncSetAttribute(k_big_mma, cudaFuncAttributeMaxDynamicSharedMemorySize, KB_SMEM);

    k_pool_conv   <<<NI + 2304 + 1152, 256>>>(dec, gls, pred, W2w, V2w, s1w);
    k_gemm1t      <<<dim3(6,16), 256, G1_SMEM>>>(s1b, s2w);
    k_softmax_bias<<<37, 1024>>>(out + 2*RR, W1w, W1b, W2b, V1w, V1b, V2b, Uw, Ub, clsw);
    k_big_mma     <<<dim3(12, 256), 256, KB_SMEM>>>(Waw);   // launch #4 -> profiled
    k_attn_final  <<<NI, 512>>>(dec, clsw, clsb, out);
}